// round 1
// baseline (speedup 1.0000x reference)
#include <cuda_runtime.h>
#include <cuda_bf16.h>
#include <math.h>

// ---------------------------------------------------------------------------
// GQA block: y = proj( attn( x@Wq^T, x@Wk^T, x@Wv^T ) )
// B=2, T=2048, D_MODEL=1024, N_HEADS=16, N_KV=8, GROUP=2, D_HEAD=64
// ---------------------------------------------------------------------------

#define BATCH   2
#define T_SEQ   2048
#define DMODEL  1024
#define NKV_DIM 512
#define NHEADS  16
#define DHEAD   64
#define SCALE_F 0.125f   // 64^-0.5

#define MTOT (BATCH * T_SEQ)   // 4096 rows

// Scratch (static device globals: allowed; no allocation)
__device__ float g_q[(size_t)MTOT * DMODEL];
__device__ float g_k[(size_t)MTOT * NKV_DIM];
__device__ float g_v[(size_t)MTOT * NKV_DIM];
__device__ float g_y[(size_t)MTOT * DMODEL];

// ---------------------------------------------------------------------------
// GEMM: C[M,N] = A[M,K] @ B[N,K]^T   (both row-major, K-major inner)
// BM=BN=128, BK=8, 256 threads, 8x8 microtile per thread.
// ---------------------------------------------------------------------------
#define BM 128
#define BN 128
#define BK 8

__global__ __launch_bounds__(256, 2)
void gemm_tn_kernel(const float* __restrict__ A, const float* __restrict__ B,
                    float* __restrict__ C, int M, int N, int K) {
    __shared__ float As[BK][BM];
    __shared__ float Bs[BK][BN];

    const int tid = threadIdx.x;
    const int ty  = tid >> 4;        // 0..15
    const int tx  = tid & 15;        // 0..15
    const int m0  = blockIdx.y * BM;
    const int n0  = blockIdx.x * BN;

    const float* Ap = A + (size_t)m0 * K;
    const float* Bp = B + (size_t)n0 * K;

    const int lrow = tid >> 1;        // 0..127
    const int lcol = (tid & 1) * 4;   // 0 or 4

    float acc[8][8];
#pragma unroll
    for (int i = 0; i < 8; i++)
#pragma unroll
        for (int j = 0; j < 8; j++) acc[i][j] = 0.0f;

    for (int k0 = 0; k0 < K; k0 += BK) {
        float4 av = *(const float4*)(Ap + (size_t)lrow * K + k0 + lcol);
        float4 bv = *(const float4*)(Bp + (size_t)lrow * K + k0 + lcol);
        __syncthreads();   // previous iter's smem reads complete
        As[lcol + 0][lrow] = av.x;
        As[lcol + 1][lrow] = av.y;
        As[lcol + 2][lrow] = av.z;
        As[lcol + 3][lrow] = av.w;
        Bs[lcol + 0][lrow] = bv.x;
        Bs[lcol + 1][lrow] = bv.y;
        Bs[lcol + 2][lrow] = bv.z;
        Bs[lcol + 3][lrow] = bv.w;
        __syncthreads();

#pragma unroll
        for (int kk = 0; kk < BK; kk++) {
            float a[8], b[8];
            *(float4*)&a[0] = *(const float4*)&As[kk][ty * 8];
            *(float4*)&a[4] = *(const float4*)&As[kk][ty * 8 + 4];
            *(float4*)&b[0] = *(const float4*)&Bs[kk][tx * 8];
            *(float4*)&b[4] = *(const float4*)&Bs[kk][tx * 8 + 4];
#pragma unroll
            for (int i = 0; i < 8; i++)
#pragma unroll
                for (int j = 0; j < 8; j++) acc[i][j] = fmaf(a[i], b[j], acc[i][j]);
        }
    }

#pragma unroll
    for (int i = 0; i < 8; i++) {
        float* cp = C + (size_t)(m0 + ty * 8 + i) * N + n0 + tx * 8;
        *(float4*)(cp)     = make_float4(acc[i][0], acc[i][1], acc[i][2], acc[i][3]);
        *(float4*)(cp + 4) = make_float4(acc[i][4], acc[i][5], acc[i][6], acc[i][7]);
    }
}

// ---------------------------------------------------------------------------
// Flash-attention (no mask), fp32. One block: (batch b, head h, 64-row q tile).
// 64x64 tiles, 256 threads, 4x4 microtiles. Online softmax via intra-16-lane
// shuffles (per-thread m/l state for its 4 q-rows). K smem buffer aliased
// for P so total static smem == 48 KB.
// ---------------------------------------------------------------------------
__global__ __launch_bounds__(256)
void attn_kernel(const float* __restrict__ Q, const float* __restrict__ Kg,
                 const float* __restrict__ Vg, float* __restrict__ Y) {
    __shared__ float Qs[64 * 64];   // [d][i]  (transposed, pre-scaled)
    __shared__ float KS[64 * 64];   // [d][j] as K, then [i][j] as P
    __shared__ float Vs[64 * 64];   // [j][d]

    const int qt = blockIdx.x;       // 0..31
    const int h  = blockIdx.y;       // 0..15
    const int b  = blockIdx.z;       // 0..1
    const int kv = h >> 1;

    const int tid = threadIdx.x;
    const int ty  = tid >> 4;        // 0..15 -> q rows ty*4..+3
    const int tx  = tid & 15;        // 0..15 -> cols tx*4..+3

    const float* qbase = Q + ((size_t)(b * T_SEQ + qt * 64)) * DMODEL + h * DHEAD;
    const float* kbase = Kg + ((size_t)(b * T_SEQ)) * NKV_DIM + kv * DHEAD;
    const float* vbase = Vg + ((size_t)(b * T_SEQ)) * NKV_DIM + kv * DHEAD;

    // load Q tile transposed, pre-scaled
#pragma unroll
    for (int u = 0; u < 4; u++) {
        int ff = tid * 4 + u;          // float4 index 0..1023
        int i  = ff >> 4;              // q row 0..63
        int d4 = (ff & 15) * 4;        // d offset
        float4 v = *(const float4*)(qbase + (size_t)i * DMODEL + d4);
        Qs[(d4 + 0) * 64 + i] = v.x * SCALE_F;
        Qs[(d4 + 1) * 64 + i] = v.y * SCALE_F;
        Qs[(d4 + 2) * 64 + i] = v.z * SCALE_F;
        Qs[(d4 + 3) * 64 + i] = v.w * SCALE_F;
    }

    float acc[4][4];
    float m_i[4], l_i[4];
#pragma unroll
    for (int i = 0; i < 4; i++) {
        m_i[i] = -1e30f;
        l_i[i] = 0.0f;
#pragma unroll
        for (int j = 0; j < 4; j++) acc[i][j] = 0.0f;
    }

    for (int st = 0; st < T_SEQ / 64; st++) {
        __syncthreads();   // prior PV reads of KS/Vs done; also orders Q store
        const float* kp = kbase + (size_t)st * 64 * NKV_DIM;
        const float* vp = vbase + (size_t)st * 64 * NKV_DIM;
#pragma unroll
        for (int u = 0; u < 4; u++) {
            int ff = tid * 4 + u;
            int j  = ff >> 4;            // s row 0..63
            int d4 = (ff & 15) * 4;
            float4 kvv = *(const float4*)(kp + (size_t)j * NKV_DIM + d4);
            KS[(d4 + 0) * 64 + j] = kvv.x;
            KS[(d4 + 1) * 64 + j] = kvv.y;
            KS[(d4 + 2) * 64 + j] = kvv.z;
            KS[(d4 + 3) * 64 + j] = kvv.w;
            float4 vv = *(const float4*)(vp + (size_t)j * NKV_DIM + d4);
            *(float4*)&Vs[j * 64 + d4] = vv;
        }
        __syncthreads();

        // S = (Q*scale) @ K^T  -> s[ii][jj], rows ty*4+ii, cols tx*4+jj
        float s[4][4];
#pragma unroll
        for (int i = 0; i < 4; i++)
#pragma unroll
            for (int j = 0; j < 4; j++) s[i][j] = 0.0f;

#pragma unroll
        for (int dk = 0; dk < DHEAD; dk++) {
            float4 qv = *(const float4*)&Qs[dk * 64 + ty * 4];
            float4 kk = *(const float4*)&KS[dk * 64 + tx * 4];
            float qa[4] = {qv.x, qv.y, qv.z, qv.w};
            float ka[4] = {kk.x, kk.y, kk.z, kk.w};
#pragma unroll
            for (int i = 0; i < 4; i++)
#pragma unroll
                for (int j = 0; j < 4; j++) s[i][j] = fmaf(qa[i], ka[j], s[i][j]);
        }

        // online softmax per q-row (reduce across the 16 tx lanes)
#pragma unroll
        for (int ii = 0; ii < 4; ii++) {
            float rm = fmaxf(fmaxf(s[ii][0], s[ii][1]), fmaxf(s[ii][2], s[ii][3]));
#pragma unroll
            for (int off = 1; off < 16; off <<= 1)
                rm = fmaxf(rm, __shfl_xor_sync(0xffffffffu, rm, off));
            float mnew  = fmaxf(m_i[ii], rm);
            float alpha = __expf(m_i[ii] - mnew);
            float rs = 0.0f;
#pragma unroll
            for (int jj = 0; jj < 4; jj++) {
                s[ii][jj] = __expf(s[ii][jj] - mnew);
                rs += s[ii][jj];
            }
#pragma unroll
            for (int off = 1; off < 16; off <<= 1)
                rs += __shfl_xor_sync(0xffffffffu, rs, off);
            l_i[ii] = l_i[ii] * alpha + rs;
            m_i[ii] = mnew;
#pragma unroll
            for (int jj = 0; jj < 4; jj++) acc[ii][jj] *= alpha;
        }

        __syncthreads();   // everyone done reading KS as K
#pragma unroll
        for (int ii = 0; ii < 4; ii++)
            *(float4*)&KS[(ty * 4 + ii) * 64 + tx * 4] =
                make_float4(s[ii][0], s[ii][1], s[ii][2], s[ii][3]);
        __syncthreads();

        // O += P @ V : rows ty*4+ii, out cols tx*4+jj, k-dim j=0..63
#pragma unroll
        for (int j = 0; j < 64; j++) {
            float4 vv = *(const float4*)&Vs[j * 64 + tx * 4];
            float va[4] = {vv.x, vv.y, vv.z, vv.w};
            float p0 = KS[(ty * 4 + 0) * 64 + j];
            float p1 = KS[(ty * 4 + 1) * 64 + j];
            float p2 = KS[(ty * 4 + 2) * 64 + j];
            float p3 = KS[(ty * 4 + 3) * 64 + j];
#pragma unroll
            for (int jj = 0; jj < 4; jj++) {
                acc[0][jj] = fmaf(p0, va[jj], acc[0][jj]);
                acc[1][jj] = fmaf(p1, va[jj], acc[1][jj]);
                acc[2][jj] = fmaf(p2, va[jj], acc[2][jj]);
                acc[3][jj] = fmaf(p3, va[jj], acc[3][jj]);
            }
        }
    }

    // epilogue: y[b, t, h*64 + d] = acc / l
    float* yp = Y + ((size_t)(b * T_SEQ + qt * 64)) * DMODEL + h * DHEAD;
#pragma unroll
    for (int ii = 0; ii < 4; ii++) {
        float inv = 1.0f / l_i[ii];
        *(float4*)(yp + (size_t)(ty * 4 + ii) * DMODEL + tx * 4) =
            make_float4(acc[ii][0] * inv, acc[ii][1] * inv,
                        acc[ii][2] * inv, acc[ii][3] * inv);
    }
}

// ---------------------------------------------------------------------------
// Launch
// ---------------------------------------------------------------------------
extern "C" void kernel_launch(void* const* d_in, const int* in_sizes, int n_in,
                              void* d_out, int out_size) {
    const float* x     = (const float*)d_in[0];
    const float* Wq    = (const float*)d_in[1];
    const float* Wk    = (const float*)d_in[2];
    const float* Wv    = (const float*)d_in[3];
    const float* Wproj = (const float*)d_in[4];
    float* out = (float*)d_out;

    void *pq, *pk, *pv, *py;
    cudaGetSymbolAddress(&pq, g_q);
    cudaGetSymbolAddress(&pk, g_k);
    cudaGetSymbolAddress(&pv, g_v);
    cudaGetSymbolAddress(&py, g_y);

    dim3 blk(256);
    // Q/K/V projections
    gemm_tn_kernel<<<dim3(DMODEL / BN, MTOT / BM), blk>>>(x, Wq, (float*)pq,
                                                          MTOT, DMODEL, DMODEL);
    gemm_tn_kernel<<<dim3(NKV_DIM / BN, MTOT / BM), blk>>>(x, Wk, (float*)pk,
                                                           MTOT, NKV_DIM, DMODEL);
    gemm_tn_kernel<<<dim3(NKV_DIM / BN, MTOT / BM), blk>>>(x, Wv, (float*)pv,
                                                           MTOT, NKV_DIM, DMODEL);
    // attention
    attn_kernel<<<dim3(T_SEQ / 64, NHEADS, BATCH), blk>>>(
        (const float*)pq, (const float*)pk, (const float*)pv, (float*)py);
    // output projection
    gemm_tn_kernel<<<dim3(DMODEL / BN, MTOT / BM), blk>>>((const float*)py, Wproj,
                                                          out, MTOT, DMODEL, DMODEL);
}

// round 4
// speedup vs baseline: 1.2966x; 1.2966x over previous
#include <cuda_runtime.h>
#include <cuda_bf16.h>
#include <cstdint>
#include <math.h>

// ---------------------------------------------------------------------------
// GQA block: y = proj( attn( x@Wq^T, x@Wk^T, x@Wv^T ) )
// B=2, T=2048, D_MODEL=1024, N_HEADS=16, N_KV=8, GROUP=2, D_HEAD=64
// R3: tcgen05 is rejected by this toolchain (targets sm_103, not sm_103a).
//     GEMMs now use warp-level mma.sync tf32 (legacy HMMA path, sm_80+ ISA).
//     Attention unchanged (proven fp32).
// ---------------------------------------------------------------------------

#define BATCH   2
#define T_SEQ   2048
#define DMODEL  1024
#define NKV_DIM 512
#define NHEADS  16
#define DHEAD   64
#define SCALE_F 0.125f   // 64^-0.5

#define MTOT (BATCH * T_SEQ)   // 4096 rows

// Scratch (static device globals: allowed; no allocation)
__device__ float g_q[(size_t)MTOT * DMODEL];
__device__ float g_k[(size_t)MTOT * NKV_DIM];
__device__ float g_v[(size_t)MTOT * NKV_DIM];
__device__ float g_y[(size_t)MTOT * DMODEL];

// ---------------------------------------------------------------------------
// helpers
// ---------------------------------------------------------------------------
__device__ __forceinline__ float tf32r(float f) {
    uint32_t r;
    asm("cvt.rna.tf32.f32 %0, %1;" : "=r"(r) : "f"(f));
    return __uint_as_float(r);
}

__device__ __forceinline__ void mma_tf32(float* d, const uint32_t* a,
                                         const uint32_t* b) {
    asm volatile(
        "mma.sync.aligned.m16n8k8.row.col.f32.tf32.tf32.f32 "
        "{%0,%1,%2,%3}, {%4,%5,%6,%7}, {%8,%9}, {%0,%1,%2,%3};"
        : "+f"(d[0]), "+f"(d[1]), "+f"(d[2]), "+f"(d[3])
        : "r"(a[0]), "r"(a[1]), "r"(a[2]), "r"(a[3]), "r"(b[0]), "r"(b[1]));
}

// ---------------------------------------------------------------------------
// tf32 mma.sync GEMM: C[M,N] = A[M,K] @ B[N,K]^T (row-major, K-major inner).
// CTA tile 128x128, BK=16, double-buffered smem, 256 threads (8 warps, 2x4).
// Warp tile 64x32 = 4x4 grid of m16n8k8. Smem row stride 20 floats =>
// fragment-load bank = (4*m + k) mod 32 = lane  => conflict-free.
// Requires: M%128==0, N%128==0, K%16==0.
// ---------------------------------------------------------------------------
#define GBK 16
#define AST 20   // smem row stride in floats

__global__ __launch_bounds__(256, 2)
void gemm_mma(const float* __restrict__ A, const float* __restrict__ B,
              float* __restrict__ C, int M, int N, int K) {
    __shared__ float As[2][128 * AST];
    __shared__ float Bs[2][128 * AST];

    const int tid  = threadIdx.x;
    const int lane = tid & 31;
    const int wid  = tid >> 5;
    const int wm   = (wid & 1) * 64;    // warp m offset in tile
    const int wn   = (wid >> 1) * 32;   // warp n offset in tile
    const int lq   = lane >> 2;         // 0..7
    const int lr   = lane & 3;          // 0..3

    const int m0 = blockIdx.y * 128;
    const int n0 = blockIdx.x * 128;

    const float* Ap = A + (size_t)m0 * K;
    const float* Bp = B + (size_t)n0 * K;

    // producer mapping: each thread loads 2 float4 from A and 2 from B per iter
    const int prow = tid >> 2;          // 0..63 (+64 for second half)
    const int pc4  = (tid & 3) * 4;     // k offset 0/4/8/12

    float acc[16][4];
#pragma unroll
    for (int i = 0; i < 16; i++)
#pragma unroll
        for (int j = 0; j < 4; j++) acc[i][j] = 0.0f;

    const int kiters = K / GBK;
    float4 ra0, ra1, rb0, rb1;

    // ---- load iter 0 ----
    {
        ra0 = *(const float4*)(Ap + (size_t)prow * K + pc4);
        ra1 = *(const float4*)(Ap + (size_t)(prow + 64) * K + pc4);
        rb0 = *(const float4*)(Bp + (size_t)prow * K + pc4);
        rb1 = *(const float4*)(Bp + (size_t)(prow + 64) * K + pc4);
    }
    // ---- store iter 0 into buf 0 ----
    {
        float* a0 = &As[0][prow * AST + pc4];
        float* a1 = &As[0][(prow + 64) * AST + pc4];
        float* b0 = &Bs[0][prow * AST + pc4];
        float* b1 = &Bs[0][(prow + 64) * AST + pc4];
        a0[0] = tf32r(ra0.x); a0[1] = tf32r(ra0.y); a0[2] = tf32r(ra0.z); a0[3] = tf32r(ra0.w);
        a1[0] = tf32r(ra1.x); a1[1] = tf32r(ra1.y); a1[2] = tf32r(ra1.z); a1[3] = tf32r(ra1.w);
        b0[0] = tf32r(rb0.x); b0[1] = tf32r(rb0.y); b0[2] = tf32r(rb0.z); b0[3] = tf32r(rb0.w);
        b1[0] = tf32r(rb1.x); b1[1] = tf32r(rb1.y); b1[2] = tf32r(rb1.z); b1[3] = tf32r(rb1.w);
    }
    __syncthreads();

    for (int it = 0; it < kiters; ++it) {
        // prefetch next tile (gmem -> regs), overlaps with MMA below
        if (it + 1 < kiters) {
            const float* Apn = Ap + (it + 1) * GBK;
            const float* Bpn = Bp + (it + 1) * GBK;
            ra0 = *(const float4*)(Apn + (size_t)prow * K + pc4);
            ra1 = *(const float4*)(Apn + (size_t)(prow + 64) * K + pc4);
            rb0 = *(const float4*)(Bpn + (size_t)prow * K + pc4);
            rb1 = *(const float4*)(Bpn + (size_t)(prow + 64) * K + pc4);
        }

        // compute from buf (it & 1)
        const float* as = As[it & 1];
        const float* bs = Bs[it & 1];
#pragma unroll
        for (int ks = 0; ks < 2; ++ks) {
            const int kb = ks * 8;
            uint32_t afr[4][4], bfr[4][2];
#pragma unroll
            for (int mt = 0; mt < 4; mt++) {
                const int r = wm + mt * 16 + lq;
                afr[mt][0] = __float_as_uint(as[r * AST + kb + lr]);
                afr[mt][1] = __float_as_uint(as[(r + 8) * AST + kb + lr]);
                afr[mt][2] = __float_as_uint(as[r * AST + kb + lr + 4]);
                afr[mt][3] = __float_as_uint(as[(r + 8) * AST + kb + lr + 4]);
            }
#pragma unroll
            for (int nt = 0; nt < 4; nt++) {
                const int nrow = wn + nt * 8 + lq;
                bfr[nt][0] = __float_as_uint(bs[nrow * AST + kb + lr]);
                bfr[nt][1] = __float_as_uint(bs[nrow * AST + kb + lr + 4]);
            }
#pragma unroll
            for (int mt = 0; mt < 4; mt++)
#pragma unroll
                for (int nt = 0; nt < 4; nt++)
                    mma_tf32(acc[mt * 4 + nt], afr[mt], bfr[nt]);
        }

        // stage next tile into the other buffer
        if (it + 1 < kiters) {
            const int nb = (it + 1) & 1;
            float* a0 = &As[nb][prow * AST + pc4];
            float* a1 = &As[nb][(prow + 64) * AST + pc4];
            float* b0 = &Bs[nb][prow * AST + pc4];
            float* b1 = &Bs[nb][(prow + 64) * AST + pc4];
            a0[0] = tf32r(ra0.x); a0[1] = tf32r(ra0.y); a0[2] = tf32r(ra0.z); a0[3] = tf32r(ra0.w);
            a1[0] = tf32r(ra1.x); a1[1] = tf32r(ra1.y); a1[2] = tf32r(ra1.z); a1[3] = tf32r(ra1.w);
            b0[0] = tf32r(rb0.x); b0[1] = tf32r(rb0.y); b0[2] = tf32r(rb0.z); b0[3] = tf32r(rb0.w);
            b1[0] = tf32r(rb1.x); b1[1] = tf32r(rb1.y); b1[2] = tf32r(rb1.z); b1[3] = tf32r(rb1.w);
        }
        __syncthreads();
    }

    // ---- epilogue ----
#pragma unroll
    for (int mt = 0; mt < 4; mt++) {
        const int row = m0 + wm + mt * 16 + lq;
#pragma unroll
        for (int nt = 0; nt < 4; nt++) {
            const int col = n0 + wn + nt * 8 + 2 * lr;
            float* d = acc[mt * 4 + nt];
            *(float2*)(C + (size_t)row * N + col)       = make_float2(d[0], d[1]);
            *(float2*)(C + (size_t)(row + 8) * N + col) = make_float2(d[2], d[3]);
        }
    }
}

// ---------------------------------------------------------------------------
// Flash-attention (no mask), fp32 — unchanged (proven correct).
// ---------------------------------------------------------------------------
__global__ __launch_bounds__(256)
void attn_kernel(const float* __restrict__ Q, const float* __restrict__ Kg,
                 const float* __restrict__ Vg, float* __restrict__ Y) {
    __shared__ float Qs[64 * 64];   // [d][i]  (transposed, pre-scaled)
    __shared__ float KS[64 * 64];   // [d][j] as K, then [i][j] as P
    __shared__ float Vs[64 * 64];   // [j][d]

    const int qt = blockIdx.x;
    const int h  = blockIdx.y;
    const int b  = blockIdx.z;
    const int kv = h >> 1;

    const int tid = threadIdx.x;
    const int ty  = tid >> 4;
    const int tx  = tid & 15;

    const float* qbase = Q + ((size_t)(b * T_SEQ + qt * 64)) * DMODEL + h * DHEAD;
    const float* kbase = Kg + ((size_t)(b * T_SEQ)) * NKV_DIM + kv * DHEAD;
    const float* vbase = Vg + ((size_t)(b * T_SEQ)) * NKV_DIM + kv * DHEAD;

#pragma unroll
    for (int u = 0; u < 4; u++) {
        int ff = tid * 4 + u;
        int i  = ff >> 4;
        int d4 = (ff & 15) * 4;
        float4 v = *(const float4*)(qbase + (size_t)i * DMODEL + d4);
        Qs[(d4 + 0) * 64 + i] = v.x * SCALE_F;
        Qs[(d4 + 1) * 64 + i] = v.y * SCALE_F;
        Qs[(d4 + 2) * 64 + i] = v.z * SCALE_F;
        Qs[(d4 + 3) * 64 + i] = v.w * SCALE_F;
    }

    float acc[4][4];
    float m_i[4], l_i[4];
#pragma unroll
    for (int i = 0; i < 4; i++) {
        m_i[i] = -1e30f;
        l_i[i] = 0.0f;
#pragma unroll
        for (int j = 0; j < 4; j++) acc[i][j] = 0.0f;
    }

    for (int st = 0; st < T_SEQ / 64; st++) {
        __syncthreads();
        const float* kp = kbase + (size_t)st * 64 * NKV_DIM;
        const float* vp = vbase + (size_t)st * 64 * NKV_DIM;
#pragma unroll
        for (int u = 0; u < 4; u++) {
            int ff = tid * 4 + u;
            int j  = ff >> 4;
            int d4 = (ff & 15) * 4;
            float4 kvv = *(const float4*)(kp + (size_t)j * NKV_DIM + d4);
            KS[(d4 + 0) * 64 + j] = kvv.x;
            KS[(d4 + 1) * 64 + j] = kvv.y;
            KS[(d4 + 2) * 64 + j] = kvv.z;
            KS[(d4 + 3) * 64 + j] = kvv.w;
            float4 vv = *(const float4*)(vp + (size_t)j * NKV_DIM + d4);
            *(float4*)&Vs[j * 64 + d4] = vv;
        }
        __syncthreads();

        float s[4][4];
#pragma unroll
        for (int i = 0; i < 4; i++)
#pragma unroll
            for (int j = 0; j < 4; j++) s[i][j] = 0.0f;

#pragma unroll
        for (int dk = 0; dk < DHEAD; dk++) {
            float4 qv = *(const float4*)&Qs[dk * 64 + ty * 4];
            float4 kk = *(const float4*)&KS[dk * 64 + tx * 4];
            float qa[4] = {qv.x, qv.y, qv.z, qv.w};
            float ka[4] = {kk.x, kk.y, kk.z, kk.w};
#pragma unroll
            for (int i = 0; i < 4; i++)
#pragma unroll
                for (int j = 0; j < 4; j++) s[i][j] = fmaf(qa[i], ka[j], s[i][j]);
        }

#pragma unroll
        for (int ii = 0; ii < 4; ii++) {
            float rm = fmaxf(fmaxf(s[ii][0], s[ii][1]), fmaxf(s[ii][2], s[ii][3]));
#pragma unroll
            for (int off = 1; off < 16; off <<= 1)
                rm = fmaxf(rm, __shfl_xor_sync(0xffffffffu, rm, off));
            float mnew  = fmaxf(m_i[ii], rm);
            float alpha = __expf(m_i[ii] - mnew);
            float rs = 0.0f;
#pragma unroll
            for (int jj = 0; jj < 4; jj++) {
                s[ii][jj] = __expf(s[ii][jj] - mnew);
                rs += s[ii][jj];
            }
#pragma unroll
            for (int off = 1; off < 16; off <<= 1)
                rs += __shfl_xor_sync(0xffffffffu, rs, off);
            l_i[ii] = l_i[ii] * alpha + rs;
            m_i[ii] = mnew;
#pragma unroll
            for (int jj = 0; jj < 4; jj++) acc[ii][jj] *= alpha;
        }

        __syncthreads();
#pragma unroll
        for (int ii = 0; ii < 4; ii++)
            *(float4*)&KS[(ty * 4 + ii) * 64 + tx * 4] =
                make_float4(s[ii][0], s[ii][1], s[ii][2], s[ii][3]);
        __syncthreads();

#pragma unroll
        for (int j = 0; j < 64; j++) {
            float4 vv = *(const float4*)&Vs[j * 64 + tx * 4];
            float va[4] = {vv.x, vv.y, vv.z, vv.w};
            float p0 = KS[(ty * 4 + 0) * 64 + j];
            float p1 = KS[(ty * 4 + 1) * 64 + j];
            float p2 = KS[(ty * 4 + 2) * 64 + j];
            float p3 = KS[(ty * 4 + 3) * 64 + j];
#pragma unroll
            for (int jj = 0; jj < 4; jj++) {
                acc[0][jj] = fmaf(p0, va[jj], acc[0][jj]);
                acc[1][jj] = fmaf(p1, va[jj], acc[1][jj]);
                acc[2][jj] = fmaf(p2, va[jj], acc[2][jj]);
                acc[3][jj] = fmaf(p3, va[jj], acc[3][jj]);
            }
        }
    }

    float* yp = Y + ((size_t)(b * T_SEQ + qt * 64)) * DMODEL + h * DHEAD;
#pragma unroll
    for (int ii = 0; ii < 4; ii++) {
        float inv = 1.0f / l_i[ii];
        *(float4*)(yp + (size_t)(ty * 4 + ii) * DMODEL + tx * 4) =
            make_float4(acc[ii][0] * inv, acc[ii][1] * inv,
                        acc[ii][2] * inv, acc[ii][3] * inv);
    }
}

// ---------------------------------------------------------------------------
// Launch
// ---------------------------------------------------------------------------
extern "C" void kernel_launch(void* const* d_in, const int* in_sizes, int n_in,
                              void* d_out, int out_size) {
    const float* x     = (const float*)d_in[0];
    const float* Wq    = (const float*)d_in[1];
    const float* Wk    = (const float*)d_in[2];
    const float* Wv    = (const float*)d_in[3];
    const float* Wproj = (const float*)d_in[4];
    float* out = (float*)d_out;

    void *pq, *pk, *pv, *py;
    cudaGetSymbolAddress(&pq, g_q);
    cudaGetSymbolAddress(&pk, g_k);
    cudaGetSymbolAddress(&pv, g_v);
    cudaGetSymbolAddress(&py, g_y);

    dim3 blk(256);
    // Q/K/V projections (tf32 mma.sync)
    gemm_mma<<<dim3(DMODEL / 128, MTOT / 128), blk>>>(x, Wq, (float*)pq,
                                                      MTOT, DMODEL, DMODEL);
    gemm_mma<<<dim3(NKV_DIM / 128, MTOT / 128), blk>>>(x, Wk, (float*)pk,
                                                       MTOT, NKV_DIM, DMODEL);
    gemm_mma<<<dim3(NKV_DIM / 128, MTOT / 128), blk>>>(x, Wv, (float*)pv,
                                                       MTOT, NKV_DIM, DMODEL);
    // attention (fp32, unchanged)
    attn_kernel<<<dim3(T_SEQ / 64, NHEADS, BATCH), blk>>>(
        (const float*)pq, (const float*)pk, (const float*)pv, (float*)py);
    // output projection (tf32 mma.sync)
    gemm_mma<<<dim3(DMODEL / 128, MTOT / 128), blk>>>((const float*)py, Wproj,
                                                      out, MTOT, DMODEL, DMODEL);
}

// round 6
// speedup vs baseline: 3.1087x; 2.3976x over previous
#include <cuda_runtime.h>
#include <cuda_bf16.h>
#include <cstdint>
#include <math.h>

// ---------------------------------------------------------------------------
// GQA block: y = proj( attn( x@Wq^T, x@Wk^T, x@Wv^T ) )
// B=2, T=2048, D_MODEL=1024, N_HEADS=16, N_KV=8, GROUP=2, D_HEAD=64
// R5: attention moved to mma.sync tf32 (m16n8k8) with register-level
//     P layout conversion. GEMMs unchanged (proven R4).
// ---------------------------------------------------------------------------

#define BATCH   2
#define T_SEQ   2048
#define DMODEL  1024
#define NKV_DIM 512
#define NHEADS  16
#define DHEAD   64
#define SCALE_F 0.125f   // 64^-0.5

#define MTOT (BATCH * T_SEQ)   // 4096 rows

__device__ float g_q[(size_t)MTOT * DMODEL];
__device__ float g_k[(size_t)MTOT * NKV_DIM];
__device__ float g_v[(size_t)MTOT * NKV_DIM];
__device__ float g_y[(size_t)MTOT * DMODEL];

// ---------------------------------------------------------------------------
// helpers
// ---------------------------------------------------------------------------
__device__ __forceinline__ float tf32r(float f) {
    uint32_t r;
    asm("cvt.rna.tf32.f32 %0, %1;" : "=r"(r) : "f"(f));
    return __uint_as_float(r);
}
__device__ __forceinline__ uint32_t tf32u(float f) {
    uint32_t r;
    asm("cvt.rna.tf32.f32 %0, %1;" : "=r"(r) : "f"(f));
    return r;
}

__device__ __forceinline__ void mma_tf32(float* d, const uint32_t* a,
                                         const uint32_t* b) {
    asm volatile(
        "mma.sync.aligned.m16n8k8.row.col.f32.tf32.tf32.f32 "
        "{%0,%1,%2,%3}, {%4,%5,%6,%7}, {%8,%9}, {%0,%1,%2,%3};"
        : "+f"(d[0]), "+f"(d[1]), "+f"(d[2]), "+f"(d[3])
        : "r"(a[0]), "r"(a[1]), "r"(a[2]), "r"(a[3]), "r"(b[0]), "r"(b[1]));
}

// ---------------------------------------------------------------------------
// tf32 mma.sync GEMM (unchanged from R4, proven)
// ---------------------------------------------------------------------------
#define GBK 16
#define AST 20

__global__ __launch_bounds__(256, 2)
void gemm_mma(const float* __restrict__ A, const float* __restrict__ B,
              float* __restrict__ C, int M, int N, int K) {
    __shared__ float As[2][128 * AST];
    __shared__ float Bs[2][128 * AST];

    const int tid  = threadIdx.x;
    const int lane = tid & 31;
    const int wid  = tid >> 5;
    const int wm   = (wid & 1) * 64;
    const int wn   = (wid >> 1) * 32;
    const int lq   = lane >> 2;
    const int lr   = lane & 3;

    const int m0 = blockIdx.y * 128;
    const int n0 = blockIdx.x * 128;

    const float* Ap = A + (size_t)m0 * K;
    const float* Bp = B + (size_t)n0 * K;

    const int prow = tid >> 2;
    const int pc4  = (tid & 3) * 4;

    float acc[16][4];
#pragma unroll
    for (int i = 0; i < 16; i++)
#pragma unroll
        for (int j = 0; j < 4; j++) acc[i][j] = 0.0f;

    const int kiters = K / GBK;
    float4 ra0, ra1, rb0, rb1;

    ra0 = *(const float4*)(Ap + (size_t)prow * K + pc4);
    ra1 = *(const float4*)(Ap + (size_t)(prow + 64) * K + pc4);
    rb0 = *(const float4*)(Bp + (size_t)prow * K + pc4);
    rb1 = *(const float4*)(Bp + (size_t)(prow + 64) * K + pc4);
    {
        float* a0 = &As[0][prow * AST + pc4];
        float* a1 = &As[0][(prow + 64) * AST + pc4];
        float* b0 = &Bs[0][prow * AST + pc4];
        float* b1 = &Bs[0][(prow + 64) * AST + pc4];
        a0[0] = tf32r(ra0.x); a0[1] = tf32r(ra0.y); a0[2] = tf32r(ra0.z); a0[3] = tf32r(ra0.w);
        a1[0] = tf32r(ra1.x); a1[1] = tf32r(ra1.y); a1[2] = tf32r(ra1.z); a1[3] = tf32r(ra1.w);
        b0[0] = tf32r(rb0.x); b0[1] = tf32r(rb0.y); b0[2] = tf32r(rb0.z); b0[3] = tf32r(rb0.w);
        b1[0] = tf32r(rb1.x); b1[1] = tf32r(rb1.y); b1[2] = tf32r(rb1.z); b1[3] = tf32r(rb1.w);
    }
    __syncthreads();

    for (int it = 0; it < kiters; ++it) {
        if (it + 1 < kiters) {
            const float* Apn = Ap + (it + 1) * GBK;
            const float* Bpn = Bp + (it + 1) * GBK;
            ra0 = *(const float4*)(Apn + (size_t)prow * K + pc4);
            ra1 = *(const float4*)(Apn + (size_t)(prow + 64) * K + pc4);
            rb0 = *(const float4*)(Bpn + (size_t)prow * K + pc4);
            rb1 = *(const float4*)(Bpn + (size_t)(prow + 64) * K + pc4);
        }

        const float* as = As[it & 1];
        const float* bs = Bs[it & 1];
#pragma unroll
        for (int ks = 0; ks < 2; ++ks) {
            const int kb = ks * 8;
            uint32_t afr[4][4], bfr[4][2];
#pragma unroll
            for (int mt = 0; mt < 4; mt++) {
                const int r = wm + mt * 16 + lq;
                afr[mt][0] = __float_as_uint(as[r * AST + kb + lr]);
                afr[mt][1] = __float_as_uint(as[(r + 8) * AST + kb + lr]);
                afr[mt][2] = __float_as_uint(as[r * AST + kb + lr + 4]);
                afr[mt][3] = __float_as_uint(as[(r + 8) * AST + kb + lr + 4]);
            }
#pragma unroll
            for (int nt = 0; nt < 4; nt++) {
                const int nrow = wn + nt * 8 + lq;
                bfr[nt][0] = __float_as_uint(bs[nrow * AST + kb + lr]);
                bfr[nt][1] = __float_as_uint(bs[nrow * AST + kb + lr + 4]);
            }
#pragma unroll
            for (int mt = 0; mt < 4; mt++)
#pragma unroll
                for (int nt = 0; nt < 4; nt++)
                    mma_tf32(acc[mt * 4 + nt], afr[mt], bfr[nt]);
        }

        if (it + 1 < kiters) {
            const int nb = (it + 1) & 1;
            float* a0 = &As[nb][prow * AST + pc4];
            float* a1 = &As[nb][(prow + 64) * AST + pc4];
            float* b0 = &Bs[nb][prow * AST + pc4];
            float* b1 = &Bs[nb][(prow + 64) * AST + pc4];
            a0[0] = tf32r(ra0.x); a0[1] = tf32r(ra0.y); a0[2] = tf32r(ra0.z); a0[3] = tf32r(ra0.w);
            a1[0] = tf32r(ra1.x); a1[1] = tf32r(ra1.y); a1[2] = tf32r(ra1.z); a1[3] = tf32r(ra1.w);
            b0[0] = tf32r(rb0.x); b0[1] = tf32r(rb0.y); b0[2] = tf32r(rb0.z); b0[3] = tf32r(rb0.w);
            b1[0] = tf32r(rb1.x); b1[1] = tf32r(rb1.y); b1[2] = tf32r(rb1.z); b1[3] = tf32r(rb1.w);
        }
        __syncthreads();
    }

#pragma unroll
    for (int mt = 0; mt < 4; mt++) {
        const int row = m0 + wm + mt * 16 + lq;
#pragma unroll
        for (int nt = 0; nt < 4; nt++) {
            const int col = n0 + wn + nt * 8 + 2 * lr;
            float* d = acc[mt * 4 + nt];
            *(float2*)(C + (size_t)row * N + col)       = make_float2(d[0], d[1]);
            *(float2*)(C + (size_t)(row + 8) * N + col) = make_float2(d[2], d[3]);
        }
    }
}

// ---------------------------------------------------------------------------
// Tensor-core flash attention (tf32 mma.sync), no mask.
// Block: 128 q rows x (head, batch). 8 warps; warp owns 16 q rows.
// KV tile = 128 keys. K smem stride 68, V smem stride 72 (conflict-free
// fragment loads). Q fragments register-resident.
// ---------------------------------------------------------------------------
#define KST 68
#define VST 72
#define ATTN_SMEM ((128 * KST + 128 * VST) * 4)

__global__ __launch_bounds__(256, 1)
void attn_mma(const float* __restrict__ Q, const float* __restrict__ Kg,
              const float* __restrict__ Vg, float* __restrict__ Y) {
    extern __shared__ float sm[];
    float* Ks = sm;                 // [128][KST]  (also Q staging)
    float* Vs = sm + 128 * KST;     // [128][VST]

    const int qt = blockIdx.x;      // 0..15 (128-row q tiles)
    const int h  = blockIdx.y;      // 0..15
    const int b  = blockIdx.z;      // 0..1
    const int kv = h >> 1;

    const int tid  = threadIdx.x;
    const int lane = tid & 31;
    const int wid  = tid >> 5;      // warp -> q rows [wid*16, wid*16+16)
    const int lq   = lane >> 2;     // 0..7
    const int lr   = lane & 3;      // 0..3

    const float* qp = Q + ((size_t)(b * T_SEQ + qt * 128)) * DMODEL + h * DHEAD;
    const float* kbase = Kg + ((size_t)(b * T_SEQ)) * NKV_DIM + kv * DHEAD;
    const float* vbase = Vg + ((size_t)(b * T_SEQ)) * NKV_DIM + kv * DHEAD;

    const int prow = tid >> 1;            // 0..127 (2 float4 per row pair-load)
    const int pc4  = (tid & 1) * 4;       // 0 or 4 -> covers 8 of 16 cols; x2

    // ---- stage Q (scaled, tf32) into Ks, then load Q fragments ----
#pragma unroll
    for (int i = 0; i < 8; i++) {
        int ff = i * 256 + tid;           // 2048 float4
        int r  = ff >> 4;                 // row 0..127
        int c4 = (ff & 15) * 4;
        float4 v = *(const float4*)(qp + (size_t)r * DMODEL + c4);
        float* d = &Ks[r * KST + c4];
        d[0] = tf32r(v.x * SCALE_F); d[1] = tf32r(v.y * SCALE_F);
        d[2] = tf32r(v.z * SCALE_F); d[3] = tf32r(v.w * SCALE_F);
    }
    __syncthreads();

    uint32_t qf[8][4];
    {
        const int qoff = (wid * 16 + lq) * KST + lr;
#pragma unroll
        for (int kb = 0; kb < 8; kb++) {
            qf[kb][0] = __float_as_uint(Ks[qoff + kb * 8]);
            qf[kb][1] = __float_as_uint(Ks[qoff + 8 * KST + kb * 8]);
            qf[kb][2] = __float_as_uint(Ks[qoff + kb * 8 + 4]);
            qf[kb][3] = __float_as_uint(Ks[qoff + 8 * KST + kb * 8 + 4]);
        }
    }

    float o[8][4];
#pragma unroll
    for (int i = 0; i < 8; i++)
#pragma unroll
        for (int j = 0; j < 4; j++) o[i][j] = 0.0f;
    float m0 = -1e30f, m1 = -1e30f, l0 = 0.0f, l1 = 0.0f;

    const int koff = lq * KST + lr;       // key-frag base (S phase)
    const int voff = lr * VST + lq;       // v-frag base (PV phase)

    for (int st = 0; st < T_SEQ / 128; st++) {
        __syncthreads();   // previous tile fully consumed (and Q frags read)
        const float* kp = kbase + (size_t)st * 128 * NKV_DIM;
        const float* vp = vbase + (size_t)st * 128 * NKV_DIM;
#pragma unroll
        for (int i = 0; i < 8; i++) {
            int ff = i * 256 + tid;
            int r  = ff >> 4;
            int c4 = (ff & 15) * 4;
            float4 kvv = *(const float4*)(kp + (size_t)r * NKV_DIM + c4);
            float* dk = &Ks[r * KST + c4];
            dk[0] = tf32r(kvv.x); dk[1] = tf32r(kvv.y);
            dk[2] = tf32r(kvv.z); dk[3] = tf32r(kvv.w);
            float4 vv = *(const float4*)(vp + (size_t)r * NKV_DIM + c4);
            float* dv = &Vs[r * VST + c4];
            dv[0] = tf32r(vv.x); dv[1] = tf32r(vv.y);
            dv[2] = tf32r(vv.z); dv[3] = tf32r(vv.w);
        }
        __syncthreads();

        // ---- S = Q @ K^T : 16 n-tiles of 16x8 ----
        float sf[16][4];
#pragma unroll
        for (int nt = 0; nt < 16; nt++) {
            sf[nt][0] = sf[nt][1] = sf[nt][2] = sf[nt][3] = 0.0f;
            const int nbase = nt * 8 * KST + koff;
#pragma unroll
            for (int kb = 0; kb < 8; kb++) {
                uint32_t bfr[2];
                bfr[0] = __float_as_uint(Ks[nbase + kb * 8]);
                bfr[1] = __float_as_uint(Ks[nbase + kb * 8 + 4]);
                mma_tf32(sf[nt], qf[kb], bfr);
            }
        }

        // ---- online softmax (rows lq, lq+8) ----
        float mx0 = -1e30f, mx1 = -1e30f;
#pragma unroll
        for (int nt = 0; nt < 16; nt++) {
            mx0 = fmaxf(mx0, fmaxf(sf[nt][0], sf[nt][1]));
            mx1 = fmaxf(mx1, fmaxf(sf[nt][2], sf[nt][3]));
        }
        mx0 = fmaxf(mx0, __shfl_xor_sync(0xffffffffu, mx0, 1));
        mx0 = fmaxf(mx0, __shfl_xor_sync(0xffffffffu, mx0, 2));
        mx1 = fmaxf(mx1, __shfl_xor_sync(0xffffffffu, mx1, 1));
        mx1 = fmaxf(mx1, __shfl_xor_sync(0xffffffffu, mx1, 2));

        const float mn0 = fmaxf(m0, mx0);
        const float mn1 = fmaxf(m1, mx1);
        const float al0 = __expf(m0 - mn0);
        const float al1 = __expf(m1 - mn1);
        m0 = mn0; m1 = mn1;

        float s0 = 0.0f, s1 = 0.0f;
#pragma unroll
        for (int nt = 0; nt < 16; nt++) {
            sf[nt][0] = __expf(sf[nt][0] - mn0); s0 += sf[nt][0];
            sf[nt][1] = __expf(sf[nt][1] - mn0); s0 += sf[nt][1];
            sf[nt][2] = __expf(sf[nt][2] - mn1); s1 += sf[nt][2];
            sf[nt][3] = __expf(sf[nt][3] - mn1); s1 += sf[nt][3];
        }
        s0 += __shfl_xor_sync(0xffffffffu, s0, 1);
        s0 += __shfl_xor_sync(0xffffffffu, s0, 2);
        s1 += __shfl_xor_sync(0xffffffffu, s1, 1);
        s1 += __shfl_xor_sync(0xffffffffu, s1, 2);
        l0 = l0 * al0 + s0;
        l1 = l1 * al1 + s1;

#pragma unroll
        for (int nb = 0; nb < 8; nb++) {
            o[nb][0] *= al0; o[nb][1] *= al0;
            o[nb][2] *= al1; o[nb][3] *= al1;
        }

        // ---- PV: for each key k-step, convert P tile to A-frag, MMA over d ----
        const int srcA = (lane & ~3) | (lr >> 1);
        const int srcB = srcA + 2;
        const bool odd = lr & 1;
#pragma unroll
        for (int kt = 0; kt < 16; kt++) {
            float p0 = sf[kt][0], p1 = sf[kt][1], p2 = sf[kt][2], p3 = sf[kt][3];
            float e0 = __shfl_sync(0xffffffffu, p0, srcA);
            float e1 = __shfl_sync(0xffffffffu, p1, srcA);
            float e2 = __shfl_sync(0xffffffffu, p2, srcA);
            float e3 = __shfl_sync(0xffffffffu, p3, srcA);
            float f0 = __shfl_sync(0xffffffffu, p0, srcB);
            float f1 = __shfl_sync(0xffffffffu, p1, srcB);
            float f2 = __shfl_sync(0xffffffffu, p2, srcB);
            float f3 = __shfl_sync(0xffffffffu, p3, srcB);
            uint32_t pa[4];
            pa[0] = tf32u(odd ? e1 : e0);
            pa[1] = tf32u(odd ? e3 : e2);
            pa[2] = tf32u(odd ? f1 : f0);
            pa[3] = tf32u(odd ? f3 : f2);

            const int vb = kt * 8 * VST + voff;
#pragma unroll
            for (int nb = 0; nb < 8; nb++) {
                uint32_t bfr[2];
                bfr[0] = __float_as_uint(Vs[vb + nb * 8]);
                bfr[1] = __float_as_uint(Vs[vb + 4 * VST + nb * 8]);
                mma_tf32(o[nb], pa, bfr);
            }
        }
    }

    // ---- epilogue ----
    const float inv0 = 1.0f / l0;
    const float inv1 = 1.0f / l1;
    float* yp = Y + ((size_t)(b * T_SEQ + qt * 128 + wid * 16)) * DMODEL + h * DHEAD;
#pragma unroll
    for (int nb = 0; nb < 8; nb++) {
        const int col = nb * 8 + 2 * lr;
        *(float2*)(yp + (size_t)lq * DMODEL + col) =
            make_float2(o[nb][0] * inv0, o[nb][1] * inv0);
        *(float2*)(yp + (size_t)(lq + 8) * DMODEL + col) =
            make_float2(o[nb][2] * inv1, o[nb][3] * inv1);
    }
}

// ---------------------------------------------------------------------------
// Launch
// ---------------------------------------------------------------------------
extern "C" void kernel_launch(void* const* d_in, const int* in_sizes, int n_in,
                              void* d_out, int out_size) {
    const float* x     = (const float*)d_in[0];
    const float* Wq    = (const float*)d_in[1];
    const float* Wk    = (const float*)d_in[2];
    const float* Wv    = (const float*)d_in[3];
    const float* Wproj = (const float*)d_in[4];
    float* out = (float*)d_out;

    void *pq, *pk, *pv, *py;
    cudaGetSymbolAddress(&pq, g_q);
    cudaGetSymbolAddress(&pk, g_k);
    cudaGetSymbolAddress(&pv, g_v);
    cudaGetSymbolAddress(&py, g_y);

    cudaFuncSetAttribute(attn_mma, cudaFuncAttributeMaxDynamicSharedMemorySize,
                         ATTN_SMEM);

    dim3 blk(256);
    gemm_mma<<<dim3(DMODEL / 128, MTOT / 128), blk>>>(x, Wq, (float*)pq,
                                                      MTOT, DMODEL, DMODEL);
    gemm_mma<<<dim3(NKV_DIM / 128, MTOT / 128), blk>>>(x, Wk, (float*)pk,
                                                       MTOT, NKV_DIM, DMODEL);
    gemm_mma<<<dim3(NKV_DIM / 128, MTOT / 128), blk>>>(x, Wv, (float*)pv,
                                                       MTOT, NKV_DIM, DMODEL);
    attn_mma<<<dim3(T_SEQ / 128, NHEADS, BATCH), blk, ATTN_SMEM>>>(
        (const float*)pq, (const float*)pk, (const float*)pv, (float*)py);
    gemm_mma<<<dim3(DMODEL / 128, MTOT / 128), blk>>>((const float*)py, Wproj,
                                                      out, MTOT, DMODEL, DMODEL);
}

// round 7
// speedup vs baseline: 3.1306x; 1.0070x over previous
#include <cuda_runtime.h>
#include <cuda_bf16.h>
#include <cstdint>
#include <math.h>

// ---------------------------------------------------------------------------
// GQA block: y = proj( attn( x@Wq^T, x@Wk^T, x@Wv^T ) )
// B=2, T=2048, D_MODEL=1024, N_HEADS=16, N_KV=8, GROUP=2, D_HEAD=64
// R7: attention restructured for occupancy — 64-key sub-tiles (sf 32 regs),
//     Q fragments in smem (not registers), target <=128 regs => 2 CTAs/SM.
//     GEMMs unchanged (proven R4).
// ---------------------------------------------------------------------------

#define BATCH   2
#define T_SEQ   2048
#define DMODEL  1024
#define NKV_DIM 512
#define NHEADS  16
#define DHEAD   64
#define SCALE_F 0.125f   // 64^-0.5

#define MTOT (BATCH * T_SEQ)   // 4096 rows

__device__ float g_q[(size_t)MTOT * DMODEL];
__device__ float g_k[(size_t)MTOT * NKV_DIM];
__device__ float g_v[(size_t)MTOT * NKV_DIM];
__device__ float g_y[(size_t)MTOT * DMODEL];

// ---------------------------------------------------------------------------
// helpers
// ---------------------------------------------------------------------------
__device__ __forceinline__ float tf32r(float f) {
    uint32_t r;
    asm("cvt.rna.tf32.f32 %0, %1;" : "=r"(r) : "f"(f));
    return __uint_as_float(r);
}
__device__ __forceinline__ uint32_t tf32u(float f) {
    uint32_t r;
    asm("cvt.rna.tf32.f32 %0, %1;" : "=r"(r) : "f"(f));
    return r;
}

__device__ __forceinline__ void mma_tf32(float* d, const uint32_t* a,
                                         const uint32_t* b) {
    asm volatile(
        "mma.sync.aligned.m16n8k8.row.col.f32.tf32.tf32.f32 "
        "{%0,%1,%2,%3}, {%4,%5,%6,%7}, {%8,%9}, {%0,%1,%2,%3};"
        : "+f"(d[0]), "+f"(d[1]), "+f"(d[2]), "+f"(d[3])
        : "r"(a[0]), "r"(a[1]), "r"(a[2]), "r"(a[3]), "r"(b[0]), "r"(b[1]));
}

// ---------------------------------------------------------------------------
// tf32 mma.sync GEMM (unchanged from R4, proven)
// ---------------------------------------------------------------------------
#define GBK 16
#define AST 20

__global__ __launch_bounds__(256, 2)
void gemm_mma(const float* __restrict__ A, const float* __restrict__ B,
              float* __restrict__ C, int M, int N, int K) {
    __shared__ float As[2][128 * AST];
    __shared__ float Bs[2][128 * AST];

    const int tid  = threadIdx.x;
    const int lane = tid & 31;
    const int wid  = tid >> 5;
    const int wm   = (wid & 1) * 64;
    const int wn   = (wid >> 1) * 32;
    const int lq   = lane >> 2;
    const int lr   = lane & 3;

    const int m0 = blockIdx.y * 128;
    const int n0 = blockIdx.x * 128;

    const float* Ap = A + (size_t)m0 * K;
    const float* Bp = B + (size_t)n0 * K;

    const int prow = tid >> 2;
    const int pc4  = (tid & 3) * 4;

    float acc[16][4];
#pragma unroll
    for (int i = 0; i < 16; i++)
#pragma unroll
        for (int j = 0; j < 4; j++) acc[i][j] = 0.0f;

    const int kiters = K / GBK;
    float4 ra0, ra1, rb0, rb1;

    ra0 = *(const float4*)(Ap + (size_t)prow * K + pc4);
    ra1 = *(const float4*)(Ap + (size_t)(prow + 64) * K + pc4);
    rb0 = *(const float4*)(Bp + (size_t)prow * K + pc4);
    rb1 = *(const float4*)(Bp + (size_t)(prow + 64) * K + pc4);
    {
        float* a0 = &As[0][prow * AST + pc4];
        float* a1 = &As[0][(prow + 64) * AST + pc4];
        float* b0 = &Bs[0][prow * AST + pc4];
        float* b1 = &Bs[0][(prow + 64) * AST + pc4];
        a0[0] = tf32r(ra0.x); a0[1] = tf32r(ra0.y); a0[2] = tf32r(ra0.z); a0[3] = tf32r(ra0.w);
        a1[0] = tf32r(ra1.x); a1[1] = tf32r(ra1.y); a1[2] = tf32r(ra1.z); a1[3] = tf32r(ra1.w);
        b0[0] = tf32r(rb0.x); b0[1] = tf32r(rb0.y); b0[2] = tf32r(rb0.z); b0[3] = tf32r(rb0.w);
        b1[0] = tf32r(rb1.x); b1[1] = tf32r(rb1.y); b1[2] = tf32r(rb1.z); b1[3] = tf32r(rb1.w);
    }
    __syncthreads();

    for (int it = 0; it < kiters; ++it) {
        if (it + 1 < kiters) {
            const float* Apn = Ap + (it + 1) * GBK;
            const float* Bpn = Bp + (it + 1) * GBK;
            ra0 = *(const float4*)(Apn + (size_t)prow * K + pc4);
            ra1 = *(const float4*)(Apn + (size_t)(prow + 64) * K + pc4);
            rb0 = *(const float4*)(Bpn + (size_t)prow * K + pc4);
            rb1 = *(const float4*)(Bpn + (size_t)(prow + 64) * K + pc4);
        }

        const float* as = As[it & 1];
        const float* bs = Bs[it & 1];
#pragma unroll
        for (int ks = 0; ks < 2; ++ks) {
            const int kb = ks * 8;
            uint32_t afr[4][4], bfr[4][2];
#pragma unroll
            for (int mt = 0; mt < 4; mt++) {
                const int r = wm + mt * 16 + lq;
                afr[mt][0] = __float_as_uint(as[r * AST + kb + lr]);
                afr[mt][1] = __float_as_uint(as[(r + 8) * AST + kb + lr]);
                afr[mt][2] = __float_as_uint(as[r * AST + kb + lr + 4]);
                afr[mt][3] = __float_as_uint(as[(r + 8) * AST + kb + lr + 4]);
            }
#pragma unroll
            for (int nt = 0; nt < 4; nt++) {
                const int nrow = wn + nt * 8 + lq;
                bfr[nt][0] = __float_as_uint(bs[nrow * AST + kb + lr]);
                bfr[nt][1] = __float_as_uint(bs[nrow * AST + kb + lr + 4]);
            }
#pragma unroll
            for (int mt = 0; mt < 4; mt++)
#pragma unroll
                for (int nt = 0; nt < 4; nt++)
                    mma_tf32(acc[mt * 4 + nt], afr[mt], bfr[nt]);
        }

        if (it + 1 < kiters) {
            const int nb = (it + 1) & 1;
            float* a0 = &As[nb][prow * AST + pc4];
            float* a1 = &As[nb][(prow + 64) * AST + pc4];
            float* b0 = &Bs[nb][prow * AST + pc4];
            float* b1 = &Bs[nb][(prow + 64) * AST + pc4];
            a0[0] = tf32r(ra0.x); a0[1] = tf32r(ra0.y); a0[2] = tf32r(ra0.z); a0[3] = tf32r(ra0.w);
            a1[0] = tf32r(ra1.x); a1[1] = tf32r(ra1.y); a1[2] = tf32r(ra1.z); a1[3] = tf32r(ra1.w);
            b0[0] = tf32r(rb0.x); b0[1] = tf32r(rb0.y); b0[2] = tf32r(rb0.z); b0[3] = tf32r(rb0.w);
            b1[0] = tf32r(rb1.x); b1[1] = tf32r(rb1.y); b1[2] = tf32r(rb1.z); b1[3] = tf32r(rb1.w);
        }
        __syncthreads();
    }

#pragma unroll
    for (int mt = 0; mt < 4; mt++) {
        const int row = m0 + wm + mt * 16 + lq;
#pragma unroll
        for (int nt = 0; nt < 4; nt++) {
            const int col = n0 + wn + nt * 8 + 2 * lr;
            float* d = acc[mt * 4 + nt];
            *(float2*)(C + (size_t)row * N + col)       = make_float2(d[0], d[1]);
            *(float2*)(C + (size_t)(row + 8) * N + col) = make_float2(d[2], d[3]);
        }
    }
}

// ---------------------------------------------------------------------------
// Tensor-core flash attention (tf32 mma.sync), no mask.
// R7: 64-key sub-tiles, Q fragments fetched from smem per k-step,
// register budget <=128 => 2 CTAs/SM.
// Block: 128 q rows x (head, batch). 8 warps; warp owns 16 q rows.
// ---------------------------------------------------------------------------
#define KST 68
#define VST 72
#define ATTN_SMEM ((128 * KST + 64 * KST + 64 * VST) * 4)

__global__ __launch_bounds__(256, 2)
void attn_mma(const float* __restrict__ Q, const float* __restrict__ Kg,
              const float* __restrict__ Vg, float* __restrict__ Y) {
    extern __shared__ float sm[];
    float* Qs = sm;                     // [128][KST]  (persistent)
    float* Ks = sm + 128 * KST;         // [64][KST]
    float* Vs = Ks + 64 * KST;          // [64][VST]

    const int qt = blockIdx.x;          // 0..15
    const int h  = blockIdx.y;          // 0..15
    const int b  = blockIdx.z;          // 0..1
    const int kv = h >> 1;

    const int tid  = threadIdx.x;
    const int lane = tid & 31;
    const int wid  = tid >> 5;          // warp -> q rows [wid*16, wid*16+16)
    const int lq   = lane >> 2;         // 0..7
    const int lr   = lane & 3;          // 0..3

    const float* qp = Q + ((size_t)(b * T_SEQ + qt * 128)) * DMODEL + h * DHEAD;
    const float* kbase = Kg + ((size_t)(b * T_SEQ)) * NKV_DIM + kv * DHEAD;
    const float* vbase = Vg + ((size_t)(b * T_SEQ)) * NKV_DIM + kv * DHEAD;

    // ---- stage Q (scaled, tf32) into Qs ----
#pragma unroll
    for (int i = 0; i < 8; i++) {
        int ff = i * 256 + tid;         // 2048 float4
        int r  = ff >> 4;               // row 0..127
        int c4 = (ff & 15) * 4;
        float4 v = *(const float4*)(qp + (size_t)r * DMODEL + c4);
        float* d = &Qs[r * KST + c4];
        d[0] = tf32r(v.x * SCALE_F); d[1] = tf32r(v.y * SCALE_F);
        d[2] = tf32r(v.z * SCALE_F); d[3] = tf32r(v.w * SCALE_F);
    }

    float o[8][4];
#pragma unroll
    for (int i = 0; i < 8; i++)
#pragma unroll
        for (int j = 0; j < 4; j++) o[i][j] = 0.0f;
    float m0 = -1e30f, m1 = -1e30f, l0 = 0.0f, l1 = 0.0f;

    const int qoff = (wid * 16 + lq) * KST + lr;   // Q frag base
    const int koff = lq * KST + lr;                // key frag base (S phase)
    const int voff = lr * VST + lq;                // v frag base (PV phase)
    const int srcA = (lane & ~3) | (lr >> 1);
    const int srcB = srcA + 2;
    const bool odd = lr & 1;

    for (int st = 0; st < T_SEQ / 64; st++) {
        __syncthreads();   // previous sub-tile consumed (first iter: Q staged)
        const float* kp = kbase + (size_t)st * 64 * NKV_DIM;
        const float* vp = vbase + (size_t)st * 64 * NKV_DIM;
#pragma unroll
        for (int i = 0; i < 4; i++) {
            int ff = i * 256 + tid;     // 1024 float4 -> 64 rows x 16 f4
            int r  = ff >> 4;
            int c4 = (ff & 15) * 4;
            float4 kvv = *(const float4*)(kp + (size_t)r * NKV_DIM + c4);
            float* dk = &Ks[r * KST + c4];
            dk[0] = tf32r(kvv.x); dk[1] = tf32r(kvv.y);
            dk[2] = tf32r(kvv.z); dk[3] = tf32r(kvv.w);
            float4 vv = *(const float4*)(vp + (size_t)r * NKV_DIM + c4);
            float* dv = &Vs[r * VST + c4];
            dv[0] = tf32r(vv.x); dv[1] = tf32r(vv.y);
            dv[2] = tf32r(vv.z); dv[3] = tf32r(vv.w);
        }
        __syncthreads();

        // ---- S = Q @ K^T : 8 n-tiles of 16x8, K=64 ----
        float sf[8][4];
#pragma unroll
        for (int nt = 0; nt < 8; nt++)
            sf[nt][0] = sf[nt][1] = sf[nt][2] = sf[nt][3] = 0.0f;

#pragma unroll
        for (int kb = 0; kb < 8; kb++) {
            uint32_t qf[4];
            qf[0] = __float_as_uint(Qs[qoff + kb * 8]);
            qf[1] = __float_as_uint(Qs[qoff + 8 * KST + kb * 8]);
            qf[2] = __float_as_uint(Qs[qoff + kb * 8 + 4]);
            qf[3] = __float_as_uint(Qs[qoff + 8 * KST + kb * 8 + 4]);
#pragma unroll
            for (int nt = 0; nt < 8; nt++) {
                uint32_t bfr[2];
                const int nbase = nt * 8 * KST + koff;
                bfr[0] = __float_as_uint(Ks[nbase + kb * 8]);
                bfr[1] = __float_as_uint(Ks[nbase + kb * 8 + 4]);
                mma_tf32(sf[nt], qf, bfr);
            }
        }

        // ---- online softmax (rows lq, lq+8) over 64 cols ----
        float mx0 = -1e30f, mx1 = -1e30f;
#pragma unroll
        for (int nt = 0; nt < 8; nt++) {
            mx0 = fmaxf(mx0, fmaxf(sf[nt][0], sf[nt][1]));
            mx1 = fmaxf(mx1, fmaxf(sf[nt][2], sf[nt][3]));
        }
        mx0 = fmaxf(mx0, __shfl_xor_sync(0xffffffffu, mx0, 1));
        mx0 = fmaxf(mx0, __shfl_xor_sync(0xffffffffu, mx0, 2));
        mx1 = fmaxf(mx1, __shfl_xor_sync(0xffffffffu, mx1, 1));
        mx1 = fmaxf(mx1, __shfl_xor_sync(0xffffffffu, mx1, 2));

        const float mn0 = fmaxf(m0, mx0);
        const float mn1 = fmaxf(m1, mx1);
        const float al0 = __expf(m0 - mn0);
        const float al1 = __expf(m1 - mn1);
        m0 = mn0; m1 = mn1;

        float s0 = 0.0f, s1 = 0.0f;
#pragma unroll
        for (int nt = 0; nt < 8; nt++) {
            sf[nt][0] = __expf(sf[nt][0] - mn0); s0 += sf[nt][0];
            sf[nt][1] = __expf(sf[nt][1] - mn0); s0 += sf[nt][1];
            sf[nt][2] = __expf(sf[nt][2] - mn1); s1 += sf[nt][2];
            sf[nt][3] = __expf(sf[nt][3] - mn1); s1 += sf[nt][3];
        }
        s0 += __shfl_xor_sync(0xffffffffu, s0, 1);
        s0 += __shfl_xor_sync(0xffffffffu, s0, 2);
        s1 += __shfl_xor_sync(0xffffffffu, s1, 1);
        s1 += __shfl_xor_sync(0xffffffffu, s1, 2);
        l0 = l0 * al0 + s0;
        l1 = l1 * al1 + s1;

#pragma unroll
        for (int nb = 0; nb < 8; nb++) {
            o[nb][0] *= al0; o[nb][1] *= al0;
            o[nb][2] *= al1; o[nb][3] *= al1;
        }

        // ---- PV: per key k-step, convert P tile to A-frag, MMA over d ----
#pragma unroll
        for (int kt = 0; kt < 8; kt++) {
            float p0 = sf[kt][0], p1 = sf[kt][1], p2 = sf[kt][2], p3 = sf[kt][3];
            float e0 = __shfl_sync(0xffffffffu, p0, srcA);
            float e1 = __shfl_sync(0xffffffffu, p1, srcA);
            float e2 = __shfl_sync(0xffffffffu, p2, srcA);
            float e3 = __shfl_sync(0xffffffffu, p3, srcA);
            float f0 = __shfl_sync(0xffffffffu, p0, srcB);
            float f1 = __shfl_sync(0xffffffffu, p1, srcB);
            float f2 = __shfl_sync(0xffffffffu, p2, srcB);
            float f3 = __shfl_sync(0xffffffffu, p3, srcB);
            uint32_t pa[4];
            pa[0] = tf32u(odd ? e1 : e0);
            pa[1] = tf32u(odd ? e3 : e2);
            pa[2] = tf32u(odd ? f1 : f0);
            pa[3] = tf32u(odd ? f3 : f2);

            const int vb = kt * 8 * VST + voff;
#pragma unroll
            for (int nb = 0; nb < 8; nb++) {
                uint32_t bfr[2];
                bfr[0] = __float_as_uint(Vs[vb + nb * 8]);
                bfr[1] = __float_as_uint(Vs[vb + 4 * VST + nb * 8]);
                mma_tf32(o[nb], pa, bfr);
            }
        }
    }

    // ---- epilogue ----
    const float inv0 = 1.0f / l0;
    const float inv1 = 1.0f / l1;
    float* yp = Y + ((size_t)(b * T_SEQ + qt * 128 + wid * 16)) * DMODEL + h * DHEAD;
#pragma unroll
    for (int nb = 0; nb < 8; nb++) {
        const int col = nb * 8 + 2 * lr;
        *(float2*)(yp + (size_t)lq * DMODEL + col) =
            make_float2(o[nb][0] * inv0, o[nb][1] * inv0);
        *(float2*)(yp + (size_t)(lq + 8) * DMODEL + col) =
            make_float2(o[nb][2] * inv1, o[nb][3] * inv1);
    }
}

// ---------------------------------------------------------------------------
// Launch
// ---------------------------------------------------------------------------
extern "C" void kernel_launch(void* const* d_in, const int* in_sizes, int n_in,
                              void* d_out, int out_size) {
    const float* x     = (const float*)d_in[0];
    const float* Wq    = (const float*)d_in[1];
    const float* Wk    = (const float*)d_in[2];
    const float* Wv    = (const float*)d_in[3];
    const float* Wproj = (const float*)d_in[4];
    float* out = (float*)d_out;

    void *pq, *pk, *pv, *py;
    cudaGetSymbolAddress(&pq, g_q);
    cudaGetSymbolAddress(&pk, g_k);
    cudaGetSymbolAddress(&pv, g_v);
    cudaGetSymbolAddress(&py, g_y);

    cudaFuncSetAttribute(attn_mma, cudaFuncAttributeMaxDynamicSharedMemorySize,
                         ATTN_SMEM);

    dim3 blk(256);
    gemm_mma<<<dim3(DMODEL / 128, MTOT / 128), blk>>>(x, Wq, (float*)pq,
                                                      MTOT, DMODEL, DMODEL);
    gemm_mma<<<dim3(NKV_DIM / 128, MTOT / 128), blk>>>(x, Wk, (float*)pk,
                                                       MTOT, NKV_DIM, DMODEL);
    gemm_mma<<<dim3(NKV_DIM / 128, MTOT / 128), blk>>>(x, Wv, (float*)pv,
                                                       MTOT, NKV_DIM, DMODEL);
    attn_mma<<<dim3(T_SEQ / 128, NHEADS, BATCH), blk, ATTN_SMEM>>>(
        (const float*)pq, (const float*)pk, (const float*)pv, (float*)py);
    gemm_mma<<<dim3(DMODEL / 128, MTOT / 128), blk>>>((const float*)py, Wproj,
                                                      out, MTOT, DMODEL, DMODEL);
}

// round 8
// speedup vs baseline: 3.1766x; 1.0147x over previous
#include <cuda_runtime.h>
#include <cuda_bf16.h>
#include <cstdint>
#include <math.h>

// ---------------------------------------------------------------------------
// GQA block: y = proj( attn( x@Wq^T, x@Wk^T, x@Wv^T ) )
// B=2, T=2048, D_MODEL=1024, N_HEADS=16, N_KV=8, GROUP=2, D_HEAD=64
// R8: fragment-layout smem (LDS.128/LDS.64 fragment loads) for both the
//     GEMM and attention kernels; exp2-based softmax. Numerics unchanged.
// ---------------------------------------------------------------------------

#define BATCH   2
#define T_SEQ   2048
#define DMODEL  1024
#define NKV_DIM 512
#define NHEADS  16
#define DHEAD   64
#define QSCALE  0.18033688f   // 64^-0.5 * log2(e)

#define MTOT (BATCH * T_SEQ)   // 4096 rows

__device__ float g_q[(size_t)MTOT * DMODEL];
__device__ float g_k[(size_t)MTOT * NKV_DIM];
__device__ float g_v[(size_t)MTOT * NKV_DIM];
__device__ float g_y[(size_t)MTOT * DMODEL];

// ---------------------------------------------------------------------------
// helpers
// ---------------------------------------------------------------------------
__device__ __forceinline__ float tf32r(float f) {
    uint32_t r;
    asm("cvt.rna.tf32.f32 %0, %1;" : "=r"(r) : "f"(f));
    return __uint_as_float(r);
}
__device__ __forceinline__ uint32_t tf32u(float f) {
    uint32_t r;
    asm("cvt.rna.tf32.f32 %0, %1;" : "=r"(r) : "f"(f));
    return r;
}
__device__ __forceinline__ float ex2f(float x) {
    float y;
    asm("ex2.approx.f32 %0, %1;" : "=f"(y) : "f"(x));
    return y;
}

__device__ __forceinline__ void mma_tf32(float* d, const uint32_t* a,
                                         const uint32_t* b) {
    asm volatile(
        "mma.sync.aligned.m16n8k8.row.col.f32.tf32.tf32.f32 "
        "{%0,%1,%2,%3}, {%4,%5,%6,%7}, {%8,%9}, {%0,%1,%2,%3};"
        : "+f"(d[0]), "+f"(d[1]), "+f"(d[2]), "+f"(d[3])
        : "r"(a[0]), "r"(a[1]), "r"(a[2]), "r"(a[3]), "r"(b[0]), "r"(b[1]));
}

// Fragment-layout smem blocks:
//  A-frag block (16 rows x 8 k): 128 floats + 4 pad = 132. Thread `lane` owns
//    4 consecutive floats at lane*4 (a0,a1,a2,a3) -> one LDS.128.
//  B-frag block (8 n x 8 k):      64 floats + 2 pad = 66. Thread `lane` owns
//    2 consecutive floats at lane*2 (b0,b1) -> one LDS.64.
#define ABLK 132
#define BBLK 66

// scatter a float4 of A (row r, k-cols c4..c4+3) into A-frag layout
__device__ __forceinline__ void stA(float* buf, int r, int c4, float4 v) {
    const int blk  = (r >> 4) * 2 + (c4 >> 3);          // [mblk][kb], kb-count 2
    const int slot = ((r >> 3) & 1) + 2 * ((c4 >> 2) & 1);
    float* p = buf + blk * ABLK + ((r & 7) * 4) * 4 + slot;
    p[0]  = tf32r(v.x);
    p[4]  = tf32r(v.y);
    p[8]  = tf32r(v.z);
    p[12] = tf32r(v.w);
}
// scatter a float4 of B (n-row r, k-cols c4..c4+3) into B-frag layout
__device__ __forceinline__ void stB(float* buf, int r, int c4, float4 v) {
    const int blk  = (r >> 3) * 2 + (c4 >> 3);          // [nblk][kb], kb-count 2
    const int slot = (c4 >> 2) & 1;
    float* p = buf + blk * BBLK + ((r & 7) * 4) * 2 + slot;
    p[0] = tf32r(v.x);
    p[2] = tf32r(v.y);
    p[4] = tf32r(v.z);
    p[6] = tf32r(v.w);
}

// ---------------------------------------------------------------------------
// tf32 mma.sync GEMM: C[M,N] = A[M,K] @ B[N,K]^T. CTA tile 128x128, BK=16,
// double-buffered fragment-layout smem. 8 warps (2x4), warp tile 64x32.
// ---------------------------------------------------------------------------
#define GBK 16

__global__ __launch_bounds__(256, 2)
void gemm_mma(const float* __restrict__ A, const float* __restrict__ B,
              float* __restrict__ C, int M, int N, int K) {
    __shared__ float Af[2][16 * ABLK];   // 8 mblk x 2 kb
    __shared__ float Bf[2][32 * BBLK];   // 16 nblk x 2 kb

    const int tid  = threadIdx.x;
    const int lane = tid & 31;
    const int wid  = tid >> 5;
    const int wmb  = (wid & 1) * 4;      // mblk base (x16 rows)
    const int wnb  = (wid >> 1) * 4;     // nblk base (x8 rows)
    const int lq   = lane >> 2;
    const int lr   = lane & 3;

    const int m0 = blockIdx.y * 128;
    const int n0 = blockIdx.x * 128;

    const float* Ap = A + (size_t)m0 * K;
    const float* Bp = B + (size_t)n0 * K;

    const int prow = tid >> 2;
    const int pc4  = (tid & 3) * 4;

    float acc[16][4];
#pragma unroll
    for (int i = 0; i < 16; i++)
#pragma unroll
        for (int j = 0; j < 4; j++) acc[i][j] = 0.0f;

    const int kiters = K / GBK;
    float4 ra0, ra1, rb0, rb1;

    ra0 = *(const float4*)(Ap + (size_t)prow * K + pc4);
    ra1 = *(const float4*)(Ap + (size_t)(prow + 64) * K + pc4);
    rb0 = *(const float4*)(Bp + (size_t)prow * K + pc4);
    rb1 = *(const float4*)(Bp + (size_t)(prow + 64) * K + pc4);
    stA(Af[0], prow, pc4, ra0);
    stA(Af[0], prow + 64, pc4, ra1);
    stB(Bf[0], prow, pc4, rb0);
    stB(Bf[0], prow + 64, pc4, rb1);
    __syncthreads();

    for (int it = 0; it < kiters; ++it) {
        if (it + 1 < kiters) {
            const float* Apn = Ap + (it + 1) * GBK;
            const float* Bpn = Bp + (it + 1) * GBK;
            ra0 = *(const float4*)(Apn + (size_t)prow * K + pc4);
            ra1 = *(const float4*)(Apn + (size_t)(prow + 64) * K + pc4);
            rb0 = *(const float4*)(Bpn + (size_t)prow * K + pc4);
            rb1 = *(const float4*)(Bpn + (size_t)(prow + 64) * K + pc4);
        }

        const float* af = Af[it & 1];
        const float* bf = Bf[it & 1];
#pragma unroll
        for (int ks = 0; ks < 2; ++ks) {
            uint32_t afr[4][4], bfr[4][2];
#pragma unroll
            for (int mt = 0; mt < 4; mt++) {
                const float4 av =
                    *(const float4*)&af[((wmb + mt) * 2 + ks) * ABLK + lane * 4];
                afr[mt][0] = __float_as_uint(av.x);
                afr[mt][1] = __float_as_uint(av.y);
                afr[mt][2] = __float_as_uint(av.z);
                afr[mt][3] = __float_as_uint(av.w);
            }
#pragma unroll
            for (int nt = 0; nt < 4; nt++) {
                const float2 bv =
                    *(const float2*)&bf[((wnb + nt) * 2 + ks) * BBLK + lane * 2];
                bfr[nt][0] = __float_as_uint(bv.x);
                bfr[nt][1] = __float_as_uint(bv.y);
            }
#pragma unroll
            for (int mt = 0; mt < 4; mt++)
#pragma unroll
                for (int nt = 0; nt < 4; nt++)
                    mma_tf32(acc[mt * 4 + nt], afr[mt], bfr[nt]);
        }

        if (it + 1 < kiters) {
            const int nb = (it + 1) & 1;
            stA(Af[nb], prow, pc4, ra0);
            stA(Af[nb], prow + 64, pc4, ra1);
            stB(Bf[nb], prow, pc4, rb0);
            stB(Bf[nb], prow + 64, pc4, rb1);
        }
        __syncthreads();
    }

#pragma unroll
    for (int mt = 0; mt < 4; mt++) {
        const int row = m0 + (wmb + mt) * 16 + lq;
#pragma unroll
        for (int nt = 0; nt < 4; nt++) {
            const int col = n0 + (wnb + nt) * 8 + 2 * lr;
            float* d = acc[mt * 4 + nt];
            *(float2*)(C + (size_t)row * N + col)       = make_float2(d[0], d[1]);
            *(float2*)(C + (size_t)(row + 8) * N + col) = make_float2(d[2], d[3]);
        }
    }
}

// ---------------------------------------------------------------------------
// Tensor-core flash attention, fragment-layout smem, exp2 softmax.
// Block: 128 q rows x (head, batch), 8 warps, warp owns 16 q rows.
// 64-key sub-tiles.
//   Qf: 8 wq x 8 kb A-frag blocks (132 fl each)  = 8448 floats (persistent)
//   Kf: 8 nt x 8 kb B-frag blocks (66 fl each)   = 4224 floats
//   Vf: 8 kt x 8 nb B-frag blocks (66 fl each)   = 4224 floats
// ---------------------------------------------------------------------------
#define ATTN_SMEM ((8448 + 4224 + 4224) * 4)

__global__ __launch_bounds__(256, 2)
void attn_mma(const float* __restrict__ Q, const float* __restrict__ Kg,
              const float* __restrict__ Vg, float* __restrict__ Y) {
    extern __shared__ float sm[];
    float* Qf = sm;              // persistent
    float* Kf = sm + 8448;
    float* Vf = Kf + 4224;

    const int qt = blockIdx.x;
    const int h  = blockIdx.y;
    const int b  = blockIdx.z;
    const int kv = h >> 1;

    const int tid  = threadIdx.x;
    const int lane = tid & 31;
    const int wid  = tid >> 5;
    const int lq   = lane >> 2;
    const int lr   = lane & 3;

    const float* qp = Q + ((size_t)(b * T_SEQ + qt * 128)) * DMODEL + h * DHEAD;
    const float* kbase = Kg + ((size_t)(b * T_SEQ)) * NKV_DIM + kv * DHEAD;
    const float* vbase = Vg + ((size_t)(b * T_SEQ)) * NKV_DIM + kv * DHEAD;

    // ---- stage Q (scaled by 1/8*log2e, tf32) into A-frag layout ----
#pragma unroll
    for (int i = 0; i < 8; i++) {
        int ff = i * 256 + tid;          // 2048 float4
        int r  = ff >> 4;                // q row 0..127
        int c4 = (ff & 15) * 4;          // k col
        float4 v = *(const float4*)(qp + (size_t)r * DMODEL + c4);
        v.x *= QSCALE; v.y *= QSCALE; v.z *= QSCALE; v.w *= QSCALE;
        // A-frag scatter: blk = (r>>4)*8 + kb  (kb-count 8 here)
        const int blk  = (r >> 4) * 8 + (c4 >> 3);
        const int slot = ((r >> 3) & 1) + 2 * ((c4 >> 2) & 1);
        float* p = Qf + blk * ABLK + ((r & 7) * 4) * 4 + slot;
        p[0]  = tf32r(v.x);
        p[4]  = tf32r(v.y);
        p[8]  = tf32r(v.z);
        p[12] = tf32r(v.w);
    }

    float o[8][4];
#pragma unroll
    for (int i = 0; i < 8; i++)
#pragma unroll
        for (int j = 0; j < 4; j++) o[i][j] = 0.0f;
    float m0 = -1e30f, m1 = -1e30f, l0 = 0.0f, l1 = 0.0f;

    const int srcA = (lane & ~3) | (lr >> 1);
    const int srcB = srcA + 2;
    const bool odd = lr & 1;

    for (int st = 0; st < T_SEQ / 64; st++) {
        __syncthreads();   // previous sub-tile consumed (first iter: Q staged)
        const float* kp = kbase + (size_t)st * 64 * NKV_DIM;
        const float* vp = vbase + (size_t)st * 64 * NKV_DIM;
#pragma unroll
        for (int i = 0; i < 4; i++) {
            int ff = i * 256 + tid;      // 1024 float4: 64 rows x 16 f4
            int r  = ff >> 4;            // key row 0..63
            int c4 = (ff & 15) * 4;      // d col
            float4 kvv = *(const float4*)(kp + (size_t)r * NKV_DIM + c4);
            {   // K -> B-frag layout: blk = (r>>3)*8 + kb
                const int blk  = (r >> 3) * 8 + (c4 >> 3);
                const int slot = (c4 >> 2) & 1;
                float* p = Kf + blk * BBLK + ((r & 7) * 4) * 2 + slot;
                p[0] = tf32r(kvv.x);
                p[2] = tf32r(kvv.y);
                p[4] = tf32r(kvv.z);
                p[6] = tf32r(kvv.w);
            }
            float4 vv = *(const float4*)(vp + (size_t)r * NKV_DIM + c4);
            {   // V -> B-frag layout (k = key, n = d): blk = (r>>3)*8 + nb
                const int blk  = (r >> 3) * 8 + (c4 >> 3);
                const int slot = (r >> 2) & 1;
                float* p = Vf + blk * BBLK + ((c4 & 7) * 4 + (r & 3)) * 2 + slot;
                p[0] = tf32r(vv.x);
                p[8] = tf32r(vv.y);      // next d -> lane+4 -> +8 floats
                p[16] = tf32r(vv.z);
                p[24] = tf32r(vv.w);
            }
        }
        __syncthreads();

        // ---- S = Q @ K^T : 8 n-tiles of 16x8, K=64 ----
        float sf[8][4];
#pragma unroll
        for (int nt = 0; nt < 8; nt++)
            sf[nt][0] = sf[nt][1] = sf[nt][2] = sf[nt][3] = 0.0f;

#pragma unroll
        for (int kb = 0; kb < 8; kb++) {
            uint32_t qfr[4];
            const float4 qv =
                *(const float4*)&Qf[(wid * 8 + kb) * ABLK + lane * 4];
            qfr[0] = __float_as_uint(qv.x);
            qfr[1] = __float_as_uint(qv.y);
            qfr[2] = __float_as_uint(qv.z);
            qfr[3] = __float_as_uint(qv.w);
#pragma unroll
            for (int nt = 0; nt < 8; nt++) {
                uint32_t bfr[2];
                const float2 bv =
                    *(const float2*)&Kf[(nt * 8 + kb) * BBLK + lane * 2];
                bfr[0] = __float_as_uint(bv.x);
                bfr[1] = __float_as_uint(bv.y);
                mma_tf32(sf[nt], qfr, bfr);
            }
        }

        // ---- online softmax in log2 domain (rows lq, lq+8) ----
        float mx0 = -1e30f, mx1 = -1e30f;
#pragma unroll
        for (int nt = 0; nt < 8; nt++) {
            mx0 = fmaxf(mx0, fmaxf(sf[nt][0], sf[nt][1]));
            mx1 = fmaxf(mx1, fmaxf(sf[nt][2], sf[nt][3]));
        }
        mx0 = fmaxf(mx0, __shfl_xor_sync(0xffffffffu, mx0, 1));
        mx0 = fmaxf(mx0, __shfl_xor_sync(0xffffffffu, mx0, 2));
        mx1 = fmaxf(mx1, __shfl_xor_sync(0xffffffffu, mx1, 1));
        mx1 = fmaxf(mx1, __shfl_xor_sync(0xffffffffu, mx1, 2));

        const float mn0 = fmaxf(m0, mx0);
        const float mn1 = fmaxf(m1, mx1);
        const float al0 = ex2f(m0 - mn0);
        const float al1 = ex2f(m1 - mn1);
        m0 = mn0; m1 = mn1;

        float s0 = 0.0f, s1 = 0.0f;
#pragma unroll
        for (int nt = 0; nt < 8; nt++) {
            sf[nt][0] = ex2f(sf[nt][0] - mn0); s0 += sf[nt][0];
            sf[nt][1] = ex2f(sf[nt][1] - mn0); s0 += sf[nt][1];
            sf[nt][2] = ex2f(sf[nt][2] - mn1); s1 += sf[nt][2];
            sf[nt][3] = ex2f(sf[nt][3] - mn1); s1 += sf[nt][3];
        }
        s0 += __shfl_xor_sync(0xffffffffu, s0, 1);
        s0 += __shfl_xor_sync(0xffffffffu, s0, 2);
        s1 += __shfl_xor_sync(0xffffffffu, s1, 1);
        s1 += __shfl_xor_sync(0xffffffffu, s1, 2);
        l0 = l0 * al0 + s0;
        l1 = l1 * al1 + s1;

#pragma unroll
        for (int nb = 0; nb < 8; nb++) {
            o[nb][0] *= al0; o[nb][1] *= al0;
            o[nb][2] *= al1; o[nb][3] *= al1;
        }

        // ---- PV: per key k-step, convert P tile to A-frag, MMA over d ----
#pragma unroll
        for (int kt = 0; kt < 8; kt++) {
            float p0 = sf[kt][0], p1 = sf[kt][1], p2 = sf[kt][2], p3 = sf[kt][3];
            float e0 = __shfl_sync(0xffffffffu, p0, srcA);
            float e1 = __shfl_sync(0xffffffffu, p1, srcA);
            float e2 = __shfl_sync(0xffffffffu, p2, srcA);
            float e3 = __shfl_sync(0xffffffffu, p3, srcA);
            float f0 = __shfl_sync(0xffffffffu, p0, srcB);
            float f1 = __shfl_sync(0xffffffffu, p1, srcB);
            float f2 = __shfl_sync(0xffffffffu, p2, srcB);
            float f3 = __shfl_sync(0xffffffffu, p3, srcB);
            uint32_t pa[4];
            pa[0] = tf32u(odd ? e1 : e0);
            pa[1] = tf32u(odd ? e3 : e2);
            pa[2] = tf32u(odd ? f1 : f0);
            pa[3] = tf32u(odd ? f3 : f2);

#pragma unroll
            for (int nb = 0; nb < 8; nb++) {
                uint32_t bfr[2];
                const float2 bv =
                    *(const float2*)&Vf[(kt * 8 + nb) * BBLK + lane * 2];
                bfr[0] = __float_as_uint(bv.x);
                bfr[1] = __float_as_uint(bv.y);
                mma_tf32(o[nb], pa, bfr);
            }
        }
    }

    // ---- epilogue ----
    const float inv0 = 1.0f / l0;
    const float inv1 = 1.0f / l1;
    float* yp = Y + ((size_t)(b * T_SEQ + qt * 128 + wid * 16)) * DMODEL + h * DHEAD;
#pragma unroll
    for (int nb = 0; nb < 8; nb++) {
        const int col = nb * 8 + 2 * lr;
        *(float2*)(yp + (size_t)lq * DMODEL + col) =
            make_float2(o[nb][0] * inv0, o[nb][1] * inv0);
        *(float2*)(yp + (size_t)(lq + 8) * DMODEL + col) =
            make_float2(o[nb][2] * inv1, o[nb][3] * inv1);
    }
}

// ---------------------------------------------------------------------------
// Launch
// ---------------------------------------------------------------------------
extern "C" void kernel_launch(void* const* d_in, const int* in_sizes, int n_in,
                              void* d_out, int out_size) {
    const float* x     = (const float*)d_in[0];
    const float* Wq    = (const float*)d_in[1];
    const float* Wk    = (const float*)d_in[2];
    const float* Wv    = (const float*)d_in[3];
    const float* Wproj = (const float*)d_in[4];
    float* out = (float*)d_out;

    void *pq, *pk, *pv, *py;
    cudaGetSymbolAddress(&pq, g_q);
    cudaGetSymbolAddress(&pk, g_k);
    cudaGetSymbolAddress(&pv, g_v);
    cudaGetSymbolAddress(&py, g_y);

    cudaFuncSetAttribute(attn_mma, cudaFuncAttributeMaxDynamicSharedMemorySize,
                         ATTN_SMEM);

    dim3 blk(256);
    gemm_mma<<<dim3(DMODEL / 128, MTOT / 128), blk>>>(x, Wq, (float*)pq,
                                                      MTOT, DMODEL, DMODEL);
    gemm_mma<<<dim3(NKV_DIM / 128, MTOT / 128), blk>>>(x, Wk, (float*)pk,
                                                       MTOT, NKV_DIM, DMODEL);
    gemm_mma<<<dim3(NKV_DIM / 128, MTOT / 128), blk>>>(x, Wv, (float*)pv,
                                                       MTOT, NKV_DIM, DMODEL);
    attn_mma<<<dim3(T_SEQ / 128, NHEADS, BATCH), blk, ATTN_SMEM>>>(
        (const float*)pq, (const float*)pk, (const float*)pv, (float*)py);
    gemm_mma<<<dim3(DMODEL / 128, MTOT / 128), blk>>>((const float*)py, Wproj,
                                                      out, MTOT, DMODEL, DMODEL);
}

// round 9
// speedup vs baseline: 3.5358x; 1.1131x over previous
#include <cuda_runtime.h>
#include <cuda_bf16.h>
#include <cstdint>
#include <math.h>

// ---------------------------------------------------------------------------
// GQA block: y = proj( attn( x@Wq^T, x@Wk^T, x@Wv^T ) )
// B=2, T=2048, D_MODEL=1024, N_HEADS=16, N_KV=8, GROUP=2, D_HEAD=64
// R9: attention warps own 32 q-rows (2 m-tiles) so each K/V B-fragment
//     feeds 2 MMAs (halves smem load traffic per unit work). QKV fused
//     into one GEMM launch. Numerics unchanged from R8.
// ---------------------------------------------------------------------------

#define BATCH   2
#define T_SEQ   2048
#define DMODEL  1024
#define NKV_DIM 512
#define NHEADS  16
#define DHEAD   64
#define QSCALE  0.18033688f   // 64^-0.5 * log2(e)

#define MTOT (BATCH * T_SEQ)   // 4096 rows

__device__ float g_q[(size_t)MTOT * DMODEL];
__device__ float g_k[(size_t)MTOT * NKV_DIM];
__device__ float g_v[(size_t)MTOT * NKV_DIM];
__device__ float g_y[(size_t)MTOT * DMODEL];

// ---------------------------------------------------------------------------
// helpers
// ---------------------------------------------------------------------------
__device__ __forceinline__ float tf32r(float f) {
    uint32_t r;
    asm("cvt.rna.tf32.f32 %0, %1;" : "=r"(r) : "f"(f));
    return __uint_as_float(r);
}
__device__ __forceinline__ uint32_t tf32u(float f) {
    uint32_t r;
    asm("cvt.rna.tf32.f32 %0, %1;" : "=r"(r) : "f"(f));
    return r;
}
__device__ __forceinline__ float ex2f(float x) {
    float y;
    asm("ex2.approx.f32 %0, %1;" : "=f"(y) : "f"(x));
    return y;
}

__device__ __forceinline__ void mma_tf32(float* d, const uint32_t* a,
                                         const uint32_t* b) {
    asm volatile(
        "mma.sync.aligned.m16n8k8.row.col.f32.tf32.tf32.f32 "
        "{%0,%1,%2,%3}, {%4,%5,%6,%7}, {%8,%9}, {%0,%1,%2,%3};"
        : "+f"(d[0]), "+f"(d[1]), "+f"(d[2]), "+f"(d[3])
        : "r"(a[0]), "r"(a[1]), "r"(a[2]), "r"(a[3]), "r"(b[0]), "r"(b[1]));
}

// Fragment-layout smem blocks (proven R8):
#define ABLK 132
#define BBLK 66

__device__ __forceinline__ void stA(float* buf, int r, int c4, float4 v) {
    const int blk  = (r >> 4) * 2 + (c4 >> 3);
    const int slot = ((r >> 3) & 1) + 2 * ((c4 >> 2) & 1);
    float* p = buf + blk * ABLK + ((r & 7) * 4) * 4 + slot;
    p[0]  = tf32r(v.x);
    p[4]  = tf32r(v.y);
    p[8]  = tf32r(v.z);
    p[12] = tf32r(v.w);
}
__device__ __forceinline__ void stB(float* buf, int r, int c4, float4 v) {
    const int blk  = (r >> 3) * 2 + (c4 >> 3);
    const int slot = (c4 >> 2) & 1;
    float* p = buf + blk * BBLK + ((r & 7) * 4) * 2 + slot;
    p[0] = tf32r(v.x);
    p[2] = tf32r(v.y);
    p[4] = tf32r(v.z);
    p[6] = tf32r(v.w);
}

// ---------------------------------------------------------------------------
// Shared GEMM mainloop body (CTA tile 128x128, BK=16, frag-layout smem,
// 8 warps 2x4, warp tile 64x32). Writes acc; caller does epilogue.
// ---------------------------------------------------------------------------
#define GBK 16

struct GemmCtx {
    const float* Ap;
    const float* Bp;
    int K;
};

__device__ __forceinline__ void gemm_mainloop(const GemmCtx& g, float acc[16][4],
                                              float Af[2][16 * ABLK],
                                              float Bf[2][32 * BBLK]) {
    const int tid  = threadIdx.x;
    const int lane = tid & 31;
    const int wid  = tid >> 5;
    const int wmb  = (wid & 1) * 4;
    const int wnb  = (wid >> 1) * 4;
    const int K = g.K;

    const int prow = tid >> 2;
    const int pc4  = (tid & 3) * 4;

#pragma unroll
    for (int i = 0; i < 16; i++)
#pragma unroll
        for (int j = 0; j < 4; j++) acc[i][j] = 0.0f;

    const int kiters = K / GBK;
    float4 ra0, ra1, rb0, rb1;

    ra0 = *(const float4*)(g.Ap + (size_t)prow * K + pc4);
    ra1 = *(const float4*)(g.Ap + (size_t)(prow + 64) * K + pc4);
    rb0 = *(const float4*)(g.Bp + (size_t)prow * K + pc4);
    rb1 = *(const float4*)(g.Bp + (size_t)(prow + 64) * K + pc4);
    stA(Af[0], prow, pc4, ra0);
    stA(Af[0], prow + 64, pc4, ra1);
    stB(Bf[0], prow, pc4, rb0);
    stB(Bf[0], prow + 64, pc4, rb1);
    __syncthreads();

    for (int it = 0; it < kiters; ++it) {
        if (it + 1 < kiters) {
            const float* Apn = g.Ap + (it + 1) * GBK;
            const float* Bpn = g.Bp + (it + 1) * GBK;
            ra0 = *(const float4*)(Apn + (size_t)prow * K + pc4);
            ra1 = *(const float4*)(Apn + (size_t)(prow + 64) * K + pc4);
            rb0 = *(const float4*)(Bpn + (size_t)prow * K + pc4);
            rb1 = *(const float4*)(Bpn + (size_t)(prow + 64) * K + pc4);
        }

        const float* af = Af[it & 1];
        const float* bf = Bf[it & 1];
#pragma unroll
        for (int ks = 0; ks < 2; ++ks) {
            uint32_t afr[4][4], bfr[4][2];
#pragma unroll
            for (int mt = 0; mt < 4; mt++) {
                const float4 av =
                    *(const float4*)&af[((wmb + mt) * 2 + ks) * ABLK + lane * 4];
                afr[mt][0] = __float_as_uint(av.x);
                afr[mt][1] = __float_as_uint(av.y);
                afr[mt][2] = __float_as_uint(av.z);
                afr[mt][3] = __float_as_uint(av.w);
            }
#pragma unroll
            for (int nt = 0; nt < 4; nt++) {
                const float2 bv =
                    *(const float2*)&bf[((wnb + nt) * 2 + ks) * BBLK + lane * 2];
                bfr[nt][0] = __float_as_uint(bv.x);
                bfr[nt][1] = __float_as_uint(bv.y);
            }
#pragma unroll
            for (int mt = 0; mt < 4; mt++)
#pragma unroll
                for (int nt = 0; nt < 4; nt++)
                    mma_tf32(acc[mt * 4 + nt], afr[mt], bfr[nt]);
        }

        if (it + 1 < kiters) {
            const int nb = (it + 1) & 1;
            stA(Af[nb], prow, pc4, ra0);
            stA(Af[nb], prow + 64, pc4, ra1);
            stB(Bf[nb], prow, pc4, rb0);
            stB(Bf[nb], prow + 64, pc4, rb1);
        }
        __syncthreads();
    }
}

// Fused QKV projection: grid.x 0..7 -> Wq/g_q, 8..11 -> Wk/g_k, 12..15 -> Wv/g_v
__global__ __launch_bounds__(256, 2)
void gemm_qkv(const float* __restrict__ x,
              const float* __restrict__ Wq, const float* __restrict__ Wk,
              const float* __restrict__ Wv,
              float* __restrict__ q, float* __restrict__ k,
              float* __restrict__ v) {
    __shared__ float Af[2][16 * ABLK];
    __shared__ float Bf[2][32 * BBLK];

    const int nb = blockIdx.x;
    const int m0 = blockIdx.y * 128;

    const float* W; float* C; int ldc, n0;
    if (nb < 8)       { W = Wq; C = q; ldc = DMODEL;  n0 = nb * 128; }
    else if (nb < 12) { W = Wk; C = k; ldc = NKV_DIM; n0 = (nb - 8) * 128; }
    else              { W = Wv; C = v; ldc = NKV_DIM; n0 = (nb - 12) * 128; }

    GemmCtx g;
    g.Ap = x + (size_t)m0 * DMODEL;
    g.Bp = W + (size_t)n0 * DMODEL;
    g.K  = DMODEL;

    float acc[16][4];
    gemm_mainloop(g, acc, Af, Bf);

    const int tid  = threadIdx.x;
    const int lane = tid & 31;
    const int wid  = tid >> 5;
    const int wmb  = (wid & 1) * 4;
    const int wnb  = (wid >> 1) * 4;
    const int lq   = lane >> 2;
    const int lr   = lane & 3;

#pragma unroll
    for (int mt = 0; mt < 4; mt++) {
        const int row = m0 + (wmb + mt) * 16 + lq;
#pragma unroll
        for (int nt = 0; nt < 4; nt++) {
            const int col = n0 + (wnb + nt) * 8 + 2 * lr;
            float* d = acc[mt * 4 + nt];
            *(float2*)(C + (size_t)row * ldc + col)       = make_float2(d[0], d[1]);
            *(float2*)(C + (size_t)(row + 8) * ldc + col) = make_float2(d[2], d[3]);
        }
    }
}

// Output projection (generic)
__global__ __launch_bounds__(256, 2)
void gemm_mma(const float* __restrict__ A, const float* __restrict__ B,
              float* __restrict__ C, int M, int N, int K) {
    __shared__ float Af[2][16 * ABLK];
    __shared__ float Bf[2][32 * BBLK];

    const int m0 = blockIdx.y * 128;
    const int n0 = blockIdx.x * 128;

    GemmCtx g;
    g.Ap = A + (size_t)m0 * K;
    g.Bp = B + (size_t)n0 * K;
    g.K  = K;

    float acc[16][4];
    gemm_mainloop(g, acc, Af, Bf);

    const int tid  = threadIdx.x;
    const int lane = tid & 31;
    const int wid  = tid >> 5;
    const int wmb  = (wid & 1) * 4;
    const int wnb  = (wid >> 1) * 4;
    const int lq   = lane >> 2;
    const int lr   = lane & 3;

#pragma unroll
    for (int mt = 0; mt < 4; mt++) {
        const int row = m0 + (wmb + mt) * 16 + lq;
#pragma unroll
        for (int nt = 0; nt < 4; nt++) {
            const int col = n0 + (wnb + nt) * 8 + 2 * lr;
            float* d = acc[mt * 4 + nt];
            *(float2*)(C + (size_t)row * N + col)       = make_float2(d[0], d[1]);
            *(float2*)(C + (size_t)(row + 8) * N + col) = make_float2(d[2], d[3]);
        }
    }
}

// ---------------------------------------------------------------------------
// Tensor-core flash attention. R9: 128 threads / 4 warps per block; each warp
// owns 32 q rows (2 m-tiles) so every K/V B-frag load feeds 2 MMAs.
// 64-key sub-tiles; fragment-layout smem; exp2 softmax.
//   Qf: 8 m-tiles x 8 kb A-frag blocks = 8448 floats (persistent)
//   Kf: 8 nt x 8 kb B-frag blocks     = 4224 floats
//   Vf: 8 kt x 8 nb B-frag blocks     = 4224 floats
// ---------------------------------------------------------------------------
#define ATTN_SMEM ((8448 + 4224 + 4224) * 4)

__global__ __launch_bounds__(128, 2)
void attn_mma(const float* __restrict__ Q, const float* __restrict__ Kg,
              const float* __restrict__ Vg, float* __restrict__ Y) {
    extern __shared__ float sm[];
    float* Qf = sm;              // persistent
    float* Kf = sm + 8448;
    float* Vf = Kf + 4224;

    const int qt = blockIdx.x;
    const int h  = blockIdx.y;
    const int b  = blockIdx.z;
    const int kv = h >> 1;

    const int tid  = threadIdx.x;
    const int lane = tid & 31;
    const int wid  = tid >> 5;       // 0..3; owns m-tiles 2*wid, 2*wid+1
    const int lq   = lane >> 2;
    const int lr   = lane & 3;

    const float* qp = Q + ((size_t)(b * T_SEQ + qt * 128)) * DMODEL + h * DHEAD;
    const float* kbase = Kg + ((size_t)(b * T_SEQ)) * NKV_DIM + kv * DHEAD;
    const float* vbase = Vg + ((size_t)(b * T_SEQ)) * NKV_DIM + kv * DHEAD;

    // ---- stage Q (scaled, tf32) into A-frag layout ----
#pragma unroll
    for (int i = 0; i < 16; i++) {
        int ff = i * 128 + tid;          // 2048 float4
        int r  = ff >> 4;                // q row 0..127
        int c4 = (ff & 15) * 4;
        float4 v = *(const float4*)(qp + (size_t)r * DMODEL + c4);
        v.x *= QSCALE; v.y *= QSCALE; v.z *= QSCALE; v.w *= QSCALE;
        const int blk  = (r >> 4) * 8 + (c4 >> 3);
        const int slot = ((r >> 3) & 1) + 2 * ((c4 >> 2) & 1);
        float* p = Qf + blk * ABLK + ((r & 7) * 4) * 4 + slot;
        p[0]  = tf32r(v.x);
        p[4]  = tf32r(v.y);
        p[8]  = tf32r(v.z);
        p[12] = tf32r(v.w);
    }

    float oA[8][4], oB[8][4];
#pragma unroll
    for (int i = 0; i < 8; i++)
#pragma unroll
        for (int j = 0; j < 4; j++) { oA[i][j] = 0.0f; oB[i][j] = 0.0f; }
    float mA0 = -1e30f, mA1 = -1e30f, lA0 = 0.0f, lA1 = 0.0f;
    float mB0 = -1e30f, mB1 = -1e30f, lB0 = 0.0f, lB1 = 0.0f;

    const int srcA = (lane & ~3) | (lr >> 1);
    const int srcB = srcA + 2;
    const bool odd = lr & 1;
    const int mtA = wid * 2;
    const int mtB = wid * 2 + 1;

    for (int st = 0; st < T_SEQ / 64; st++) {
        __syncthreads();
        const float* kp = kbase + (size_t)st * 64 * NKV_DIM;
        const float* vp = vbase + (size_t)st * 64 * NKV_DIM;
#pragma unroll
        for (int i = 0; i < 8; i++) {
            int ff = i * 128 + tid;      // 1024 float4: 64 rows x 16 f4
            int r  = ff >> 4;            // key row 0..63
            int c4 = (ff & 15) * 4;
            float4 kvv = *(const float4*)(kp + (size_t)r * NKV_DIM + c4);
            {   // K -> B-frag: blk = (r>>3)*8 + kb
                const int blk  = (r >> 3) * 8 + (c4 >> 3);
                const int slot = (c4 >> 2) & 1;
                float* p = Kf + blk * BBLK + ((r & 7) * 4) * 2 + slot;
                p[0] = tf32r(kvv.x);
                p[2] = tf32r(kvv.y);
                p[4] = tf32r(kvv.z);
                p[6] = tf32r(kvv.w);
            }
            float4 vv = *(const float4*)(vp + (size_t)r * NKV_DIM + c4);
            {   // V -> B-frag (n=d, k=key)
                const int blk  = (r >> 3) * 8 + (c4 >> 3);
                const int slot = (r >> 2) & 1;
                float* p = Vf + blk * BBLK + ((c4 & 7) * 4 + (r & 3)) * 2 + slot;
                p[0]  = tf32r(vv.x);
                p[8]  = tf32r(vv.y);
                p[16] = tf32r(vv.z);
                p[24] = tf32r(vv.w);
            }
        }
        __syncthreads();

        // ---- S = Q @ K^T for both m-tiles; K frag shared ----
        float sfA[8][4], sfB[8][4];
#pragma unroll
        for (int nt = 0; nt < 8; nt++) {
            sfA[nt][0] = sfA[nt][1] = sfA[nt][2] = sfA[nt][3] = 0.0f;
            sfB[nt][0] = sfB[nt][1] = sfB[nt][2] = sfB[nt][3] = 0.0f;
        }

#pragma unroll
        for (int kb = 0; kb < 8; kb++) {
            uint32_t qa[4], qb[4];
            {
                const float4 v =
                    *(const float4*)&Qf[(mtA * 8 + kb) * ABLK + lane * 4];
                qa[0] = __float_as_uint(v.x); qa[1] = __float_as_uint(v.y);
                qa[2] = __float_as_uint(v.z); qa[3] = __float_as_uint(v.w);
            }
            {
                const float4 v =
                    *(const float4*)&Qf[(mtB * 8 + kb) * ABLK + lane * 4];
                qb[0] = __float_as_uint(v.x); qb[1] = __float_as_uint(v.y);
                qb[2] = __float_as_uint(v.z); qb[3] = __float_as_uint(v.w);
            }
#pragma unroll
            for (int nt = 0; nt < 8; nt++) {
                uint32_t bfr[2];
                const float2 bv =
                    *(const float2*)&Kf[(nt * 8 + kb) * BBLK + lane * 2];
                bfr[0] = __float_as_uint(bv.x);
                bfr[1] = __float_as_uint(bv.y);
                mma_tf32(sfA[nt], qa, bfr);
                mma_tf32(sfB[nt], qb, bfr);
            }
        }

        // ---- online softmax (log2 domain) for each m-tile ----
        {
            float mx0 = -1e30f, mx1 = -1e30f;
#pragma unroll
            for (int nt = 0; nt < 8; nt++) {
                mx0 = fmaxf(mx0, fmaxf(sfA[nt][0], sfA[nt][1]));
                mx1 = fmaxf(mx1, fmaxf(sfA[nt][2], sfA[nt][3]));
            }
            mx0 = fmaxf(mx0, __shfl_xor_sync(0xffffffffu, mx0, 1));
            mx0 = fmaxf(mx0, __shfl_xor_sync(0xffffffffu, mx0, 2));
            mx1 = fmaxf(mx1, __shfl_xor_sync(0xffffffffu, mx1, 1));
            mx1 = fmaxf(mx1, __shfl_xor_sync(0xffffffffu, mx1, 2));
            const float mn0 = fmaxf(mA0, mx0);
            const float mn1 = fmaxf(mA1, mx1);
            const float al0 = ex2f(mA0 - mn0);
            const float al1 = ex2f(mA1 - mn1);
            mA0 = mn0; mA1 = mn1;
            float s0 = 0.0f, s1 = 0.0f;
#pragma unroll
            for (int nt = 0; nt < 8; nt++) {
                sfA[nt][0] = ex2f(sfA[nt][0] - mn0); s0 += sfA[nt][0];
                sfA[nt][1] = ex2f(sfA[nt][1] - mn0); s0 += sfA[nt][1];
                sfA[nt][2] = ex2f(sfA[nt][2] - mn1); s1 += sfA[nt][2];
                sfA[nt][3] = ex2f(sfA[nt][3] - mn1); s1 += sfA[nt][3];
            }
            s0 += __shfl_xor_sync(0xffffffffu, s0, 1);
            s0 += __shfl_xor_sync(0xffffffffu, s0, 2);
            s1 += __shfl_xor_sync(0xffffffffu, s1, 1);
            s1 += __shfl_xor_sync(0xffffffffu, s1, 2);
            lA0 = lA0 * al0 + s0;
            lA1 = lA1 * al1 + s1;
#pragma unroll
            for (int nb = 0; nb < 8; nb++) {
                oA[nb][0] *= al0; oA[nb][1] *= al0;
                oA[nb][2] *= al1; oA[nb][3] *= al1;
            }
        }
        {
            float mx0 = -1e30f, mx1 = -1e30f;
#pragma unroll
            for (int nt = 0; nt < 8; nt++) {
                mx0 = fmaxf(mx0, fmaxf(sfB[nt][0], sfB[nt][1]));
                mx1 = fmaxf(mx1, fmaxf(sfB[nt][2], sfB[nt][3]));
            }
            mx0 = fmaxf(mx0, __shfl_xor_sync(0xffffffffu, mx0, 1));
            mx0 = fmaxf(mx0, __shfl_xor_sync(0xffffffffu, mx0, 2));
            mx1 = fmaxf(mx1, __shfl_xor_sync(0xffffffffu, mx1, 1));
            mx1 = fmaxf(mx1, __shfl_xor_sync(0xffffffffu, mx1, 2));
            const float mn0 = fmaxf(mB0, mx0);
            const float mn1 = fmaxf(mB1, mx1);
            const float al0 = ex2f(mB0 - mn0);
            const float al1 = ex2f(mB1 - mn1);
            mB0 = mn0; mB1 = mn1;
            float s0 = 0.0f, s1 = 0.0f;
#pragma unroll
            for (int nt = 0; nt < 8; nt++) {
                sfB[nt][0] = ex2f(sfB[nt][0] - mn0); s0 += sfB[nt][0];
                sfB[nt][1] = ex2f(sfB[nt][1] - mn0); s0 += sfB[nt][1];
                sfB[nt][2] = ex2f(sfB[nt][2] - mn1); s1 += sfB[nt][2];
                sfB[nt][3] = ex2f(sfB[nt][3] - mn1); s1 += sfB[nt][3];
            }
            s0 += __shfl_xor_sync(0xffffffffu, s0, 1);
            s0 += __shfl_xor_sync(0xffffffffu, s0, 2);
            s1 += __shfl_xor_sync(0xffffffffu, s1, 1);
            s1 += __shfl_xor_sync(0xffffffffu, s1, 2);
            lB0 = lB0 * al0 + s0;
            lB1 = lB1 * al1 + s1;
#pragma unroll
            for (int nb = 0; nb < 8; nb++) {
                oB[nb][0] *= al0; oB[nb][1] *= al0;
                oB[nb][2] *= al1; oB[nb][3] *= al1;
            }
        }

        // ---- PV: V frag shared across both m-tiles ----
#pragma unroll
        for (int kt = 0; kt < 8; kt++) {
            uint32_t paA[4], paB[4];
            {
                float p0 = sfA[kt][0], p1 = sfA[kt][1];
                float p2 = sfA[kt][2], p3 = sfA[kt][3];
                float e0 = __shfl_sync(0xffffffffu, p0, srcA);
                float e1 = __shfl_sync(0xffffffffu, p1, srcA);
                float e2 = __shfl_sync(0xffffffffu, p2, srcA);
                float e3 = __shfl_sync(0xffffffffu, p3, srcA);
                float f0 = __shfl_sync(0xffffffffu, p0, srcB);
                float f1 = __shfl_sync(0xffffffffu, p1, srcB);
                float f2 = __shfl_sync(0xffffffffu, p2, srcB);
                float f3 = __shfl_sync(0xffffffffu, p3, srcB);
                paA[0] = tf32u(odd ? e1 : e0);
                paA[1] = tf32u(odd ? e3 : e2);
                paA[2] = tf32u(odd ? f1 : f0);
                paA[3] = tf32u(odd ? f3 : f2);
            }
            {
                float p0 = sfB[kt][0], p1 = sfB[kt][1];
                float p2 = sfB[kt][2], p3 = sfB[kt][3];
                float e0 = __shfl_sync(0xffffffffu, p0, srcA);
                float e1 = __shfl_sync(0xffffffffu, p1, srcA);
                float e2 = __shfl_sync(0xffffffffu, p2, srcA);
                float e3 = __shfl_sync(0xffffffffu, p3, srcA);
                float f0 = __shfl_sync(0xffffffffu, p0, srcB);
                float f1 = __shfl_sync(0xffffffffu, p1, srcB);
                float f2 = __shfl_sync(0xffffffffu, p2, srcB);
                float f3 = __shfl_sync(0xffffffffu, p3, srcB);
                paB[0] = tf32u(odd ? e1 : e0);
                paB[1] = tf32u(odd ? e3 : e2);
                paB[2] = tf32u(odd ? f1 : f0);
                paB[3] = tf32u(odd ? f3 : f2);
            }

#pragma unroll
            for (int nb = 0; nb < 8; nb++) {
                uint32_t bfr[2];
                const float2 bv =
                    *(const float2*)&Vf[(kt * 8 + nb) * BBLK + lane * 2];
                bfr[0] = __float_as_uint(bv.x);
                bfr[1] = __float_as_uint(bv.y);
                mma_tf32(oA[nb], paA, bfr);
                mma_tf32(oB[nb], paB, bfr);
            }
        }
    }

    // ---- epilogue ----
    {
        const float i0 = 1.0f / lA0, i1 = 1.0f / lA1;
        float* yp = Y + ((size_t)(b * T_SEQ + qt * 128 + mtA * 16)) * DMODEL + h * DHEAD;
#pragma unroll
        for (int nb = 0; nb < 8; nb++) {
            const int col = nb * 8 + 2 * lr;
            *(float2*)(yp + (size_t)lq * DMODEL + col) =
                make_float2(oA[nb][0] * i0, oA[nb][1] * i0);
            *(float2*)(yp + (size_t)(lq + 8) * DMODEL + col) =
                make_float2(oA[nb][2] * i1, oA[nb][3] * i1);
        }
    }
    {
        const float i0 = 1.0f / lB0, i1 = 1.0f / lB1;
        float* yp = Y + ((size_t)(b * T_SEQ + qt * 128 + mtB * 16)) * DMODEL + h * DHEAD;
#pragma unroll
        for (int nb = 0; nb < 8; nb++) {
            const int col = nb * 8 + 2 * lr;
            *(float2*)(yp + (size_t)lq * DMODEL + col) =
                make_float2(oB[nb][0] * i0, oB[nb][1] * i0);
            *(float2*)(yp + (size_t)(lq + 8) * DMODEL + col) =
                make_float2(oB[nb][2] * i1, oB[nb][3] * i1);
        }
    }
}

// ---------------------------------------------------------------------------
// Launch
// ---------------------------------------------------------------------------
extern "C" void kernel_launch(void* const* d_in, const int* in_sizes, int n_in,
                              void* d_out, int out_size) {
    const float* x     = (const float*)d_in[0];
    const float* Wq    = (const float*)d_in[1];
    const float* Wk    = (const float*)d_in[2];
    const float* Wv    = (const float*)d_in[3];
    const float* Wproj = (const float*)d_in[4];
    float* out = (float*)d_out;

    void *pq, *pk, *pv, *py;
    cudaGetSymbolAddress(&pq, g_q);
    cudaGetSymbolAddress(&pk, g_k);
    cudaGetSymbolAddress(&pv, g_v);
    cudaGetSymbolAddress(&py, g_y);

    cudaFuncSetAttribute(attn_mma, cudaFuncAttributeMaxDynamicSharedMemorySize,
                         ATTN_SMEM);

    // fused QKV projection (16 n-blocks: 8 Q + 4 K + 4 V)
    gemm_qkv<<<dim3(16, MTOT / 128), dim3(256)>>>(
        x, Wq, Wk, Wv, (float*)pq, (float*)pk, (float*)pv);
    // attention
    attn_mma<<<dim3(T_SEQ / 128, NHEADS, BATCH), dim3(128), ATTN_SMEM>>>(
        (const float*)pq, (const float*)pk, (const float*)pv, (float*)py);
    // output projection
    gemm_mma<<<dim3(DMODEL / 128, MTOT / 128), dim3(256)>>>(
        (const float*)py, Wproj, out, MTOT, DMODEL, DMODEL);
}

// round 11
// speedup vs baseline: 5.7768x; 1.6338x over previous
#include <cuda_runtime.h>
#include <cuda_fp16.h>
#include <cstdint>
#include <math.h>

// ---------------------------------------------------------------------------
// GQA block: y = proj( attn( x@Wq^T, x@Wk^T, x@Wv^T ) )
// B=2, T=2048, D_MODEL=1024, N_HEADS=16, N_KV=8, GROUP=2, D_HEAD=64
// R10: everything on fp16 m16n8k16 (same 10-bit mantissa as tf32; half the
//      smem bytes and MMA instructions per MAC; PV C->A fragment conversion
//      becomes pure register packing, no shuffles).
// ---------------------------------------------------------------------------

#define BATCH   2
#define T_SEQ   2048
#define DMODEL  1024
#define NKV_DIM 512
#define NHEADS  16
#define DHEAD   64
#define QSCALE  0.18033688f   // 64^-0.5 * log2(e)

#define MTOT (BATCH * T_SEQ)   // 4096 rows

__device__ float g_q[(size_t)MTOT * DMODEL];
__device__ float g_k[(size_t)MTOT * NKV_DIM];
__device__ float g_v[(size_t)MTOT * NKV_DIM];
__device__ float g_y[(size_t)MTOT * DMODEL];

// ---------------------------------------------------------------------------
// helpers
// ---------------------------------------------------------------------------
__device__ __forceinline__ uint32_t h2(float a, float b) {
    __half2 h = __floats2half2_rn(a, b);
    return *(uint32_t*)&h;
}
__device__ __forceinline__ float ex2f(float x) {
    float y;
    asm("ex2.approx.f32 %0, %1;" : "=f"(y) : "f"(x));
    return y;
}

__device__ __forceinline__ void mma_f16(float* d, const uint32_t* a,
                                        const uint32_t* b) {
    asm volatile(
        "mma.sync.aligned.m16n8k16.row.col.f32.f16.f16.f32 "
        "{%0,%1,%2,%3}, {%4,%5,%6,%7}, {%8,%9}, {%0,%1,%2,%3};"
        : "+f"(d[0]), "+f"(d[1]), "+f"(d[2]), "+f"(d[3])
        : "r"(a[0]), "r"(a[1]), "r"(a[2]), "r"(a[3]), "r"(b[0]), "r"(b[1]));
}

// Fragment-layout smem blocks (uint32 = half2 units):
//  A-frag block: 16 rows x 16 k = 256 halves = 128 u32 (+4 pad = 132).
//    lane owns u32[lane*4 .. +3] = [a0,a1,a2,a3]  -> one LDS.128.
//  B-frag block: 8 n x 16 k = 128 halves = 64 u32 (+2 pad = 66).
//    lane owns u32[lane*2 .. +1] = [b0,b1]        -> one LDS.64.
#define ABLK 132
#define BBLK 66

// scatter fp32 float4 (row r, k-cols c4..c4+3) into fp16 A-frag layout
__device__ __forceinline__ void stAh(uint32_t* buf, int r, int c4, float4 v) {
    const uint32_t h0 = h2(v.x, v.y);
    const uint32_t h1 = h2(v.z, v.w);
    const int lane0 = (r & 7) * 4 + ((c4 & 7) >> 1);
    const int slot  = ((c4 >> 3) & 1) * 2 + ((r >> 3) & 1);
    uint32_t* p = buf + (r >> 4) * ABLK + slot;
    p[lane0 * 4]       = h0;
    p[(lane0 + 1) * 4] = h1;
}
// scatter fp32 float4 (n-row r, k-cols c4..c4+3) into fp16 B-frag layout
__device__ __forceinline__ void stBh(uint32_t* buf, int r, int c4, float4 v) {
    const uint32_t h0 = h2(v.x, v.y);
    const uint32_t h1 = h2(v.z, v.w);
    const int lane0 = (r & 7) * 4 + ((c4 & 7) >> 1);
    const int slot  = (c4 >> 3) & 1;
    uint32_t* p = buf + (r >> 3) * BBLK + slot;
    p[lane0 * 2]       = h0;
    p[(lane0 + 1) * 2] = h1;
}

// ---------------------------------------------------------------------------
// fp16 GEMM mainloop: C[M,N] = A[M,K] @ B[N,K]^T. CTA tile 128x128, BK=16,
// double-buffered frag-layout smem, 8 warps (2x4), warp tile 64x32.
// ---------------------------------------------------------------------------
#define GBK 16

struct GemmCtx {
    const float* Ap;
    const float* Bp;
    int K;
};

__device__ __forceinline__ void gemm_mainloop(const GemmCtx& g, float acc[16][4],
                                              uint32_t Af[2][8 * ABLK],
                                              uint32_t Bf[2][16 * BBLK]) {
    const int tid  = threadIdx.x;
    const int lane = tid & 31;
    const int wid  = tid >> 5;
    const int wmb  = (wid & 1) * 4;     // mblk base
    const int wnb  = (wid >> 1) * 4;    // nblk base
    const int K = g.K;

    const int prow = tid >> 2;          // 0..63 (+64)
    const int pc4  = (tid & 3) * 4;     // 0/4/8/12

#pragma unroll
    for (int i = 0; i < 16; i++)
#pragma unroll
        for (int j = 0; j < 4; j++) acc[i][j] = 0.0f;

    const int kiters = K / GBK;
    float4 ra0, ra1, rb0, rb1;

    ra0 = *(const float4*)(g.Ap + (size_t)prow * K + pc4);
    ra1 = *(const float4*)(g.Ap + (size_t)(prow + 64) * K + pc4);
    rb0 = *(const float4*)(g.Bp + (size_t)prow * K + pc4);
    rb1 = *(const float4*)(g.Bp + (size_t)(prow + 64) * K + pc4);
    stAh(Af[0], prow, pc4, ra0);
    stAh(Af[0], prow + 64, pc4, ra1);
    stBh(Bf[0], prow, pc4, rb0);
    stBh(Bf[0], prow + 64, pc4, rb1);
    __syncthreads();

    for (int it = 0; it < kiters; ++it) {
        if (it + 1 < kiters) {
            const float* Apn = g.Ap + (it + 1) * GBK;
            const float* Bpn = g.Bp + (it + 1) * GBK;
            ra0 = *(const float4*)(Apn + (size_t)prow * K + pc4);
            ra1 = *(const float4*)(Apn + (size_t)(prow + 64) * K + pc4);
            rb0 = *(const float4*)(Bpn + (size_t)prow * K + pc4);
            rb1 = *(const float4*)(Bpn + (size_t)(prow + 64) * K + pc4);
        }

        const uint32_t* af = Af[it & 1];
        const uint32_t* bf = Bf[it & 1];
        uint32_t afr[4][4], bfr[4][2];
#pragma unroll
        for (int mt = 0; mt < 4; mt++) {
            const uint4 av = *(const uint4*)&af[(wmb + mt) * ABLK + lane * 4];
            afr[mt][0] = av.x; afr[mt][1] = av.y;
            afr[mt][2] = av.z; afr[mt][3] = av.w;
        }
#pragma unroll
        for (int nt = 0; nt < 4; nt++) {
            const uint2 bv = *(const uint2*)&bf[(wnb + nt) * BBLK + lane * 2];
            bfr[nt][0] = bv.x; bfr[nt][1] = bv.y;
        }
#pragma unroll
        for (int mt = 0; mt < 4; mt++)
#pragma unroll
            for (int nt = 0; nt < 4; nt++)
                mma_f16(acc[mt * 4 + nt], afr[mt], bfr[nt]);

        if (it + 1 < kiters) {
            const int nb = (it + 1) & 1;
            stAh(Af[nb], prow, pc4, ra0);
            stAh(Af[nb], prow + 64, pc4, ra1);
            stBh(Bf[nb], prow, pc4, rb0);
            stBh(Bf[nb], prow + 64, pc4, rb1);
        }
        __syncthreads();
    }
}

// Fused QKV projection: grid.x 0..7 -> Wq/g_q, 8..11 -> Wk/g_k, 12..15 -> Wv/g_v
__global__ __launch_bounds__(256, 2)
void gemm_qkv(const float* __restrict__ x,
              const float* __restrict__ Wq, const float* __restrict__ Wk,
              const float* __restrict__ Wv,
              float* __restrict__ q, float* __restrict__ k,
              float* __restrict__ v) {
    __shared__ alignas(16) uint32_t Af[2][8 * ABLK];
    __shared__ alignas(16) uint32_t Bf[2][16 * BBLK];

    const int nb = blockIdx.x;
    const int m0 = blockIdx.y * 128;

    const float* W; float* C; int ldc, n0;
    if (nb < 8)       { W = Wq; C = q; ldc = DMODEL;  n0 = nb * 128; }
    else if (nb < 12) { W = Wk; C = k; ldc = NKV_DIM; n0 = (nb - 8) * 128; }
    else              { W = Wv; C = v; ldc = NKV_DIM; n0 = (nb - 12) * 128; }

    GemmCtx g;
    g.Ap = x + (size_t)m0 * DMODEL;
    g.Bp = W + (size_t)n0 * DMODEL;
    g.K  = DMODEL;

    float acc[16][4];
    gemm_mainloop(g, acc, Af, Bf);

    const int tid  = threadIdx.x;
    const int lane = tid & 31;
    const int wid  = tid >> 5;
    const int wmb  = (wid & 1) * 4;
    const int wnb  = (wid >> 1) * 4;
    const int lq   = lane >> 2;
    const int lr   = lane & 3;

#pragma unroll
    for (int mt = 0; mt < 4; mt++) {
        const int row = m0 + (wmb + mt) * 16 + lq;
#pragma unroll
        for (int nt = 0; nt < 4; nt++) {
            const int col = n0 + (wnb + nt) * 8 + 2 * lr;
            float* d = acc[mt * 4 + nt];
            *(float2*)(C + (size_t)row * ldc + col)       = make_float2(d[0], d[1]);
            *(float2*)(C + (size_t)(row + 8) * ldc + col) = make_float2(d[2], d[3]);
        }
    }
}

// Output projection (generic)
__global__ __launch_bounds__(256, 2)
void gemm_mma(const float* __restrict__ A, const float* __restrict__ B,
              float* __restrict__ C, int M, int N, int K) {
    __shared__ alignas(16) uint32_t Af[2][8 * ABLK];
    __shared__ alignas(16) uint32_t Bf[2][16 * BBLK];

    const int m0 = blockIdx.y * 128;
    const int n0 = blockIdx.x * 128;

    GemmCtx g;
    g.Ap = A + (size_t)m0 * K;
    g.Bp = B + (size_t)n0 * K;
    g.K  = K;

    float acc[16][4];
    gemm_mainloop(g, acc, Af, Bf);

    const int tid  = threadIdx.x;
    const int lane = tid & 31;
    const int wid  = tid >> 5;
    const int wmb  = (wid & 1) * 4;
    const int wnb  = (wid >> 1) * 4;
    const int lq   = lane >> 2;
    const int lr   = lane & 3;

#pragma unroll
    for (int mt = 0; mt < 4; mt++) {
        const int row = m0 + (wmb + mt) * 16 + lq;
#pragma unroll
        for (int nt = 0; nt < 4; nt++) {
            const int col = n0 + (wnb + nt) * 8 + 2 * lr;
            float* d = acc[mt * 4 + nt];
            *(float2*)(C + (size_t)row * N + col)       = make_float2(d[0], d[1]);
            *(float2*)(C + (size_t)(row + 8) * N + col) = make_float2(d[2], d[3]);
        }
    }
}

// ---------------------------------------------------------------------------
// fp16 tensor-core flash attention. 128 threads / 4 warps; each warp owns
// 32 q rows (2 m-tiles). 64-key sub-tiles, frag-layout smem, exp2 softmax.
//   Qf: 8 mblk x 4 kb A-frag blocks = 32 x 132 = 4224 u32 (persistent)
//   Kf: 8 nt  x 4 kb B-frag blocks = 32 x 66  = 2112 u32
//   Vf: 4 kt  x 8 nb B-frag blocks = 32 x 66  = 2112 u32
// ---------------------------------------------------------------------------
#define ATTN_SMEM ((4224 + 2112 + 2112) * 4)

__global__ __launch_bounds__(128, 2)
void attn_mma(const float* __restrict__ Q, const float* __restrict__ Kg,
              const float* __restrict__ Vg, float* __restrict__ Y) {
    extern __shared__ uint32_t smu[];
    uint32_t* Qf = smu;              // persistent
    uint32_t* Kf = smu + 4224;
    uint32_t* Vf = Kf + 2112;

    const int qt = blockIdx.x;
    const int h  = blockIdx.y;
    const int b  = blockIdx.z;
    const int kv = h >> 1;

    const int tid  = threadIdx.x;
    const int lane = tid & 31;
    const int wid  = tid >> 5;       // 0..3; owns m-tiles 2*wid, 2*wid+1
    const int lq   = lane >> 2;
    const int lr   = lane & 3;

    const float* qp = Q + ((size_t)(b * T_SEQ + qt * 128)) * DMODEL + h * DHEAD;
    const float* kbase = Kg + ((size_t)(b * T_SEQ)) * NKV_DIM + kv * DHEAD;
    const float* vbase = Vg + ((size_t)(b * T_SEQ)) * NKV_DIM + kv * DHEAD;

    // ---- stage Q (scaled, fp16) into A-frag layout ----
#pragma unroll
    for (int i = 0; i < 16; i++) {
        int ff = i * 128 + tid;          // 2048 float4
        int r  = ff >> 4;                // q row 0..127
        int c4 = (ff & 15) * 4;          // d col
        float4 v = *(const float4*)(qp + (size_t)r * DMODEL + c4);
        v.x *= QSCALE; v.y *= QSCALE; v.z *= QSCALE; v.w *= QSCALE;
        const uint32_t h0 = h2(v.x, v.y);
        const uint32_t h1 = h2(v.z, v.w);
        const int blk   = (r >> 4) * 4 + (c4 >> 4);
        const int lane0 = (r & 7) * 4 + ((c4 & 7) >> 1);
        const int slot  = ((c4 >> 3) & 1) * 2 + ((r >> 3) & 1);
        uint32_t* p = Qf + blk * ABLK + slot;
        p[lane0 * 4]       = h0;
        p[(lane0 + 1) * 4] = h1;
    }

    float oA[8][4], oB[8][4];
#pragma unroll
    for (int i = 0; i < 8; i++)
#pragma unroll
        for (int j = 0; j < 4; j++) { oA[i][j] = 0.0f; oB[i][j] = 0.0f; }
    float mA0 = -1e30f, mA1 = -1e30f, lA0 = 0.0f, lA1 = 0.0f;
    float mB0 = -1e30f, mB1 = -1e30f, lB0 = 0.0f, lB1 = 0.0f;

    const int mtA = wid * 2;
    const int mtB = wid * 2 + 1;

    for (int st = 0; st < T_SEQ / 64; st++) {
        __syncthreads();
        const float* kp = kbase + (size_t)st * 64 * NKV_DIM;
        const float* vp = vbase + (size_t)st * 64 * NKV_DIM;
#pragma unroll
        for (int i = 0; i < 8; i++) {
            int ff = i * 128 + tid;      // 1024 float4: 64 rows x 16 f4
            int r  = ff >> 4;            // key row 0..63
            int c4 = (ff & 15) * 4;      // d col
            float4 kvv = *(const float4*)(kp + (size_t)r * NKV_DIM + c4);
            {   // K -> B-frag (n = key, k = d)
                const uint32_t h0 = h2(kvv.x, kvv.y);
                const uint32_t h1 = h2(kvv.z, kvv.w);
                const int blk   = (r >> 3) * 4 + (c4 >> 4);
                const int lane0 = (r & 7) * 4 + ((c4 & 7) >> 1);
                const int slot  = (c4 >> 3) & 1;
                uint32_t* p = Kf + blk * BBLK + slot;
                p[lane0 * 2]       = h0;
                p[(lane0 + 1) * 2] = h1;
            }
            float4 vv = *(const float4*)(vp + (size_t)r * NKV_DIM + c4);
            {   // V -> B-frag (n = d, k = key): scalar half stores
                const int blk  = (r >> 4) * 8 + (c4 >> 3);
                const int slot = (r >> 3) & 1;
                const int lrp  = (r & 7) >> 1;
                __half* base = (__half*)Vf;
                const int u0 = blk * BBLK + ((c4 & 7) + 0) * 8 + lrp * 2 + slot;
                const int u1 = u0 + 8;
                const int u2 = u0 + 16;
                const int u3 = u0 + 24;
                const int hsel = r & 1;
                base[u0 * 2 + hsel] = __float2half_rn(vv.x);
                base[u1 * 2 + hsel] = __float2half_rn(vv.y);
                base[u2 * 2 + hsel] = __float2half_rn(vv.z);
                base[u3 * 2 + hsel] = __float2half_rn(vv.w);
            }
        }
        __syncthreads();

        // ---- S = Q @ K^T for both m-tiles; K frag shared ----
        float sfA[8][4], sfB[8][4];
#pragma unroll
        for (int nt = 0; nt < 8; nt++) {
            sfA[nt][0] = sfA[nt][1] = sfA[nt][2] = sfA[nt][3] = 0.0f;
            sfB[nt][0] = sfB[nt][1] = sfB[nt][2] = sfB[nt][3] = 0.0f;
        }

#pragma unroll
        for (int kb = 0; kb < 4; kb++) {
            uint32_t qa[4], qb[4];
            {
                const uint4 v = *(const uint4*)&Qf[(mtA * 4 + kb) * ABLK + lane * 4];
                qa[0] = v.x; qa[1] = v.y; qa[2] = v.z; qa[3] = v.w;
            }
            {
                const uint4 v = *(const uint4*)&Qf[(mtB * 4 + kb) * ABLK + lane * 4];
                qb[0] = v.x; qb[1] = v.y; qb[2] = v.z; qb[3] = v.w;
            }
#pragma unroll
            for (int nt = 0; nt < 8; nt++) {
                uint32_t bfr[2];
                const uint2 bv = *(const uint2*)&Kf[(nt * 4 + kb) * BBLK + lane * 2];
                bfr[0] = bv.x; bfr[1] = bv.y;
                mma_f16(sfA[nt], qa, bfr);
                mma_f16(sfB[nt], qb, bfr);
            }
        }

        // ---- online softmax (log2 domain) per m-tile ----
        {
            float mx0 = -1e30f, mx1 = -1e30f;
#pragma unroll
            for (int nt = 0; nt < 8; nt++) {
                mx0 = fmaxf(mx0, fmaxf(sfA[nt][0], sfA[nt][1]));
                mx1 = fmaxf(mx1, fmaxf(sfA[nt][2], sfA[nt][3]));
            }
            mx0 = fmaxf(mx0, __shfl_xor_sync(0xffffffffu, mx0, 1));
            mx0 = fmaxf(mx0, __shfl_xor_sync(0xffffffffu, mx0, 2));
            mx1 = fmaxf(mx1, __shfl_xor_sync(0xffffffffu, mx1, 1));
            mx1 = fmaxf(mx1, __shfl_xor_sync(0xffffffffu, mx1, 2));
            const float mn0 = fmaxf(mA0, mx0);
            const float mn1 = fmaxf(mA1, mx1);
            const float al0 = ex2f(mA0 - mn0);
            const float al1 = ex2f(mA1 - mn1);
            mA0 = mn0; mA1 = mn1;
            float s0 = 0.0f, s1 = 0.0f;
#pragma unroll
            for (int nt = 0; nt < 8; nt++) {
                sfA[nt][0] = ex2f(sfA[nt][0] - mn0); s0 += sfA[nt][0];
                sfA[nt][1] = ex2f(sfA[nt][1] - mn0); s0 += sfA[nt][1];
                sfA[nt][2] = ex2f(sfA[nt][2] - mn1); s1 += sfA[nt][2];
                sfA[nt][3] = ex2f(sfA[nt][3] - mn1); s1 += sfA[nt][3];
            }
            s0 += __shfl_xor_sync(0xffffffffu, s0, 1);
            s0 += __shfl_xor_sync(0xffffffffu, s0, 2);
            s1 += __shfl_xor_sync(0xffffffffu, s1, 1);
            s1 += __shfl_xor_sync(0xffffffffu, s1, 2);
            lA0 = lA0 * al0 + s0;
            lA1 = lA1 * al1 + s1;
#pragma unroll
            for (int nb = 0; nb < 8; nb++) {
                oA[nb][0] *= al0; oA[nb][1] *= al0;
                oA[nb][2] *= al1; oA[nb][3] *= al1;
            }
        }
        {
            float mx0 = -1e30f, mx1 = -1e30f;
#pragma unroll
            for (int nt = 0; nt < 8; nt++) {
                mx0 = fmaxf(mx0, fmaxf(sfB[nt][0], sfB[nt][1]));
                mx1 = fmaxf(mx1, fmaxf(sfB[nt][2], sfB[nt][3]));
            }
            mx0 = fmaxf(mx0, __shfl_xor_sync(0xffffffffu, mx0, 1));
            mx0 = fmaxf(mx0, __shfl_xor_sync(0xffffffffu, mx0, 2));
            mx1 = fmaxf(mx1, __shfl_xor_sync(0xffffffffu, mx1, 1));
            mx1 = fmaxf(mx1, __shfl_xor_sync(0xffffffffu, mx1, 2));
            const float mn0 = fmaxf(mB0, mx0);
            const float mn1 = fmaxf(mB1, mx1);
            const float al0 = ex2f(mB0 - mn0);
            const float al1 = ex2f(mB1 - mn1);
            mB0 = mn0; mB1 = mn1;
            float s0 = 0.0f, s1 = 0.0f;
#pragma unroll
            for (int nt = 0; nt < 8; nt++) {
                sfB[nt][0] = ex2f(sfB[nt][0] - mn0); s0 += sfB[nt][0];
                sfB[nt][1] = ex2f(sfB[nt][1] - mn0); s0 += sfB[nt][1];
                sfB[nt][2] = ex2f(sfB[nt][2] - mn1); s1 += sfB[nt][2];
                sfB[nt][3] = ex2f(sfB[nt][3] - mn1); s1 += sfB[nt][3];
            }
            s0 += __shfl_xor_sync(0xffffffffu, s0, 1);
            s0 += __shfl_xor_sync(0xffffffffu, s0, 2);
            s1 += __shfl_xor_sync(0xffffffffu, s1, 1);
            s1 += __shfl_xor_sync(0xffffffffu, s1, 2);
            lB0 = lB0 * al0 + s0;
            lB1 = lB1 * al1 + s1;
#pragma unroll
            for (int nb = 0; nb < 8; nb++) {
                oB[nb][0] *= al0; oB[nb][1] *= al0;
                oB[nb][2] *= al1; oB[nb][3] *= al1;
            }
        }

        // ---- PV: P C-frag -> A-frag is pure packing for m16n8k16 ----
#pragma unroll
        for (int kt = 0; kt < 4; kt++) {
            uint32_t paA[4], paB[4];
            paA[0] = h2(sfA[2 * kt][0],     sfA[2 * kt][1]);
            paA[1] = h2(sfA[2 * kt][2],     sfA[2 * kt][3]);
            paA[2] = h2(sfA[2 * kt + 1][0], sfA[2 * kt + 1][1]);
            paA[3] = h2(sfA[2 * kt + 1][2], sfA[2 * kt + 1][3]);
            paB[0] = h2(sfB[2 * kt][0],     sfB[2 * kt][1]);
            paB[1] = h2(sfB[2 * kt][2],     sfB[2 * kt][3]);
            paB[2] = h2(sfB[2 * kt + 1][0], sfB[2 * kt + 1][1]);
            paB[3] = h2(sfB[2 * kt + 1][2], sfB[2 * kt + 1][3]);

#pragma unroll
            for (int nb = 0; nb < 8; nb++) {
                uint32_t bfr[2];
                const uint2 bv = *(const uint2*)&Vf[(kt * 8 + nb) * BBLK + lane * 2];
                bfr[0] = bv.x; bfr[1] = bv.y;
                mma_f16(oA[nb], paA, bfr);
                mma_f16(oB[nb], paB, bfr);
            }
        }
    }

    // ---- epilogue ----
    {
        const float i0 = 1.0f / lA0, i1 = 1.0f / lA1;
        float* yp = Y + ((size_t)(b * T_SEQ + qt * 128 + mtA * 16)) * DMODEL + h * DHEAD;
#pragma unroll
        for (int nb = 0; nb < 8; nb++) {
            const int col = nb * 8 + 2 * lr;
            *(float2*)(yp + (size_t)lq * DMODEL + col) =
                make_float2(oA[nb][0] * i0, oA[nb][1] * i0);
            *(float2*)(yp + (size_t)(lq + 8) * DMODEL + col) =
                make_float2(oA[nb][2] * i1, oA[nb][3] * i1);
        }
    }
    {
        const float i0 = 1.0f / lB0, i1 = 1.0f / lB1;
        float* yp = Y + ((size_t)(b * T_SEQ + qt * 128 + mtB * 16)) * DMODEL + h * DHEAD;
#pragma unroll
        for (int nb = 0; nb < 8; nb++) {
            const int col = nb * 8 + 2 * lr;
            *(float2*)(yp + (size_t)lq * DMODEL + col) =
                make_float2(oB[nb][0] * i0, oB[nb][1] * i0);
            *(float2*)(yp + (size_t)(lq + 8) * DMODEL + col) =
                make_float2(oB[nb][2] * i1, oB[nb][3] * i1);
        }
    }
}

// ---------------------------------------------------------------------------
// Launch
// ---------------------------------------------------------------------------
extern "C" void kernel_launch(void* const* d_in, const int* in_sizes, int n_in,
                              void* d_out, int out_size) {
    const float* x     = (const float*)d_in[0];
    const float* Wq    = (const float*)d_in[1];
    const float* Wk    = (const float*)d_in[2];
    const float* Wv    = (const float*)d_in[3];
    const float* Wproj = (const float*)d_in[4];
    float* out = (float*)d_out;

    void *pq, *pk, *pv, *py;
    cudaGetSymbolAddress(&pq, g_q);
    cudaGetSymbolAddress(&pk, g_k);
    cudaGetSymbolAddress(&pv, g_v);
    cudaGetSymbolAddress(&py, g_y);

    cudaFuncSetAttribute(attn_mma, cudaFuncAttributeMaxDynamicSharedMemorySize,
                         ATTN_SMEM);

    // fused QKV projection (16 n-blocks: 8 Q + 4 K + 4 V)
    gemm_qkv<<<dim3(16, MTOT / 128), dim3(256)>>>(
        x, Wq, Wk, Wv, (float*)pq, (float*)pk, (float*)pv);
    // attention
    attn_mma<<<dim3(T_SEQ / 128, NHEADS, BATCH), dim3(128), ATTN_SMEM>>>(
        (const float*)pq, (const float*)pk, (const float*)pv, (float*)py);
    // output projection
    gemm_mma<<<dim3(DMODEL / 128, MTOT / 128), dim3(256)>>>(
        (const float*)py, Wproj, out, MTOT, DMODEL, DMODEL);
}

// round 13
// speedup vs baseline: 6.1494x; 1.0645x over previous
#include <cuda_runtime.h>
#include <cuda_fp16.h>
#include <cstdint>
#include <math.h>

// ---------------------------------------------------------------------------
// GQA block: y = proj( attn( x@Wq^T, x@Wk^T, x@Wv^T ) )
// B=2, T=2048, D_MODEL=1024, N_HEADS=16, N_KV=8, GROUP=2, D_HEAD=64
// R11: fp16 end-to-end datapath (inputs pre-converted once; all
//      intermediates fp16 in gmem) + 64x64 warp tiles in the GEMMs.
// ---------------------------------------------------------------------------

#define BATCH   2
#define T_SEQ   2048
#define DMODEL  1024
#define NKV_DIM 512
#define NHEADS  16
#define DHEAD   64
#define QSCALE  0.18033688f   // 64^-0.5 * log2(e)

#define MTOT (BATCH * T_SEQ)   // 4096 rows

// fp16 scratch (static device globals)
__device__ __align__(16) __half g_xh[(size_t)MTOT * DMODEL];
__device__ __align__(16) __half g_wqh[(size_t)DMODEL * DMODEL];
__device__ __align__(16) __half g_wkh[(size_t)NKV_DIM * DMODEL];
__device__ __align__(16) __half g_wvh[(size_t)NKV_DIM * DMODEL];
__device__ __align__(16) __half g_wph[(size_t)DMODEL * DMODEL];
__device__ __align__(16) __half g_q[(size_t)MTOT * DMODEL];
__device__ __align__(16) __half g_k[(size_t)MTOT * NKV_DIM];
__device__ __align__(16) __half g_v[(size_t)MTOT * NKV_DIM];
__device__ __align__(16) __half g_y[(size_t)MTOT * DMODEL];

// ---------------------------------------------------------------------------
// helpers
// ---------------------------------------------------------------------------
__device__ __forceinline__ float ex2f(float x) {
    float y;
    asm("ex2.approx.f32 %0, %1;" : "=f"(y) : "f"(x));
    return y;
}
__device__ __forceinline__ uint32_t scaleh2(uint32_t h, float s) {
    __half2 hh = *(__half2*)&h;
    float2 f = __half22float2(hh);
    __half2 r = __floats2half2_rn(f.x * s, f.y * s);
    return *(uint32_t*)&r;
}

__device__ __forceinline__ void mma_f16(float* d, const uint32_t* a,
                                        const uint32_t* b) {
    asm volatile(
        "mma.sync.aligned.m16n8k16.row.col.f32.f16.f16.f32 "
        "{%0,%1,%2,%3}, {%4,%5,%6,%7}, {%8,%9}, {%0,%1,%2,%3};"
        : "+f"(d[0]), "+f"(d[1]), "+f"(d[2]), "+f"(d[3])
        : "r"(a[0]), "r"(a[1]), "r"(a[2]), "r"(a[3]), "r"(b[0]), "r"(b[1]));
}

// Fragment-layout smem blocks (uint32 = half2 units), proven in R10:
//  A-frag block (16m x 16k): 128 u32 + 4 pad = 132; lane owns u32[lane*4..+3].
//  B-frag block (8n x 16k):   64 u32 + 2 pad = 66; lane owns u32[lane*2..+1].
#define ABLK 132
#define BBLK 66

// stage 8 halves (row r, k cols hg..hg+7, hg in {0,8}) into A-frag layout
__device__ __forceinline__ void stA8(uint32_t* buf, int r, int hg, uint4 v) {
    const int j = ((hg >> 3) & 1) * 2 + ((r >> 3) & 1);
    uint32_t* p = buf + (r >> 4) * ABLK + (r & 7) * 16 + j;
    p[0] = v.x; p[4] = v.y; p[8] = v.z; p[12] = v.w;
}
// stage 8 halves (n-row r, k cols hg..hg+7, hg in {0,8}) into B-frag layout
__device__ __forceinline__ void stB8(uint32_t* buf, int r, int hg, uint4 v) {
    const int j = (hg >> 3) & 1;
    uint32_t* p = buf + (r >> 3) * BBLK + (r & 7) * 8 + j;
    p[0] = v.x; p[2] = v.y; p[4] = v.z; p[6] = v.w;
}

// ---------------------------------------------------------------------------
// fp32 -> fp16 conversion kernel
// ---------------------------------------------------------------------------
__global__ __launch_bounds__(256)
void cvt_f2h(const float* __restrict__ src, __half* __restrict__ dst, int n4) {
    int i = blockIdx.x * blockDim.x + threadIdx.x;
    if (i < n4) {
        float4 v = ((const float4*)src)[i];
        __half2* d = (__half2*)dst + (size_t)i * 2;
        d[0] = __floats2half2_rn(v.x, v.y);
        d[1] = __floats2half2_rn(v.z, v.w);
    }
}

// ---------------------------------------------------------------------------
// fp16 GEMM mainloop: C[M,N] = A[M,K] @ B[N,K]^T (both fp16 K-major).
// CTA tile 128x128, BK=16, double-buffered frag smem.
// 128 threads / 4 warps; warp tile 64x64 (4 mblk x 8 nblk = 32 MMAs).
// ---------------------------------------------------------------------------
__device__ __forceinline__ void hgemm_mainloop(
    const __half* Ap, const __half* Bp, int K, float acc[32][4],
    uint32_t Af[2][8 * ABLK], uint32_t Bf[2][16 * BBLK]) {
    const int tid  = threadIdx.x;
    const int lane = tid & 31;
    const int wid  = tid >> 5;          // 0..3
    const int mb0  = (wid & 1) * 4;     // mblk base
    const int nb0  = (wid >> 1) * 8;    // nblk base

    const int sr  = tid >> 1;           // staging row 0..63 (+64)
    const int shg = (tid & 1) * 8;      // k-half-group 0/8

#pragma unroll
    for (int i = 0; i < 32; i++)
#pragma unroll
        for (int j = 0; j < 4; j++) acc[i][j] = 0.0f;

    const int kiters = K / 16;
    uint4 a0, a1, b0, b1;

    a0 = *(const uint4*)(Ap + (size_t)sr * K + shg);
    a1 = *(const uint4*)(Ap + (size_t)(sr + 64) * K + shg);
    b0 = *(const uint4*)(Bp + (size_t)sr * K + shg);
    b1 = *(const uint4*)(Bp + (size_t)(sr + 64) * K + shg);
    stA8(Af[0], sr, shg, a0);
    stA8(Af[0], sr + 64, shg, a1);
    stB8(Bf[0], sr, shg, b0);
    stB8(Bf[0], sr + 64, shg, b1);
    __syncthreads();

    for (int it = 0; it < kiters; ++it) {
        if (it + 1 < kiters) {
            const __half* An = Ap + (it + 1) * 16;
            const __half* Bn = Bp + (it + 1) * 16;
            a0 = *(const uint4*)(An + (size_t)sr * K + shg);
            a1 = *(const uint4*)(An + (size_t)(sr + 64) * K + shg);
            b0 = *(const uint4*)(Bn + (size_t)sr * K + shg);
            b1 = *(const uint4*)(Bn + (size_t)(sr + 64) * K + shg);
        }

        const uint32_t* af = Af[it & 1];
        const uint32_t* bf = Bf[it & 1];
        uint32_t afr[4][4], bfr[8][2];
#pragma unroll
        for (int mt = 0; mt < 4; mt++) {
            const uint4 v = *(const uint4*)&af[(mb0 + mt) * ABLK + lane * 4];
            afr[mt][0] = v.x; afr[mt][1] = v.y;
            afr[mt][2] = v.z; afr[mt][3] = v.w;
        }
#pragma unroll
        for (int nt = 0; nt < 8; nt++) {
            const uint2 v = *(const uint2*)&bf[(nb0 + nt) * BBLK + lane * 2];
            bfr[nt][0] = v.x; bfr[nt][1] = v.y;
        }
#pragma unroll
        for (int mt = 0; mt < 4; mt++)
#pragma unroll
            for (int nt = 0; nt < 8; nt++)
                mma_f16(acc[mt * 8 + nt], afr[mt], bfr[nt]);

        if (it + 1 < kiters) {
            const int nb = (it + 1) & 1;
            stA8(Af[nb], sr, shg, a0);
            stA8(Af[nb], sr + 64, shg, a1);
            stB8(Bf[nb], sr, shg, b0);
            stB8(Bf[nb], sr + 64, shg, b1);
        }
        __syncthreads();
    }
}

// Fused QKV projection (fp16 in, fp16 out).
// grid.x 0..7 -> Wq/g_q, 8..11 -> Wk/g_k, 12..15 -> Wv/g_v
__global__ __launch_bounds__(128, 2)
void gemm_qkv_h(const __half* __restrict__ x,
                const __half* __restrict__ Wq, const __half* __restrict__ Wk,
                const __half* __restrict__ Wv,
                __half* __restrict__ q, __half* __restrict__ k,
                __half* __restrict__ v) {
    __shared__ alignas(16) uint32_t Af[2][8 * ABLK];
    __shared__ alignas(16) uint32_t Bf[2][16 * BBLK];

    const int nb = blockIdx.x;
    const int m0 = blockIdx.y * 128;

    const __half* W; __half* C; int ldc, n0;
    if (nb < 8)       { W = Wq; C = q; ldc = DMODEL;  n0 = nb * 128; }
    else if (nb < 12) { W = Wk; C = k; ldc = NKV_DIM; n0 = (nb - 8) * 128; }
    else              { W = Wv; C = v; ldc = NKV_DIM; n0 = (nb - 12) * 128; }

    float acc[32][4];
    hgemm_mainloop(x + (size_t)m0 * DMODEL, W + (size_t)n0 * DMODEL, DMODEL,
                   acc, Af, Bf);

    const int tid  = threadIdx.x;
    const int lane = tid & 31;
    const int wid  = tid >> 5;
    const int mb0  = (wid & 1) * 4;
    const int nb0  = (wid >> 1) * 8;
    const int lq   = lane >> 2;
    const int lr   = lane & 3;

#pragma unroll
    for (int mt = 0; mt < 4; mt++) {
        const int row = m0 + (mb0 + mt) * 16 + lq;
#pragma unroll
        for (int nt = 0; nt < 8; nt++) {
            const int col = n0 + (nb0 + nt) * 8 + 2 * lr;
            float* d = acc[mt * 8 + nt];
            *(__half2*)(C + (size_t)row * ldc + col) =
                __floats2half2_rn(d[0], d[1]);
            *(__half2*)(C + (size_t)(row + 8) * ldc + col) =
                __floats2half2_rn(d[2], d[3]);
        }
    }
}

// Output projection (fp16 in, fp32 out).
__global__ __launch_bounds__(128, 2)
void gemm_proj_h(const __half* __restrict__ A, const __half* __restrict__ B,
                 float* __restrict__ C, int N, int K) {
    __shared__ alignas(16) uint32_t Af[2][8 * ABLK];
    __shared__ alignas(16) uint32_t Bf[2][16 * BBLK];

    const int m0 = blockIdx.y * 128;
    const int n0 = blockIdx.x * 128;

    float acc[32][4];
    hgemm_mainloop(A + (size_t)m0 * K, B + (size_t)n0 * K, K, acc, Af, Bf);

    const int tid  = threadIdx.x;
    const int lane = tid & 31;
    const int wid  = tid >> 5;
    const int mb0  = (wid & 1) * 4;
    const int nb0  = (wid >> 1) * 8;
    const int lq   = lane >> 2;
    const int lr   = lane & 3;

#pragma unroll
    for (int mt = 0; mt < 4; mt++) {
        const int row = m0 + (mb0 + mt) * 16 + lq;
#pragma unroll
        for (int nt = 0; nt < 8; nt++) {
            const int col = n0 + (nb0 + nt) * 8 + 2 * lr;
            float* d = acc[mt * 8 + nt];
            *(float2*)(C + (size_t)row * N + col)       = make_float2(d[0], d[1]);
            *(float2*)(C + (size_t)(row + 8) * N + col) = make_float2(d[2], d[3]);
        }
    }
}

// ---------------------------------------------------------------------------
// fp16 tensor-core flash attention (fp16 gmem in/out). 128 threads / 4 warps;
// each warp owns 32 q rows (2 m-tiles). 64-key sub-tiles, frag smem, exp2.
//   Qf: 8 mblk x 4 kb A-frag blocks = 4224 u32 (persistent)
//   Kf: 8 nt  x 4 kb B-frag blocks = 2112 u32
//   Vf: 4 kt  x 8 nb B-frag blocks = 2112 u32
// ---------------------------------------------------------------------------
#define ATTN_SMEM ((4224 + 2112 + 2112) * 4)

__global__ __launch_bounds__(128, 2)
void attn_mma(const __half* __restrict__ Q, const __half* __restrict__ Kg,
              const __half* __restrict__ Vg, __half* __restrict__ Y) {
    extern __shared__ uint32_t smu[];
    uint32_t* Qf = smu;              // persistent
    uint32_t* Kf = smu + 4224;
    uint32_t* Vf = Kf + 2112;

    const int qt = blockIdx.x;
    const int h  = blockIdx.y;
    const int b  = blockIdx.z;
    const int kv = h >> 1;

    const int tid  = threadIdx.x;
    const int lane = tid & 31;
    const int wid  = tid >> 5;       // 0..3; owns m-tiles 2*wid, 2*wid+1
    const int lq   = lane >> 2;
    const int lr   = lane & 3;

    const __half* qp = Q + ((size_t)(b * T_SEQ + qt * 128)) * DMODEL + h * DHEAD;
    const __half* kbase = Kg + ((size_t)(b * T_SEQ)) * NKV_DIM + kv * DHEAD;
    const __half* vbase = Vg + ((size_t)(b * T_SEQ)) * NKV_DIM + kv * DHEAD;

    // ---- stage Q (scaled in fp32, repacked fp16) into A-frag layout ----
#pragma unroll
    for (int i = 0; i < 8; i++) {
        int ff = i * 128 + tid;          // 1024 uint4
        int r  = ff >> 3;                // q row 0..127
        int hg = (ff & 7) * 8;           // d col 0..56
        uint4 v = *(const uint4*)(qp + (size_t)r * DMODEL + hg);
        const int blk = (r >> 4) * 4 + (hg >> 4);
        const int j   = ((hg >> 3) & 1) * 2 + ((r >> 3) & 1);
        uint32_t* p = Qf + blk * ABLK + (r & 7) * 16 + j;
        p[0]  = scaleh2(v.x, QSCALE);
        p[4]  = scaleh2(v.y, QSCALE);
        p[8]  = scaleh2(v.z, QSCALE);
        p[12] = scaleh2(v.w, QSCALE);
    }

    float oA[8][4], oB[8][4];
#pragma unroll
    for (int i = 0; i < 8; i++)
#pragma unroll
        for (int j = 0; j < 4; j++) { oA[i][j] = 0.0f; oB[i][j] = 0.0f; }
    float mA0 = -1e30f, mA1 = -1e30f, lA0 = 0.0f, lA1 = 0.0f;
    float mB0 = -1e30f, mB1 = -1e30f, lB0 = 0.0f, lB1 = 0.0f;

    const int mtA = wid * 2;
    const int mtB = wid * 2 + 1;

    for (int st = 0; st < T_SEQ / 64; st++) {
        __syncthreads();
        const __half* kp = kbase + (size_t)st * 64 * NKV_DIM;
        const __half* vp = vbase + (size_t)st * 64 * NKV_DIM;
#pragma unroll
        for (int i = 0; i < 4; i++) {
            int ff = i * 128 + tid;      // 512 uint4: 64 rows x 8
            int r  = ff >> 3;            // key row 0..63
            int hg = (ff & 7) * 8;       // d col
            uint4 kvv = *(const uint4*)(kp + (size_t)r * NKV_DIM + hg);
            {   // K -> B-frag (n = key, k = d)
                const int blk = (r >> 3) * 4 + (hg >> 4);
                const int j   = (hg >> 3) & 1;
                uint32_t* p = Kf + blk * BBLK + (r & 7) * 8 + j;
                p[0] = kvv.x; p[2] = kvv.y; p[4] = kvv.z; p[6] = kvv.w;
            }
            uint4 vv = *(const uint4*)(vp + (size_t)r * NKV_DIM + hg);
            {   // V -> B-frag (n = d, k = key): scalar half scatter
                const int blk = (r >> 4) * 8 + (hg >> 3);
                __half* base = (__half*)(Vf + blk * BBLK +
                                         ((r & 7) >> 1) * 2 + ((r >> 3) & 1)) +
                               (r & 1);
                const __half* hv = (const __half*)&vv;
#pragma unroll
                for (int jj = 0; jj < 8; jj++) base[jj * 16] = hv[jj];
            }
        }
        __syncthreads();

        // ---- S = Q @ K^T for both m-tiles; K frag shared ----
        float sfA[8][4], sfB[8][4];
#pragma unroll
        for (int nt = 0; nt < 8; nt++) {
            sfA[nt][0] = sfA[nt][1] = sfA[nt][2] = sfA[nt][3] = 0.0f;
            sfB[nt][0] = sfB[nt][1] = sfB[nt][2] = sfB[nt][3] = 0.0f;
        }

#pragma unroll
        for (int kb = 0; kb < 4; kb++) {
            uint32_t qa[4], qb[4];
            {
                const uint4 v = *(const uint4*)&Qf[(mtA * 4 + kb) * ABLK + lane * 4];
                qa[0] = v.x; qa[1] = v.y; qa[2] = v.z; qa[3] = v.w;
            }
            {
                const uint4 v = *(const uint4*)&Qf[(mtB * 4 + kb) * ABLK + lane * 4];
                qb[0] = v.x; qb[1] = v.y; qb[2] = v.z; qb[3] = v.w;
            }
#pragma unroll
            for (int nt = 0; nt < 8; nt++) {
                uint32_t bfr[2];
                const uint2 bv = *(const uint2*)&Kf[(nt * 4 + kb) * BBLK + lane * 2];
                bfr[0] = bv.x; bfr[1] = bv.y;
                mma_f16(sfA[nt], qa, bfr);
                mma_f16(sfB[nt], qb, bfr);
            }
        }

        // ---- online softmax (log2 domain) per m-tile ----
        {
            float mx0 = -1e30f, mx1 = -1e30f;
#pragma unroll
            for (int nt = 0; nt < 8; nt++) {
                mx0 = fmaxf(mx0, fmaxf(sfA[nt][0], sfA[nt][1]));
                mx1 = fmaxf(mx1, fmaxf(sfA[nt][2], sfA[nt][3]));
            }
            mx0 = fmaxf(mx0, __shfl_xor_sync(0xffffffffu, mx0, 1));
            mx0 = fmaxf(mx0, __shfl_xor_sync(0xffffffffu, mx0, 2));
            mx1 = fmaxf(mx1, __shfl_xor_sync(0xffffffffu, mx1, 1));
            mx1 = fmaxf(mx1, __shfl_xor_sync(0xffffffffu, mx1, 2));
            const float mn0 = fmaxf(mA0, mx0);
            const float mn1 = fmaxf(mA1, mx1);
            const float al0 = ex2f(mA0 - mn0);
            const float al1 = ex2f(mA1 - mn1);
            mA0 = mn0; mA1 = mn1;
            float s0 = 0.0f, s1 = 0.0f;
#pragma unroll
            for (int nt = 0; nt < 8; nt++) {
                sfA[nt][0] = ex2f(sfA[nt][0] - mn0); s0 += sfA[nt][0];
                sfA[nt][1] = ex2f(sfA[nt][1] - mn0); s0 += sfA[nt][1];
                sfA[nt][2] = ex2f(sfA[nt][2] - mn1); s1 += sfA[nt][2];
                sfA[nt][3] = ex2f(sfA[nt][3] - mn1); s1 += sfA[nt][3];
            }
            s0 += __shfl_xor_sync(0xffffffffu, s0, 1);
            s0 += __shfl_xor_sync(0xffffffffu, s0, 2);
            s1 += __shfl_xor_sync(0xffffffffu, s1, 1);
            s1 += __shfl_xor_sync(0xffffffffu, s1, 2);
            lA0 = lA0 * al0 + s0;
            lA1 = lA1 * al1 + s1;
#pragma unroll
            for (int nb = 0; nb < 8; nb++) {
                oA[nb][0] *= al0; oA[nb][1] *= al0;
                oA[nb][2] *= al1; oA[nb][3] *= al1;
            }
        }
        {
            float mx0 = -1e30f, mx1 = -1e30f;
#pragma unroll
            for (int nt = 0; nt < 8; nt++) {
                mx0 = fmaxf(mx0, fmaxf(sfB[nt][0], sfB[nt][1]));
                mx1 = fmaxf(mx1, fmaxf(sfB[nt][2], sfB[nt][3]));
            }
            mx0 = fmaxf(mx0, __shfl_xor_sync(0xffffffffu, mx0, 1));
            mx0 = fmaxf(mx0, __shfl_xor_sync(0xffffffffu, mx0, 2));
            mx1 = fmaxf(mx1, __shfl_xor_sync(0xffffffffu, mx1, 1));
            mx1 = fmaxf(mx1, __shfl_xor_sync(0xffffffffu, mx1, 2));
            const float mn0 = fmaxf(mB0, mx0);
            const float mn1 = fmaxf(mB1, mx1);
            const float al0 = ex2f(mB0 - mn0);
            const float al1 = ex2f(mB1 - mn1);
            mB0 = mn0; mB1 = mn1;
            float s0 = 0.0f, s1 = 0.0f;
#pragma unroll
            for (int nt = 0; nt < 8; nt++) {
                sfB[nt][0] = ex2f(sfB[nt][0] - mn0); s0 += sfB[nt][0];
                sfB[nt][1] = ex2f(sfB[nt][1] - mn0); s0 += sfB[nt][1];
                sfB[nt][2] = ex2f(sfB[nt][2] - mn1); s1 += sfB[nt][2];
                sfB[nt][3] = ex2f(sfB[nt][3] - mn1); s1 += sfB[nt][3];
            }
            s0 += __shfl_xor_sync(0xffffffffu, s0, 1);
            s0 += __shfl_xor_sync(0xffffffffu, s0, 2);
            s1 += __shfl_xor_sync(0xffffffffu, s1, 1);
            s1 += __shfl_xor_sync(0xffffffffu, s1, 2);
            lB0 = lB0 * al0 + s0;
            lB1 = lB1 * al1 + s1;
#pragma unroll
            for (int nb = 0; nb < 8; nb++) {
                oB[nb][0] *= al0; oB[nb][1] *= al0;
                oB[nb][2] *= al1; oB[nb][3] *= al1;
            }
        }

        // ---- PV: P C-frag -> A-frag is pure register packing ----
#pragma unroll
        for (int kt = 0; kt < 4; kt++) {
            uint32_t paA[4], paB[4];
            {
                __half2 t0 = __floats2half2_rn(sfA[2 * kt][0],     sfA[2 * kt][1]);
                __half2 t1 = __floats2half2_rn(sfA[2 * kt][2],     sfA[2 * kt][3]);
                __half2 t2 = __floats2half2_rn(sfA[2 * kt + 1][0], sfA[2 * kt + 1][1]);
                __half2 t3 = __floats2half2_rn(sfA[2 * kt + 1][2], sfA[2 * kt + 1][3]);
                paA[0] = *(uint32_t*)&t0; paA[1] = *(uint32_t*)&t1;
                paA[2] = *(uint32_t*)&t2; paA[3] = *(uint32_t*)&t3;
            }
            {
                __half2 t0 = __floats2half2_rn(sfB[2 * kt][0],     sfB[2 * kt][1]);
                __half2 t1 = __floats2half2_rn(sfB[2 * kt][2],     sfB[2 * kt][3]);
                __half2 t2 = __floats2half2_rn(sfB[2 * kt + 1][0], sfB[2 * kt + 1][1]);
                __half2 t3 = __floats2half2_rn(sfB[2 * kt + 1][2], sfB[2 * kt + 1][3]);
                paB[0] = *(uint32_t*)&t0; paB[1] = *(uint32_t*)&t1;
                paB[2] = *(uint32_t*)&t2; paB[3] = *(uint32_t*)&t3;
            }

#pragma unroll
            for (int nb = 0; nb < 8; nb++) {
                uint32_t bfr[2];
                const uint2 bv = *(const uint2*)&Vf[(kt * 8 + nb) * BBLK + lane * 2];
                bfr[0] = bv.x; bfr[1] = bv.y;
                mma_f16(oA[nb], paA, bfr);
                mma_f16(oB[nb], paB, bfr);
            }
        }
    }

    // ---- epilogue: fp16 Y ----
    {
        const float i0 = 1.0f / lA0, i1 = 1.0f / lA1;
        __half* yp = Y + ((size_t)(b * T_SEQ + qt * 128 + mtA * 16)) * DMODEL + h * DHEAD;
#pragma unroll
        for (int nb = 0; nb < 8; nb++) {
            const int col = nb * 8 + 2 * lr;
            *(__half2*)(yp + (size_t)lq * DMODEL + col) =
                __floats2half2_rn(oA[nb][0] * i0, oA[nb][1] * i0);
            *(__half2*)(yp + (size_t)(lq + 8) * DMODEL + col) =
                __floats2half2_rn(oA[nb][2] * i1, oA[nb][3] * i1);
        }
    }
    {
        const float i0 = 1.0f / lB0, i1 = 1.0f / lB1;
        __half* yp = Y + ((size_t)(b * T_SEQ + qt * 128 + mtB * 16)) * DMODEL + h * DHEAD;
#pragma unroll
        for (int nb = 0; nb < 8; nb++) {
            const int col = nb * 8 + 2 * lr;
            *(__half2*)(yp + (size_t)lq * DMODEL + col) =
                __floats2half2_rn(oB[nb][0] * i0, oB[nb][1] * i0);
            *(__half2*)(yp + (size_t)(lq + 8) * DMODEL + col) =
                __floats2half2_rn(oB[nb][2] * i1, oB[nb][3] * i1);
        }
    }
}

// ---------------------------------------------------------------------------
// Launch
// ---------------------------------------------------------------------------
extern "C" void kernel_launch(void* const* d_in, const int* in_sizes, int n_in,
                              void* d_out, int out_size) {
    const float* x     = (const float*)d_in[0];
    const float* Wq    = (const float*)d_in[1];
    const float* Wk    = (const float*)d_in[2];
    const float* Wv    = (const float*)d_in[3];
    const float* Wproj = (const float*)d_in[4];
    float* out = (float*)d_out;

    void *pxh, *pwq, *pwk, *pwv, *pwp, *pq, *pk, *pv, *py;
    cudaGetSymbolAddress(&pxh, g_xh);
    cudaGetSymbolAddress(&pwq, g_wqh);
    cudaGetSymbolAddress(&pwk, g_wkh);
    cudaGetSymbolAddress(&pwv, g_wvh);
    cudaGetSymbolAddress(&pwp, g_wph);
    cudaGetSymbolAddress(&pq, g_q);
    cudaGetSymbolAddress(&pk, g_k);
    cudaGetSymbolAddress(&pv, g_v);
    cudaGetSymbolAddress(&py, g_y);

    cudaFuncSetAttribute(attn_mma, cudaFuncAttributeMaxDynamicSharedMemorySize,
                         ATTN_SMEM);

    // fp32 -> fp16 input conversion
    cvt_f2h<<<4096, 256>>>(x, (__half*)pxh, MTOT * DMODEL / 4);
    cvt_f2h<<<1024, 256>>>(Wq, (__half*)pwq, DMODEL * DMODEL / 4);
    cvt_f2h<<<512, 256>>>(Wk, (__half*)pwk, NKV_DIM * DMODEL / 4);
    cvt_f2h<<<512, 256>>>(Wv, (__half*)pwv, NKV_DIM * DMODEL / 4);
    cvt_f2h<<<1024, 256>>>(Wproj, (__half*)pwp, DMODEL * DMODEL / 4);

    // fused QKV projection (16 n-blocks: 8 Q + 4 K + 4 V)
    gemm_qkv_h<<<dim3(16, MTOT / 128), dim3(128)>>>(
        (const __half*)pxh, (const __half*)pwq, (const __half*)pwk,
        (const __half*)pwv, (__half*)pq, (__half*)pk, (__half*)pv);
    // attention
    attn_mma<<<dim3(T_SEQ / 128, NHEADS, BATCH), dim3(128), ATTN_SMEM>>>(
        (const __half*)pq, (const __half*)pk, (const __half*)pv, (__half*)py);
    // output projection
    gemm_proj_h<<<dim3(DMODEL / 128, MTOT / 128), dim3(128)>>>(
        (const __half*)py, (const __half*)pwp, out, DMODEL, DMODEL);
}

// round 14
// speedup vs baseline: 6.6160x; 1.0759x over previous
#include <cuda_runtime.h>
#include <cuda_fp16.h>
#include <cstdint>
#include <math.h>

// ---------------------------------------------------------------------------
// GQA block: y = proj( attn( x@Wq^T, x@Wk^T, x@Wv^T ) )
// B=2, T=2048, D_MODEL=1024, N_HEADS=16, N_KV=8, GROUP=2, D_HEAD=64
// R14: attention K/V gmem loads software-pipelined (prefetch regs during
//      compute, latency hidden); 5 cvt launches fused into 1.
// ---------------------------------------------------------------------------

#define BATCH   2
#define T_SEQ   2048
#define DMODEL  1024
#define NKV_DIM 512
#define NHEADS  16
#define DHEAD   64
#define QSCALE  0.18033688f   // 64^-0.5 * log2(e)

#define MTOT (BATCH * T_SEQ)   // 4096 rows

// fp16 scratch (static device globals)
__device__ __align__(16) __half g_xh[(size_t)MTOT * DMODEL];
__device__ __align__(16) __half g_wqh[(size_t)DMODEL * DMODEL];
__device__ __align__(16) __half g_wkh[(size_t)NKV_DIM * DMODEL];
__device__ __align__(16) __half g_wvh[(size_t)NKV_DIM * DMODEL];
__device__ __align__(16) __half g_wph[(size_t)DMODEL * DMODEL];
__device__ __align__(16) __half g_q[(size_t)MTOT * DMODEL];
__device__ __align__(16) __half g_k[(size_t)MTOT * NKV_DIM];
__device__ __align__(16) __half g_v[(size_t)MTOT * NKV_DIM];
__device__ __align__(16) __half g_y[(size_t)MTOT * DMODEL];

// ---------------------------------------------------------------------------
// helpers
// ---------------------------------------------------------------------------
__device__ __forceinline__ float ex2f(float x) {
    float y;
    asm("ex2.approx.f32 %0, %1;" : "=f"(y) : "f"(x));
    return y;
}
__device__ __forceinline__ uint32_t scaleh2(uint32_t h, float s) {
    __half2 hh = *(__half2*)&h;
    float2 f = __half22float2(hh);
    __half2 r = __floats2half2_rn(f.x * s, f.y * s);
    return *(uint32_t*)&r;
}

__device__ __forceinline__ void mma_f16(float* d, const uint32_t* a,
                                        const uint32_t* b) {
    asm volatile(
        "mma.sync.aligned.m16n8k16.row.col.f32.f16.f16.f32 "
        "{%0,%1,%2,%3}, {%4,%5,%6,%7}, {%8,%9}, {%0,%1,%2,%3};"
        : "+f"(d[0]), "+f"(d[1]), "+f"(d[2]), "+f"(d[3])
        : "r"(a[0]), "r"(a[1]), "r"(a[2]), "r"(a[3]), "r"(b[0]), "r"(b[1]));
}

// Fragment-layout smem blocks (uint32 = half2 units), proven:
#define ABLK 132
#define BBLK 66

__device__ __forceinline__ void stA8(uint32_t* buf, int r, int hg, uint4 v) {
    const int j = ((hg >> 3) & 1) * 2 + ((r >> 3) & 1);
    uint32_t* p = buf + (r >> 4) * ABLK + (r & 7) * 16 + j;
    p[0] = v.x; p[4] = v.y; p[8] = v.z; p[12] = v.w;
}
__device__ __forceinline__ void stB8(uint32_t* buf, int r, int hg, uint4 v) {
    const int j = (hg >> 3) & 1;
    uint32_t* p = buf + (r >> 3) * BBLK + (r & 7) * 8 + j;
    p[0] = v.x; p[2] = v.y; p[4] = v.z; p[6] = v.w;
}

// ---------------------------------------------------------------------------
// fused fp32 -> fp16 conversion (all 5 tensors, one launch)
// ---------------------------------------------------------------------------
#define CVT_N0 1048576   // x      (4096*1024/4)
#define CVT_N1 1310720   // + Wq   (1024*1024/4)
#define CVT_N2 1441792   // + Wk   (512*1024/4)
#define CVT_N3 1572864   // + Wv
#define CVT_N4 1835008   // + Wproj

__global__ __launch_bounds__(256)
void cvt_all(const float* __restrict__ x, const float* __restrict__ wq,
             const float* __restrict__ wk, const float* __restrict__ wv,
             const float* __restrict__ wp) {
    int i = blockIdx.x * blockDim.x + threadIdx.x;
    const float* src; __half* dst; int base;
    if (i < CVT_N0)      { src = x;  dst = g_xh;  base = 0; }
    else if (i < CVT_N1) { src = wq; dst = g_wqh; base = CVT_N0; }
    else if (i < CVT_N2) { src = wk; dst = g_wkh; base = CVT_N1; }
    else if (i < CVT_N3) { src = wv; dst = g_wvh; base = CVT_N2; }
    else if (i < CVT_N4) { src = wp; dst = g_wph; base = CVT_N3; }
    else return;
    int j = i - base;
    float4 v = ((const float4*)src)[j];
    __half2* d = (__half2*)dst + (size_t)j * 2;
    d[0] = __floats2half2_rn(v.x, v.y);
    d[1] = __floats2half2_rn(v.z, v.w);
}

// ---------------------------------------------------------------------------
// fp16 GEMM mainloop (unchanged from R11, proven): CTA 128x128, BK=16,
// double-buffered frag smem, 4 warps, warp tile 64x64.
// ---------------------------------------------------------------------------
__device__ __forceinline__ void hgemm_mainloop(
    const __half* Ap, const __half* Bp, int K, float acc[32][4],
    uint32_t Af[2][8 * ABLK], uint32_t Bf[2][16 * BBLK]) {
    const int tid  = threadIdx.x;
    const int lane = tid & 31;
    const int wid  = tid >> 5;
    const int mb0  = (wid & 1) * 4;
    const int nb0  = (wid >> 1) * 8;

    const int sr  = tid >> 1;
    const int shg = (tid & 1) * 8;

#pragma unroll
    for (int i = 0; i < 32; i++)
#pragma unroll
        for (int j = 0; j < 4; j++) acc[i][j] = 0.0f;

    const int kiters = K / 16;
    uint4 a0, a1, b0, b1;

    a0 = *(const uint4*)(Ap + (size_t)sr * K + shg);
    a1 = *(const uint4*)(Ap + (size_t)(sr + 64) * K + shg);
    b0 = *(const uint4*)(Bp + (size_t)sr * K + shg);
    b1 = *(const uint4*)(Bp + (size_t)(sr + 64) * K + shg);
    stA8(Af[0], sr, shg, a0);
    stA8(Af[0], sr + 64, shg, a1);
    stB8(Bf[0], sr, shg, b0);
    stB8(Bf[0], sr + 64, shg, b1);
    __syncthreads();

    for (int it = 0; it < kiters; ++it) {
        if (it + 1 < kiters) {
            const __half* An = Ap + (it + 1) * 16;
            const __half* Bn = Bp + (it + 1) * 16;
            a0 = *(const uint4*)(An + (size_t)sr * K + shg);
            a1 = *(const uint4*)(An + (size_t)(sr + 64) * K + shg);
            b0 = *(const uint4*)(Bn + (size_t)sr * K + shg);
            b1 = *(const uint4*)(Bn + (size_t)(sr + 64) * K + shg);
        }

        const uint32_t* af = Af[it & 1];
        const uint32_t* bf = Bf[it & 1];
        uint32_t afr[4][4], bfr[8][2];
#pragma unroll
        for (int mt = 0; mt < 4; mt++) {
            const uint4 v = *(const uint4*)&af[(mb0 + mt) * ABLK + lane * 4];
            afr[mt][0] = v.x; afr[mt][1] = v.y;
            afr[mt][2] = v.z; afr[mt][3] = v.w;
        }
#pragma unroll
        for (int nt = 0; nt < 8; nt++) {
            const uint2 v = *(const uint2*)&bf[(nb0 + nt) * BBLK + lane * 2];
            bfr[nt][0] = v.x; bfr[nt][1] = v.y;
        }
#pragma unroll
        for (int mt = 0; mt < 4; mt++)
#pragma unroll
            for (int nt = 0; nt < 8; nt++)
                mma_f16(acc[mt * 8 + nt], afr[mt], bfr[nt]);

        if (it + 1 < kiters) {
            const int nb = (it + 1) & 1;
            stA8(Af[nb], sr, shg, a0);
            stA8(Af[nb], sr + 64, shg, a1);
            stB8(Bf[nb], sr, shg, b0);
            stB8(Bf[nb], sr + 64, shg, b1);
        }
        __syncthreads();
    }
}

// Fused QKV projection (fp16 in, fp16 out).
__global__ __launch_bounds__(128, 2)
void gemm_qkv_h(const __half* __restrict__ x,
                const __half* __restrict__ Wq, const __half* __restrict__ Wk,
                const __half* __restrict__ Wv,
                __half* __restrict__ q, __half* __restrict__ k,
                __half* __restrict__ v) {
    __shared__ alignas(16) uint32_t Af[2][8 * ABLK];
    __shared__ alignas(16) uint32_t Bf[2][16 * BBLK];

    const int nb = blockIdx.x;
    const int m0 = blockIdx.y * 128;

    const __half* W; __half* C; int ldc, n0;
    if (nb < 8)       { W = Wq; C = q; ldc = DMODEL;  n0 = nb * 128; }
    else if (nb < 12) { W = Wk; C = k; ldc = NKV_DIM; n0 = (nb - 8) * 128; }
    else              { W = Wv; C = v; ldc = NKV_DIM; n0 = (nb - 12) * 128; }

    float acc[32][4];
    hgemm_mainloop(x + (size_t)m0 * DMODEL, W + (size_t)n0 * DMODEL, DMODEL,
                   acc, Af, Bf);

    const int tid  = threadIdx.x;
    const int lane = tid & 31;
    const int wid  = tid >> 5;
    const int mb0  = (wid & 1) * 4;
    const int nb0  = (wid >> 1) * 8;
    const int lq   = lane >> 2;
    const int lr   = lane & 3;

#pragma unroll
    for (int mt = 0; mt < 4; mt++) {
        const int row = m0 + (mb0 + mt) * 16 + lq;
#pragma unroll
        for (int nt = 0; nt < 8; nt++) {
            const int col = n0 + (nb0 + nt) * 8 + 2 * lr;
            float* d = acc[mt * 8 + nt];
            *(__half2*)(C + (size_t)row * ldc + col) =
                __floats2half2_rn(d[0], d[1]);
            *(__half2*)(C + (size_t)(row + 8) * ldc + col) =
                __floats2half2_rn(d[2], d[3]);
        }
    }
}

// Output projection (fp16 in, fp32 out).
__global__ __launch_bounds__(128, 2)
void gemm_proj_h(const __half* __restrict__ A, const __half* __restrict__ B,
                 float* __restrict__ C, int N, int K) {
    __shared__ alignas(16) uint32_t Af[2][8 * ABLK];
    __shared__ alignas(16) uint32_t Bf[2][16 * BBLK];

    const int m0 = blockIdx.y * 128;
    const int n0 = blockIdx.x * 128;

    float acc[32][4];
    hgemm_mainloop(A + (size_t)m0 * K, B + (size_t)n0 * K, K, acc, Af, Bf);

    const int tid  = threadIdx.x;
    const int lane = tid & 31;
    const int wid  = tid >> 5;
    const int mb0  = (wid & 1) * 4;
    const int nb0  = (wid >> 1) * 8;
    const int lq   = lane >> 2;
    const int lr   = lane & 3;

#pragma unroll
    for (int mt = 0; mt < 4; mt++) {
        const int row = m0 + (mb0 + mt) * 16 + lq;
#pragma unroll
        for (int nt = 0; nt < 8; nt++) {
            const int col = n0 + (nb0 + nt) * 8 + 2 * lr;
            float* d = acc[mt * 8 + nt];
            *(float2*)(C + (size_t)row * N + col)       = make_float2(d[0], d[1]);
            *(float2*)(C + (size_t)(row + 8) * N + col) = make_float2(d[2], d[3]);
        }
    }
}

// ---------------------------------------------------------------------------
// fp16 flash attention with software-pipelined K/V gmem loads.
// 128 threads / 4 warps; warp owns 32 q rows (2 m-tiles); 64-key sub-tiles.
// ---------------------------------------------------------------------------
#define ATTN_SMEM ((4224 + 2112 + 2112) * 4)
#define NST (T_SEQ / 64)

__global__ __launch_bounds__(128, 2)
void attn_mma(const __half* __restrict__ Q, const __half* __restrict__ Kg,
              const __half* __restrict__ Vg, __half* __restrict__ Y) {
    extern __shared__ uint32_t smu[];
    uint32_t* Qf = smu;              // persistent
    uint32_t* Kf = smu + 4224;
    uint32_t* Vf = Kf + 2112;

    const int qt = blockIdx.x;
    const int h  = blockIdx.y;
    const int b  = blockIdx.z;
    const int kv = h >> 1;

    const int tid  = threadIdx.x;
    const int lane = tid & 31;
    const int wid  = tid >> 5;
    const int lq   = lane >> 2;
    const int lr   = lane & 3;

    const __half* qp = Q + ((size_t)(b * T_SEQ + qt * 128)) * DMODEL + h * DHEAD;
    const __half* kbase = Kg + ((size_t)(b * T_SEQ)) * NKV_DIM + kv * DHEAD;
    const __half* vbase = Vg + ((size_t)(b * T_SEQ)) * NKV_DIM + kv * DHEAD;

    // per-thread staging coordinates (4 uint4 each for K and V)
    const int srow = tid >> 3 ? 0 : 0; (void)srow;
    int srK[4], shK[4];
#pragma unroll
    for (int i = 0; i < 4; i++) {
        int ff = i * 128 + tid;
        srK[i] = ff >> 3;            // key row 0..63
        shK[i] = (ff & 7) * 8;       // d col
    }

    // ---- stage Q (scaled) into A-frag layout ----
#pragma unroll
    for (int i = 0; i < 8; i++) {
        int ff = i * 128 + tid;
        int r  = ff >> 3;
        int hg = (ff & 7) * 8;
        uint4 v = *(const uint4*)(qp + (size_t)r * DMODEL + hg);
        const int blk = (r >> 4) * 4 + (hg >> 4);
        const int j   = ((hg >> 3) & 1) * 2 + ((r >> 3) & 1);
        uint32_t* p = Qf + blk * ABLK + (r & 7) * 16 + j;
        p[0]  = scaleh2(v.x, QSCALE);
        p[4]  = scaleh2(v.y, QSCALE);
        p[8]  = scaleh2(v.z, QSCALE);
        p[12] = scaleh2(v.w, QSCALE);
    }

    float oA[8][4], oB[8][4];
#pragma unroll
    for (int i = 0; i < 8; i++)
#pragma unroll
        for (int j = 0; j < 4; j++) { oA[i][j] = 0.0f; oB[i][j] = 0.0f; }
    float mA0 = -1e30f, mA1 = -1e30f, lA0 = 0.0f, lA1 = 0.0f;
    float mB0 = -1e30f, mB1 = -1e30f, lB0 = 0.0f, lB1 = 0.0f;

    const int mtA = wid * 2;
    const int mtB = wid * 2 + 1;

    // ---- prologue: prefetch K/V tile 0 into registers ----
    uint4 kreg[4], vreg[4];
#pragma unroll
    for (int i = 0; i < 4; i++) {
        kreg[i] = *(const uint4*)(kbase + (size_t)srK[i] * NKV_DIM + shK[i]);
        vreg[i] = *(const uint4*)(vbase + (size_t)srK[i] * NKV_DIM + shK[i]);
    }

    for (int st = 0; st < NST; st++) {
        // ---- store staged K/V registers into frag smem ----
#pragma unroll
        for (int i = 0; i < 4; i++) {
            const int r  = srK[i];
            const int hg = shK[i];
            {   // K -> B-frag (n = key, k = d)
                const int blk = (r >> 3) * 4 + (hg >> 4);
                const int j   = (hg >> 3) & 1;
                uint32_t* p = Kf + blk * BBLK + (r & 7) * 8 + j;
                p[0] = kreg[i].x; p[2] = kreg[i].y;
                p[4] = kreg[i].z; p[6] = kreg[i].w;
            }
            {   // V -> B-frag (n = d, k = key): scalar half scatter
                const int blk = (r >> 4) * 8 + (hg >> 3);
                __half* base = (__half*)(Vf + blk * BBLK +
                                         ((r & 7) >> 1) * 2 + ((r >> 3) & 1)) +
                               (r & 1);
                const __half* hv = (const __half*)&vreg[i];
#pragma unroll
                for (int jj = 0; jj < 8; jj++) base[jj * 16] = hv[jj];
            }
        }
        __syncthreads();

        // ---- prefetch next tile (latency hidden behind compute) ----
        if (st + 1 < NST) {
            const __half* kp = kbase + (size_t)(st + 1) * 64 * NKV_DIM;
            const __half* vp = vbase + (size_t)(st + 1) * 64 * NKV_DIM;
#pragma unroll
            for (int i = 0; i < 4; i++) {
                kreg[i] = *(const uint4*)(kp + (size_t)srK[i] * NKV_DIM + shK[i]);
                vreg[i] = *(const uint4*)(vp + (size_t)srK[i] * NKV_DIM + shK[i]);
            }
        }

        // ---- S = Q @ K^T for both m-tiles; K frag shared ----
        float sfA[8][4], sfB[8][4];
#pragma unroll
        for (int nt = 0; nt < 8; nt++) {
            sfA[nt][0] = sfA[nt][1] = sfA[nt][2] = sfA[nt][3] = 0.0f;
            sfB[nt][0] = sfB[nt][1] = sfB[nt][2] = sfB[nt][3] = 0.0f;
        }

#pragma unroll
        for (int kb = 0; kb < 4; kb++) {
            uint32_t qa[4], qb[4];
            {
                const uint4 v = *(const uint4*)&Qf[(mtA * 4 + kb) * ABLK + lane * 4];
                qa[0] = v.x; qa[1] = v.y; qa[2] = v.z; qa[3] = v.w;
            }
            {
                const uint4 v = *(const uint4*)&Qf[(mtB * 4 + kb) * ABLK + lane * 4];
                qb[0] = v.x; qb[1] = v.y; qb[2] = v.z; qb[3] = v.w;
            }
#pragma unroll
            for (int nt = 0; nt < 8; nt++) {
                uint32_t bfr[2];
                const uint2 bv = *(const uint2*)&Kf[(nt * 4 + kb) * BBLK + lane * 2];
                bfr[0] = bv.x; bfr[1] = bv.y;
                mma_f16(sfA[nt], qa, bfr);
                mma_f16(sfB[nt], qb, bfr);
            }
        }

        // ---- online softmax (log2 domain) per m-tile ----
        {
            float mx0 = -1e30f, mx1 = -1e30f;
#pragma unroll
            for (int nt = 0; nt < 8; nt++) {
                mx0 = fmaxf(mx0, fmaxf(sfA[nt][0], sfA[nt][1]));
                mx1 = fmaxf(mx1, fmaxf(sfA[nt][2], sfA[nt][3]));
            }
            mx0 = fmaxf(mx0, __shfl_xor_sync(0xffffffffu, mx0, 1));
            mx0 = fmaxf(mx0, __shfl_xor_sync(0xffffffffu, mx0, 2));
            mx1 = fmaxf(mx1, __shfl_xor_sync(0xffffffffu, mx1, 1));
            mx1 = fmaxf(mx1, __shfl_xor_sync(0xffffffffu, mx1, 2));
            const float mn0 = fmaxf(mA0, mx0);
            const float mn1 = fmaxf(mA1, mx1);
            const float al0 = ex2f(mA0 - mn0);
            const float al1 = ex2f(mA1 - mn1);
            mA0 = mn0; mA1 = mn1;
            float s0 = 0.0f, s1 = 0.0f;
#pragma unroll
            for (int nt = 0; nt < 8; nt++) {
                sfA[nt][0] = ex2f(sfA[nt][0] - mn0); s0 += sfA[nt][0];
                sfA[nt][1] = ex2f(sfA[nt][1] - mn0); s0 += sfA[nt][1];
                sfA[nt][2] = ex2f(sfA[nt][2] - mn1); s1 += sfA[nt][2];
                sfA[nt][3] = ex2f(sfA[nt][3] - mn1); s1 += sfA[nt][3];
            }
            s0 += __shfl_xor_sync(0xffffffffu, s0, 1);
            s0 += __shfl_xor_sync(0xffffffffu, s0, 2);
            s1 += __shfl_xor_sync(0xffffffffu, s1, 1);
            s1 += __shfl_xor_sync(0xffffffffu, s1, 2);
            lA0 = lA0 * al0 + s0;
            lA1 = lA1 * al1 + s1;
#pragma unroll
            for (int nb = 0; nb < 8; nb++) {
                oA[nb][0] *= al0; oA[nb][1] *= al0;
                oA[nb][2] *= al1; oA[nb][3] *= al1;
            }
        }
        {
            float mx0 = -1e30f, mx1 = -1e30f;
#pragma unroll
            for (int nt = 0; nt < 8; nt++) {
                mx0 = fmaxf(mx0, fmaxf(sfB[nt][0], sfB[nt][1]));
                mx1 = fmaxf(mx1, fmaxf(sfB[nt][2], sfB[nt][3]));
            }
            mx0 = fmaxf(mx0, __shfl_xor_sync(0xffffffffu, mx0, 1));
            mx0 = fmaxf(mx0, __shfl_xor_sync(0xffffffffu, mx0, 2));
            mx1 = fmaxf(mx1, __shfl_xor_sync(0xffffffffu, mx1, 1));
            mx1 = fmaxf(mx1, __shfl_xor_sync(0xffffffffu, mx1, 2));
            const float mn0 = fmaxf(mB0, mx0);
            const float mn1 = fmaxf(mB1, mx1);
            const float al0 = ex2f(mB0 - mn0);
            const float al1 = ex2f(mB1 - mn1);
            mB0 = mn0; mB1 = mn1;
            float s0 = 0.0f, s1 = 0.0f;
#pragma unroll
            for (int nt = 0; nt < 8; nt++) {
                sfB[nt][0] = ex2f(sfB[nt][0] - mn0); s0 += sfB[nt][0];
                sfB[nt][1] = ex2f(sfB[nt][1] - mn0); s0 += sfB[nt][1];
                sfB[nt][2] = ex2f(sfB[nt][2] - mn1); s1 += sfB[nt][2];
                sfB[nt][3] = ex2f(sfB[nt][3] - mn1); s1 += sfB[nt][3];
            }
            s0 += __shfl_xor_sync(0xffffffffu, s0, 1);
            s0 += __shfl_xor_sync(0xffffffffu, s0, 2);
            s1 += __shfl_xor_sync(0xffffffffu, s1, 1);
            s1 += __shfl_xor_sync(0xffffffffu, s1, 2);
            lB0 = lB0 * al0 + s0;
            lB1 = lB1 * al1 + s1;
#pragma unroll
            for (int nb = 0; nb < 8; nb++) {
                oB[nb][0] *= al0; oB[nb][1] *= al0;
                oB[nb][2] *= al1; oB[nb][3] *= al1;
            }
        }

        // ---- PV: P C-frag -> A-frag is pure register packing ----
#pragma unroll
        for (int kt = 0; kt < 4; kt++) {
            uint32_t paA[4], paB[4];
            {
                __half2 t0 = __floats2half2_rn(sfA[2 * kt][0],     sfA[2 * kt][1]);
                __half2 t1 = __floats2half2_rn(sfA[2 * kt][2],     sfA[2 * kt][3]);
                __half2 t2 = __floats2half2_rn(sfA[2 * kt + 1][0], sfA[2 * kt + 1][1]);
                __half2 t3 = __floats2half2_rn(sfA[2 * kt + 1][2], sfA[2 * kt + 1][3]);
                paA[0] = *(uint32_t*)&t0; paA[1] = *(uint32_t*)&t1;
                paA[2] = *(uint32_t*)&t2; paA[3] = *(uint32_t*)&t3;
            }
            {
                __half2 t0 = __floats2half2_rn(sfB[2 * kt][0],     sfB[2 * kt][1]);
                __half2 t1 = __floats2half2_rn(sfB[2 * kt][2],     sfB[2 * kt][3]);
                __half2 t2 = __floats2half2_rn(sfB[2 * kt + 1][0], sfB[2 * kt + 1][1]);
                __half2 t3 = __floats2half2_rn(sfB[2 * kt + 1][2], sfB[2 * kt + 1][3]);
                paB[0] = *(uint32_t*)&t0; paB[1] = *(uint32_t*)&t1;
                paB[2] = *(uint32_t*)&t2; paB[3] = *(uint32_t*)&t3;
            }

#pragma unroll
            for (int nb = 0; nb < 8; nb++) {
                uint32_t bfr[2];
                const uint2 bv = *(const uint2*)&Vf[(kt * 8 + nb) * BBLK + lane * 2];
                bfr[0] = bv.x; bfr[1] = bv.y;
                mma_f16(oA[nb], paA, bfr);
                mma_f16(oB[nb], paB, bfr);
            }
        }
        __syncthreads();   // smem consumed; safe to overwrite next iteration
    }

    // ---- epilogue: fp16 Y ----
    {
        const float i0 = 1.0f / lA0, i1 = 1.0f / lA1;
        __half* yp = Y + ((size_t)(b * T_SEQ + qt * 128 + mtA * 16)) * DMODEL + h * DHEAD;
#pragma unroll
        for (int nb = 0; nb < 8; nb++) {
            const int col = nb * 8 + 2 * lr;
            *(__half2*)(yp + (size_t)lq * DMODEL + col) =
                __floats2half2_rn(oA[nb][0] * i0, oA[nb][1] * i0);
            *(__half2*)(yp + (size_t)(lq + 8) * DMODEL + col) =
                __floats2half2_rn(oA[nb][2] * i1, oA[nb][3] * i1);
        }
    }
    {
        const float i0 = 1.0f / lB0, i1 = 1.0f / lB1;
        __half* yp = Y + ((size_t)(b * T_SEQ + qt * 128 + mtB * 16)) * DMODEL + h * DHEAD;
#pragma unroll
        for (int nb = 0; nb < 8; nb++) {
            const int col = nb * 8 + 2 * lr;
            *(__half2*)(yp + (size_t)lq * DMODEL + col) =
                __floats2half2_rn(oB[nb][0] * i0, oB[nb][1] * i0);
            *(__half2*)(yp + (size_t)(lq + 8) * DMODEL + col) =
                __floats2half2_rn(oB[nb][2] * i1, oB[nb][3] * i1);
        }
    }
}

// ---------------------------------------------------------------------------
// Launch
// ---------------------------------------------------------------------------
extern "C" void kernel_launch(void* const* d_in, const int* in_sizes, int n_in,
                              void* d_out, int out_size) {
    const float* x     = (const float*)d_in[0];
    const float* Wq    = (const float*)d_in[1];
    const float* Wk    = (const float*)d_in[2];
    const float* Wv    = (const float*)d_in[3];
    const float* Wproj = (const float*)d_in[4];
    float* out = (float*)d_out;

    void *pxh, *pwq, *pwk, *pwv, *pwp, *pq, *pk, *pv, *py;
    cudaGetSymbolAddress(&pxh, g_xh);
    cudaGetSymbolAddress(&pwq, g_wqh);
    cudaGetSymbolAddress(&pwk, g_wkh);
    cudaGetSymbolAddress(&pwv, g_wvh);
    cudaGetSymbolAddress(&pwp, g_wph);
    cudaGetSymbolAddress(&pq, g_q);
    cudaGetSymbolAddress(&pk, g_k);
    cudaGetSymbolAddress(&pv, g_v);
    cudaGetSymbolAddress(&py, g_y);

    cudaFuncSetAttribute(attn_mma, cudaFuncAttributeMaxDynamicSharedMemorySize,
                         ATTN_SMEM);

    // fused fp32 -> fp16 conversion (one launch for all 5 tensors)
    cvt_all<<<(CVT_N4 + 255) / 256, 256>>>(x, Wq, Wk, Wv, Wproj);

    // fused QKV projection (16 n-blocks: 8 Q + 4 K + 4 V)
    gemm_qkv_h<<<dim3(16, MTOT / 128), dim3(128)>>>(
        (const __half*)pxh, (const __half*)pwq, (const __half*)pwk,
        (const __half*)pwv, (__half*)pq, (__half*)pk, (__half*)pv);
    // attention
    attn_mma<<<dim3(T_SEQ / 128, NHEADS, BATCH), dim3(128), ATTN_SMEM>>>(
        (const __half*)pq, (const __half*)pk, (const __half*)pv, (__half*)py);
    // output projection
    gemm_proj_h<<<dim3(DMODEL / 128, MTOT / 128), dim3(128)>>>(
        (const __half*)py, (const __half*)pwp, out, DMODEL, DMODEL);
}

// round 15
// speedup vs baseline: 8.0457x; 1.2161x over previous
#include <cuda_runtime.h>
#include <cuda_fp16.h>
#include <cstdint>
#include <math.h>

// ---------------------------------------------------------------------------
// GQA block: y = proj( attn( x@Wq^T, x@Wk^T, x@Wv^T ) )
// B=2, T=2048, D_MODEL=1024, N_HEADS=16, N_KV=8, GROUP=2, D_HEAD=64
// R15: GEMM mainloop rebuilt on cp.async (16B DMA staging) + ldmatrix
//      (HW fragment distribution) + 3-stage pipeline, BK=32.
//      Attention unchanged from R14 (proven).
// ---------------------------------------------------------------------------

#define BATCH   2
#define T_SEQ   2048
#define DMODEL  1024
#define NKV_DIM 512
#define NHEADS  16
#define DHEAD   64
#define QSCALE  0.18033688f   // 64^-0.5 * log2(e)

#define MTOT (BATCH * T_SEQ)   // 4096 rows

// fp16 scratch (static device globals)
__device__ __align__(16) __half g_xh[(size_t)MTOT * DMODEL];
__device__ __align__(16) __half g_wqh[(size_t)DMODEL * DMODEL];
__device__ __align__(16) __half g_wkh[(size_t)NKV_DIM * DMODEL];
__device__ __align__(16) __half g_wvh[(size_t)NKV_DIM * DMODEL];
__device__ __align__(16) __half g_wph[(size_t)DMODEL * DMODEL];
__device__ __align__(16) __half g_q[(size_t)MTOT * DMODEL];
__device__ __align__(16) __half g_k[(size_t)MTOT * NKV_DIM];
__device__ __align__(16) __half g_v[(size_t)MTOT * NKV_DIM];
__device__ __align__(16) __half g_y[(size_t)MTOT * DMODEL];

// ---------------------------------------------------------------------------
// helpers
// ---------------------------------------------------------------------------
__device__ __forceinline__ float ex2f(float x) {
    float y;
    asm("ex2.approx.f32 %0, %1;" : "=f"(y) : "f"(x));
    return y;
}
__device__ __forceinline__ uint32_t scaleh2(uint32_t h, float s) {
    __half2 hh = *(__half2*)&h;
    float2 f = __half22float2(hh);
    __half2 r = __floats2half2_rn(f.x * s, f.y * s);
    return *(uint32_t*)&r;
}

__device__ __forceinline__ void mma_f16(float* d, const uint32_t* a,
                                        const uint32_t* b) {
    asm volatile(
        "mma.sync.aligned.m16n8k16.row.col.f32.f16.f16.f32 "
        "{%0,%1,%2,%3}, {%4,%5,%6,%7}, {%8,%9}, {%0,%1,%2,%3};"
        : "+f"(d[0]), "+f"(d[1]), "+f"(d[2]), "+f"(d[3])
        : "r"(a[0]), "r"(a[1]), "r"(a[2]), "r"(a[3]), "r"(b[0]), "r"(b[1]));
}

__device__ __forceinline__ void cp16(uint32_t dst, const void* src) {
    asm volatile("cp.async.cg.shared.global [%0], [%1], 16;"
                 :: "r"(dst), "l"(src));
}
__device__ __forceinline__ void cp_commit() {
    asm volatile("cp.async.commit_group;" ::: "memory");
}
template <int N>
__device__ __forceinline__ void cp_wait() {
    asm volatile("cp.async.wait_group %0;" :: "n"(N) : "memory");
}
__device__ __forceinline__ void ldm_x4(uint32_t* r, uint32_t addr) {
    asm volatile("ldmatrix.sync.aligned.m8n8.x4.shared.b16 {%0,%1,%2,%3}, [%4];"
                 : "=r"(r[0]), "=r"(r[1]), "=r"(r[2]), "=r"(r[3]) : "r"(addr));
}

// ---------------------------------------------------------------------------
// cp.async + ldmatrix fp16 GEMM: C[M,N] = A[M,K] @ B[N,K]^T.
// CTA tile 128x128, BK=32, 3-stage pipeline, 128 threads / 4 warps,
// warp tile 64x64. Smem tiles row-major, row stride 80B (16-aligned;
// 5r+c mod 8 is a permutation -> ldmatrix phases conflict-free).
// ---------------------------------------------------------------------------
#define ROWB    80
#define STAGE_A 10240               // 128 rows * 80B
#define STAGE_SZ (2 * STAGE_A)      // A tile + B tile
#define NSTAGE  3
#define GEMM_SMEM (NSTAGE * STAGE_SZ)

__device__ __forceinline__ void hgemm_mainloop(
    const __half* Ap, const __half* Bp, int K, float acc[32][4], char* smem) {
    const int tid  = threadIdx.x;
    const int lane = tid & 31;
    const int wid  = tid >> 5;
    const int mb0  = (wid & 1) * 4;      // mblk base (x16 rows)
    const int nb0  = (wid >> 1) * 8;     // nblk base (x8 rows)

    const uint32_t sbase = (uint32_t)__cvta_generic_to_shared(smem);

    // staging: thread covers rows {srow, srow+32, +64, +96}, chunk sc (16B)
    const int srow = tid >> 2;           // 0..31
    const int sc   = tid & 3;            // 0..3

    // ldmatrix per-lane offsets (bytes)
    const uint32_t laneOffA =
        (uint32_t)((((lane >> 3) & 1) * 8 + (lane & 7)) * ROWB + (lane >> 4) * 16);
    const uint32_t laneOffB =
        (uint32_t)(((lane & 7) + (lane >> 4) * 8) * ROWB + ((lane >> 3) & 1) * 16);

#pragma unroll
    for (int i = 0; i < 32; i++)
#pragma unroll
        for (int j = 0; j < 4; j++) acc[i][j] = 0.0f;

    const int kiters = K / 32;

    // prologue: stages 0, 1
#pragma unroll
    for (int p = 0; p < 2; p++) {
        const __half* As = Ap + p * 32;
        const __half* Bs = Bp + p * 32;
        uint32_t ab = sbase + p * STAGE_SZ;
        uint32_t bb = ab + STAGE_A;
#pragma unroll
        for (int i = 0; i < 4; i++) {
            int r = i * 32 + srow;
            cp16(ab + r * ROWB + sc * 16, As + (size_t)r * K + sc * 8);
            cp16(bb + r * ROWB + sc * 16, Bs + (size_t)r * K + sc * 8);
        }
        cp_commit();
    }

    int buf = 0;
#pragma unroll 1
    for (int it = 0; it < kiters; ++it) {
        cp_wait<1>();
        __syncthreads();

        const uint32_t ab = sbase + buf * STAGE_SZ;
        const uint32_t bb = ab + STAGE_A;

#pragma unroll
        for (int ks = 0; ks < 2; ks++) {
            uint32_t afr[4][4], bfr[8][2];
#pragma unroll
            for (int mt = 0; mt < 4; mt++)
                ldm_x4(afr[mt],
                       ab + (mb0 + mt) * (16 * ROWB) + ks * 32 + laneOffA);
#pragma unroll
            for (int t = 0; t < 4; t++) {
                uint32_t r[4];
                ldm_x4(r, bb + (nb0 + 2 * t) * (8 * ROWB) + ks * 32 + laneOffB);
                bfr[2 * t][0]     = r[0]; bfr[2 * t][1]     = r[1];
                bfr[2 * t + 1][0] = r[2]; bfr[2 * t + 1][1] = r[3];
            }
#pragma unroll
            for (int mt = 0; mt < 4; mt++)
#pragma unroll
                for (int nt = 0; nt < 8; nt++)
                    mma_f16(acc[mt * 8 + nt], afr[mt], bfr[nt]);
        }

        // issue stage it+2 (or an empty group to keep wait arithmetic exact)
        if (it + 2 < kiters) {
            const int nbuf = (buf + 2 == 3) ? 2 : ((buf + 2) % 3);
            const __half* As = Ap + (it + 2) * 32;
            const __half* Bs = Bp + (it + 2) * 32;
            uint32_t ab2 = sbase + ((it + 2) % 3) * STAGE_SZ;
            uint32_t bb2 = ab2 + STAGE_A;
            (void)nbuf;
#pragma unroll
            for (int i = 0; i < 4; i++) {
                int r = i * 32 + srow;
                cp16(ab2 + r * ROWB + sc * 16, As + (size_t)r * K + sc * 8);
                cp16(bb2 + r * ROWB + sc * 16, Bs + (size_t)r * K + sc * 8);
            }
        }
        cp_commit();

        buf = (buf + 1 == 3) ? 0 : buf + 1;
    }
}

// ---------------------------------------------------------------------------
// fused fp32 -> fp16 conversion (all 5 tensors, one launch)
// ---------------------------------------------------------------------------
#define CVT_N0 1048576
#define CVT_N1 1310720
#define CVT_N2 1441792
#define CVT_N3 1572864
#define CVT_N4 1835008

__global__ __launch_bounds__(256)
void cvt_all(const float* __restrict__ x, const float* __restrict__ wq,
             const float* __restrict__ wk, const float* __restrict__ wv,
             const float* __restrict__ wp) {
    int i = blockIdx.x * blockDim.x + threadIdx.x;
    const float* src; __half* dst; int base;
    if (i < CVT_N0)      { src = x;  dst = g_xh;  base = 0; }
    else if (i < CVT_N1) { src = wq; dst = g_wqh; base = CVT_N0; }
    else if (i < CVT_N2) { src = wk; dst = g_wkh; base = CVT_N1; }
    else if (i < CVT_N3) { src = wv; dst = g_wvh; base = CVT_N2; }
    else if (i < CVT_N4) { src = wp; dst = g_wph; base = CVT_N3; }
    else return;
    int j = i - base;
    float4 v = ((const float4*)src)[j];
    __half2* d = (__half2*)dst + (size_t)j * 2;
    d[0] = __floats2half2_rn(v.x, v.y);
    d[1] = __floats2half2_rn(v.z, v.w);
}

// ---------------------------------------------------------------------------
// Fused QKV projection (fp16 in, fp16 out).
// ---------------------------------------------------------------------------
__global__ __launch_bounds__(128, 2)
void gemm_qkv_h(const __half* __restrict__ x,
                const __half* __restrict__ Wq, const __half* __restrict__ Wk,
                const __half* __restrict__ Wv,
                __half* __restrict__ q, __half* __restrict__ k,
                __half* __restrict__ v) {
    extern __shared__ char gsm[];

    const int nb = blockIdx.x;
    const int m0 = blockIdx.y * 128;

    const __half* W; __half* C; int ldc, n0;
    if (nb < 8)       { W = Wq; C = q; ldc = DMODEL;  n0 = nb * 128; }
    else if (nb < 12) { W = Wk; C = k; ldc = NKV_DIM; n0 = (nb - 8) * 128; }
    else              { W = Wv; C = v; ldc = NKV_DIM; n0 = (nb - 12) * 128; }

    float acc[32][4];
    hgemm_mainloop(x + (size_t)m0 * DMODEL, W + (size_t)n0 * DMODEL, DMODEL,
                   acc, gsm);

    const int tid  = threadIdx.x;
    const int lane = tid & 31;
    const int wid  = tid >> 5;
    const int mb0  = (wid & 1) * 4;
    const int nb0  = (wid >> 1) * 8;
    const int lq   = lane >> 2;
    const int lr   = lane & 3;

#pragma unroll
    for (int mt = 0; mt < 4; mt++) {
        const int row = m0 + (mb0 + mt) * 16 + lq;
#pragma unroll
        for (int nt = 0; nt < 8; nt++) {
            const int col = n0 + (nb0 + nt) * 8 + 2 * lr;
            float* d = acc[mt * 8 + nt];
            *(__half2*)(C + (size_t)row * ldc + col) =
                __floats2half2_rn(d[0], d[1]);
            *(__half2*)(C + (size_t)(row + 8) * ldc + col) =
                __floats2half2_rn(d[2], d[3]);
        }
    }
}

// Output projection (fp16 in, fp32 out).
__global__ __launch_bounds__(128, 2)
void gemm_proj_h(const __half* __restrict__ A, const __half* __restrict__ B,
                 float* __restrict__ C, int N, int K) {
    extern __shared__ char gsm[];

    const int m0 = blockIdx.y * 128;
    const int n0 = blockIdx.x * 128;

    float acc[32][4];
    hgemm_mainloop(A + (size_t)m0 * K, B + (size_t)n0 * K, K, acc, gsm);

    const int tid  = threadIdx.x;
    const int lane = tid & 31;
    const int wid  = tid >> 5;
    const int mb0  = (wid & 1) * 4;
    const int nb0  = (wid >> 1) * 8;
    const int lq   = lane >> 2;
    const int lr   = lane & 3;

#pragma unroll
    for (int mt = 0; mt < 4; mt++) {
        const int row = m0 + (mb0 + mt) * 16 + lq;
#pragma unroll
        for (int nt = 0; nt < 8; nt++) {
            const int col = n0 + (nb0 + nt) * 8 + 2 * lr;
            float* d = acc[mt * 8 + nt];
            *(float2*)(C + (size_t)row * N + col)       = make_float2(d[0], d[1]);
            *(float2*)(C + (size_t)(row + 8) * N + col) = make_float2(d[2], d[3]);
        }
    }
}

// ---------------------------------------------------------------------------
// fp16 flash attention (unchanged from R14, proven): software-pipelined K/V
// gmem loads, frag-layout smem, 128 threads / 4 warps, 2 m-tiles per warp.
// ---------------------------------------------------------------------------
#define ABLK 132
#define BBLK 66
#define ATTN_SMEM ((4224 + 2112 + 2112) * 4)
#define NST (T_SEQ / 64)

__global__ __launch_bounds__(128, 2)
void attn_mma(const __half* __restrict__ Q, const __half* __restrict__ Kg,
              const __half* __restrict__ Vg, __half* __restrict__ Y) {
    extern __shared__ uint32_t smu[];
    uint32_t* Qf = smu;
    uint32_t* Kf = smu + 4224;
    uint32_t* Vf = Kf + 2112;

    const int qt = blockIdx.x;
    const int h  = blockIdx.y;
    const int b  = blockIdx.z;
    const int kv = h >> 1;

    const int tid  = threadIdx.x;
    const int lane = tid & 31;
    const int wid  = tid >> 5;
    const int lq   = lane >> 2;
    const int lr   = lane & 3;

    const __half* qp = Q + ((size_t)(b * T_SEQ + qt * 128)) * DMODEL + h * DHEAD;
    const __half* kbase = Kg + ((size_t)(b * T_SEQ)) * NKV_DIM + kv * DHEAD;
    const __half* vbase = Vg + ((size_t)(b * T_SEQ)) * NKV_DIM + kv * DHEAD;

    int srK[4], shK[4];
#pragma unroll
    for (int i = 0; i < 4; i++) {
        int ff = i * 128 + tid;
        srK[i] = ff >> 3;
        shK[i] = (ff & 7) * 8;
    }

#pragma unroll
    for (int i = 0; i < 8; i++) {
        int ff = i * 128 + tid;
        int r  = ff >> 3;
        int hg = (ff & 7) * 8;
        uint4 v = *(const uint4*)(qp + (size_t)r * DMODEL + hg);
        const int blk = (r >> 4) * 4 + (hg >> 4);
        const int j   = ((hg >> 3) & 1) * 2 + ((r >> 3) & 1);
        uint32_t* p = Qf + blk * ABLK + (r & 7) * 16 + j;
        p[0]  = scaleh2(v.x, QSCALE);
        p[4]  = scaleh2(v.y, QSCALE);
        p[8]  = scaleh2(v.z, QSCALE);
        p[12] = scaleh2(v.w, QSCALE);
    }

    float oA[8][4], oB[8][4];
#pragma unroll
    for (int i = 0; i < 8; i++)
#pragma unroll
        for (int j = 0; j < 4; j++) { oA[i][j] = 0.0f; oB[i][j] = 0.0f; }
    float mA0 = -1e30f, mA1 = -1e30f, lA0 = 0.0f, lA1 = 0.0f;
    float mB0 = -1e30f, mB1 = -1e30f, lB0 = 0.0f, lB1 = 0.0f;

    const int mtA = wid * 2;
    const int mtB = wid * 2 + 1;

    uint4 kreg[4], vreg[4];
#pragma unroll
    for (int i = 0; i < 4; i++) {
        kreg[i] = *(const uint4*)(kbase + (size_t)srK[i] * NKV_DIM + shK[i]);
        vreg[i] = *(const uint4*)(vbase + (size_t)srK[i] * NKV_DIM + shK[i]);
    }

    for (int st = 0; st < NST; st++) {
#pragma unroll
        for (int i = 0; i < 4; i++) {
            const int r  = srK[i];
            const int hg = shK[i];
            {
                const int blk = (r >> 3) * 4 + (hg >> 4);
                const int j   = (hg >> 3) & 1;
                uint32_t* p = Kf + blk * BBLK + (r & 7) * 8 + j;
                p[0] = kreg[i].x; p[2] = kreg[i].y;
                p[4] = kreg[i].z; p[6] = kreg[i].w;
            }
            {
                const int blk = (r >> 4) * 8 + (hg >> 3);
                __half* base = (__half*)(Vf + blk * BBLK +
                                         ((r & 7) >> 1) * 2 + ((r >> 3) & 1)) +
                               (r & 1);
                const __half* hv = (const __half*)&vreg[i];
#pragma unroll
                for (int jj = 0; jj < 8; jj++) base[jj * 16] = hv[jj];
            }
        }
        __syncthreads();

        if (st + 1 < NST) {
            const __half* kp = kbase + (size_t)(st + 1) * 64 * NKV_DIM;
            const __half* vp = vbase + (size_t)(st + 1) * 64 * NKV_DIM;
#pragma unroll
            for (int i = 0; i < 4; i++) {
                kreg[i] = *(const uint4*)(kp + (size_t)srK[i] * NKV_DIM + shK[i]);
                vreg[i] = *(const uint4*)(vp + (size_t)srK[i] * NKV_DIM + shK[i]);
            }
        }

        float sfA[8][4], sfB[8][4];
#pragma unroll
        for (int nt = 0; nt < 8; nt++) {
            sfA[nt][0] = sfA[nt][1] = sfA[nt][2] = sfA[nt][3] = 0.0f;
            sfB[nt][0] = sfB[nt][1] = sfB[nt][2] = sfB[nt][3] = 0.0f;
        }

#pragma unroll
        for (int kb = 0; kb < 4; kb++) {
            uint32_t qa[4], qb[4];
            {
                const uint4 v = *(const uint4*)&Qf[(mtA * 4 + kb) * ABLK + lane * 4];
                qa[0] = v.x; qa[1] = v.y; qa[2] = v.z; qa[3] = v.w;
            }
            {
                const uint4 v = *(const uint4*)&Qf[(mtB * 4 + kb) * ABLK + lane * 4];
                qb[0] = v.x; qb[1] = v.y; qb[2] = v.z; qb[3] = v.w;
            }
#pragma unroll
            for (int nt = 0; nt < 8; nt++) {
                uint32_t bfr[2];
                const uint2 bv = *(const uint2*)&Kf[(nt * 4 + kb) * BBLK + lane * 2];
                bfr[0] = bv.x; bfr[1] = bv.y;
                mma_f16(sfA[nt], qa, bfr);
                mma_f16(sfB[nt], qb, bfr);
            }
        }

        {
            float mx0 = -1e30f, mx1 = -1e30f;
#pragma unroll
            for (int nt = 0; nt < 8; nt++) {
                mx0 = fmaxf(mx0, fmaxf(sfA[nt][0], sfA[nt][1]));
                mx1 = fmaxf(mx1, fmaxf(sfA[nt][2], sfA[nt][3]));
            }
            mx0 = fmaxf(mx0, __shfl_xor_sync(0xffffffffu, mx0, 1));
            mx0 = fmaxf(mx0, __shfl_xor_sync(0xffffffffu, mx0, 2));
            mx1 = fmaxf(mx1, __shfl_xor_sync(0xffffffffu, mx1, 1));
            mx1 = fmaxf(mx1, __shfl_xor_sync(0xffffffffu, mx1, 2));
            const float mn0 = fmaxf(mA0, mx0);
            const float mn1 = fmaxf(mA1, mx1);
            const float al0 = ex2f(mA0 - mn0);
            const float al1 = ex2f(mA1 - mn1);
            mA0 = mn0; mA1 = mn1;
            float s0 = 0.0f, s1 = 0.0f;
#pragma unroll
            for (int nt = 0; nt < 8; nt++) {
                sfA[nt][0] = ex2f(sfA[nt][0] - mn0); s0 += sfA[nt][0];
                sfA[nt][1] = ex2f(sfA[nt][1] - mn0); s0 += sfA[nt][1];
                sfA[nt][2] = ex2f(sfA[nt][2] - mn1); s1 += sfA[nt][2];
                sfA[nt][3] = ex2f(sfA[nt][3] - mn1); s1 += sfA[nt][3];
            }
            s0 += __shfl_xor_sync(0xffffffffu, s0, 1);
            s0 += __shfl_xor_sync(0xffffffffu, s0, 2);
            s1 += __shfl_xor_sync(0xffffffffu, s1, 1);
            s1 += __shfl_xor_sync(0xffffffffu, s1, 2);
            lA0 = lA0 * al0 + s0;
            lA1 = lA1 * al1 + s1;
#pragma unroll
            for (int nb = 0; nb < 8; nb++) {
                oA[nb][0] *= al0; oA[nb][1] *= al0;
                oA[nb][2] *= al1; oA[nb][3] *= al1;
            }
        }
        {
            float mx0 = -1e30f, mx1 = -1e30f;
#pragma unroll
            for (int nt = 0; nt < 8; nt++) {
                mx0 = fmaxf(mx0, fmaxf(sfB[nt][0], sfB[nt][1]));
                mx1 = fmaxf(mx1, fmaxf(sfB[nt][2], sfB[nt][3]));
            }
            mx0 = fmaxf(mx0, __shfl_xor_sync(0xffffffffu, mx0, 1));
            mx0 = fmaxf(mx0, __shfl_xor_sync(0xffffffffu, mx0, 2));
            mx1 = fmaxf(mx1, __shfl_xor_sync(0xffffffffu, mx1, 1));
            mx1 = fmaxf(mx1, __shfl_xor_sync(0xffffffffu, mx1, 2));
            const float mn0 = fmaxf(mB0, mx0);
            const float mn1 = fmaxf(mB1, mx1);
            const float al0 = ex2f(mB0 - mn0);
            const float al1 = ex2f(mB1 - mn1);
            mB0 = mn0; mB1 = mn1;
            float s0 = 0.0f, s1 = 0.0f;
#pragma unroll
            for (int nt = 0; nt < 8; nt++) {
                sfB[nt][0] = ex2f(sfB[nt][0] - mn0); s0 += sfB[nt][0];
                sfB[nt][1] = ex2f(sfB[nt][1] - mn0); s0 += sfB[nt][1];
                sfB[nt][2] = ex2f(sfB[nt][2] - mn1); s1 += sfB[nt][2];
                sfB[nt][3] = ex2f(sfB[nt][3] - mn1); s1 += sfB[nt][3];
            }
            s0 += __shfl_xor_sync(0xffffffffu, s0, 1);
            s0 += __shfl_xor_sync(0xffffffffu, s0, 2);
            s1 += __shfl_xor_sync(0xffffffffu, s1, 1);
            s1 += __shfl_xor_sync(0xffffffffu, s1, 2);
            lB0 = lB0 * al0 + s0;
            lB1 = lB1 * al1 + s1;
#pragma unroll
            for (int nb = 0; nb < 8; nb++) {
                oB[nb][0] *= al0; oB[nb][1] *= al0;
                oB[nb][2] *= al1; oB[nb][3] *= al1;
            }
        }

#pragma unroll
        for (int kt = 0; kt < 4; kt++) {
            uint32_t paA[4], paB[4];
            {
                __half2 t0 = __floats2half2_rn(sfA[2 * kt][0],     sfA[2 * kt][1]);
                __half2 t1 = __floats2half2_rn(sfA[2 * kt][2],     sfA[2 * kt][3]);
                __half2 t2 = __floats2half2_rn(sfA[2 * kt + 1][0], sfA[2 * kt + 1][1]);
                __half2 t3 = __floats2half2_rn(sfA[2 * kt + 1][2], sfA[2 * kt + 1][3]);
                paA[0] = *(uint32_t*)&t0; paA[1] = *(uint32_t*)&t1;
                paA[2] = *(uint32_t*)&t2; paA[3] = *(uint32_t*)&t3;
            }
            {
                __half2 t0 = __floats2half2_rn(sfB[2 * kt][0],     sfB[2 * kt][1]);
                __half2 t1 = __floats2half2_rn(sfB[2 * kt][2],     sfB[2 * kt][3]);
                __half2 t2 = __floats2half2_rn(sfB[2 * kt + 1][0], sfB[2 * kt + 1][1]);
                __half2 t3 = __floats2half2_rn(sfB[2 * kt + 1][2], sfB[2 * kt + 1][3]);
                paB[0] = *(uint32_t*)&t0; paB[1] = *(uint32_t*)&t1;
                paB[2] = *(uint32_t*)&t2; paB[3] = *(uint32_t*)&t3;
            }

#pragma unroll
            for (int nb = 0; nb < 8; nb++) {
                uint32_t bfr[2];
                const uint2 bv = *(const uint2*)&Vf[(kt * 8 + nb) * BBLK + lane * 2];
                bfr[0] = bv.x; bfr[1] = bv.y;
                mma_f16(oA[nb], paA, bfr);
                mma_f16(oB[nb], paB, bfr);
            }
        }
        __syncthreads();
    }

    {
        const float i0 = 1.0f / lA0, i1 = 1.0f / lA1;
        __half* yp = Y + ((size_t)(b * T_SEQ + qt * 128 + mtA * 16)) * DMODEL + h * DHEAD;
#pragma unroll
        for (int nb = 0; nb < 8; nb++) {
            const int col = nb * 8 + 2 * lr;
            *(__half2*)(yp + (size_t)lq * DMODEL + col) =
                __floats2half2_rn(oA[nb][0] * i0, oA[nb][1] * i0);
            *(__half2*)(yp + (size_t)(lq + 8) * DMODEL + col) =
                __floats2half2_rn(oA[nb][2] * i1, oA[nb][3] * i1);
        }
    }
    {
        const float i0 = 1.0f / lB0, i1 = 1.0f / lB1;
        __half* yp = Y + ((size_t)(b * T_SEQ + qt * 128 + mtB * 16)) * DMODEL + h * DHEAD;
#pragma unroll
        for (int nb = 0; nb < 8; nb++) {
            const int col = nb * 8 + 2 * lr;
            *(__half2*)(yp + (size_t)lq * DMODEL + col) =
                __floats2half2_rn(oB[nb][0] * i0, oB[nb][1] * i0);
            *(__half2*)(yp + (size_t)(lq + 8) * DMODEL + col) =
                __floats2half2_rn(oB[nb][2] * i1, oB[nb][3] * i1);
        }
    }
}

// ---------------------------------------------------------------------------
// Launch
// ---------------------------------------------------------------------------
extern "C" void kernel_launch(void* const* d_in, const int* in_sizes, int n_in,
                              void* d_out, int out_size) {
    const float* x     = (const float*)d_in[0];
    const float* Wq    = (const float*)d_in[1];
    const float* Wk    = (const float*)d_in[2];
    const float* Wv    = (const float*)d_in[3];
    const float* Wproj = (const float*)d_in[4];
    float* out = (float*)d_out;

    void *pxh, *pwq, *pwk, *pwv, *pwp, *pq, *pk, *pv, *py;
    cudaGetSymbolAddress(&pxh, g_xh);
    cudaGetSymbolAddress(&pwq, g_wqh);
    cudaGetSymbolAddress(&pwk, g_wkh);
    cudaGetSymbolAddress(&pwv, g_wvh);
    cudaGetSymbolAddress(&pwp, g_wph);
    cudaGetSymbolAddress(&pq, g_q);
    cudaGetSymbolAddress(&pk, g_k);
    cudaGetSymbolAddress(&pv, g_v);
    cudaGetSymbolAddress(&py, g_y);

    cudaFuncSetAttribute(attn_mma, cudaFuncAttributeMaxDynamicSharedMemorySize,
                         ATTN_SMEM);
    cudaFuncSetAttribute(gemm_qkv_h, cudaFuncAttributeMaxDynamicSharedMemorySize,
                         GEMM_SMEM);
    cudaFuncSetAttribute(gemm_proj_h, cudaFuncAttributeMaxDynamicSharedMemorySize,
                         GEMM_SMEM);

    cvt_all<<<(CVT_N4 + 255) / 256, 256>>>(x, Wq, Wk, Wv, Wproj);

    gemm_qkv_h<<<dim3(16, MTOT / 128), dim3(128), GEMM_SMEM>>>(
        (const __half*)pxh, (const __half*)pwq, (const __half*)pwk,
        (const __half*)pwv, (__half*)pq, (__half*)pk, (__half*)pv);
    attn_mma<<<dim3(T_SEQ / 128, NHEADS, BATCH), dim3(128), ATTN_SMEM>>>(
        (const __half*)pq, (const __half*)pk, (const __half*)pv, (__half*)py);
    gemm_proj_h<<<dim3(DMODEL / 128, MTOT / 128), dim3(128), GEMM_SMEM>>>(
        (const __half*)py, (const __half*)pwp, out, DMODEL, DMODEL);
}

// round 17
// speedup vs baseline: 8.3354x; 1.0360x over previous
#include <cuda_runtime.h>
#include <cuda_fp16.h>
#include <cstdint>
#include <math.h>

// ---------------------------------------------------------------------------
// GQA block: y = proj( attn( x@Wq^T, x@Wk^T, x@Wv^T ) )
// B=2, T=2048, D_MODEL=1024, N_HEADS=16, N_KV=8, GROUP=2, D_HEAD=64
// R16: attention rebuilt on cp.async + ldmatrix (K via ldm, V via ldm.trans,
//      Q register-persistent; QSCALE folded into softmax FMA). GEMMs from
//      R15 (proven).
// ---------------------------------------------------------------------------

#define BATCH   2
#define T_SEQ   2048
#define DMODEL  1024
#define NKV_DIM 512
#define NHEADS  16
#define DHEAD   64
#define QSCALE  0.18033688f   // 64^-0.5 * log2(e)

#define MTOT (BATCH * T_SEQ)   // 4096 rows

// fp16 scratch (static device globals)
__device__ __align__(16) __half g_xh[(size_t)MTOT * DMODEL];
__device__ __align__(16) __half g_wqh[(size_t)DMODEL * DMODEL];
__device__ __align__(16) __half g_wkh[(size_t)NKV_DIM * DMODEL];
__device__ __align__(16) __half g_wvh[(size_t)NKV_DIM * DMODEL];
__device__ __align__(16) __half g_wph[(size_t)DMODEL * DMODEL];
__device__ __align__(16) __half g_q[(size_t)MTOT * DMODEL];
__device__ __align__(16) __half g_k[(size_t)MTOT * NKV_DIM];
__device__ __align__(16) __half g_v[(size_t)MTOT * NKV_DIM];
__device__ __align__(16) __half g_y[(size_t)MTOT * DMODEL];

// ---------------------------------------------------------------------------
// helpers
// ---------------------------------------------------------------------------
__device__ __forceinline__ float ex2f(float x) {
    float y;
    asm("ex2.approx.f32 %0, %1;" : "=f"(y) : "f"(x));
    return y;
}

__device__ __forceinline__ void mma_f16(float* d, const uint32_t* a,
                                        const uint32_t* b) {
    asm volatile(
        "mma.sync.aligned.m16n8k16.row.col.f32.f16.f16.f32 "
        "{%0,%1,%2,%3}, {%4,%5,%6,%7}, {%8,%9}, {%0,%1,%2,%3};"
        : "+f"(d[0]), "+f"(d[1]), "+f"(d[2]), "+f"(d[3])
        : "r"(a[0]), "r"(a[1]), "r"(a[2]), "r"(a[3]), "r"(b[0]), "r"(b[1]));
}

__device__ __forceinline__ void cp16(uint32_t dst, const void* src) {
    asm volatile("cp.async.cg.shared.global [%0], [%1], 16;"
                 :: "r"(dst), "l"(src));
}
__device__ __forceinline__ void cp_commit() {
    asm volatile("cp.async.commit_group;" ::: "memory");
}
template <int N>
__device__ __forceinline__ void cp_wait() {
    asm volatile("cp.async.wait_group %0;" :: "n"(N) : "memory");
}
__device__ __forceinline__ void ldm_x4(uint32_t* r, uint32_t addr) {
    asm volatile("ldmatrix.sync.aligned.m8n8.x4.shared.b16 {%0,%1,%2,%3}, [%4];"
                 : "=r"(r[0]), "=r"(r[1]), "=r"(r[2]), "=r"(r[3]) : "r"(addr));
}
__device__ __forceinline__ void ldm_t4(uint32_t* r, uint32_t addr) {
    asm volatile("ldmatrix.sync.aligned.m8n8.x4.trans.shared.b16 {%0,%1,%2,%3}, [%4];"
                 : "=r"(r[0]), "=r"(r[1]), "=r"(r[2]), "=r"(r[3]) : "r"(addr));
}

// ---------------------------------------------------------------------------
// cp.async + ldmatrix fp16 GEMM (unchanged from R15, proven).
// ---------------------------------------------------------------------------
#define ROWB    80
#define STAGE_A 10240
#define STAGE_SZ (2 * STAGE_A)
#define NSTAGE  3
#define GEMM_SMEM (NSTAGE * STAGE_SZ)

__device__ __forceinline__ void hgemm_mainloop(
    const __half* Ap, const __half* Bp, int K, float acc[32][4], char* smem) {
    const int tid  = threadIdx.x;
    const int lane = tid & 31;
    const int wid  = tid >> 5;
    const int mb0  = (wid & 1) * 4;
    const int nb0  = (wid >> 1) * 8;

    const uint32_t sbase = (uint32_t)__cvta_generic_to_shared(smem);

    const int srow = tid >> 2;
    const int sc   = tid & 3;

    const uint32_t laneOffA =
        (uint32_t)((((lane >> 3) & 1) * 8 + (lane & 7)) * ROWB + (lane >> 4) * 16);
    const uint32_t laneOffB =
        (uint32_t)(((lane & 7) + (lane >> 4) * 8) * ROWB + ((lane >> 3) & 1) * 16);

#pragma unroll
    for (int i = 0; i < 32; i++)
#pragma unroll
        for (int j = 0; j < 4; j++) acc[i][j] = 0.0f;

    const int kiters = K / 32;

#pragma unroll
    for (int p = 0; p < 2; p++) {
        const __half* As = Ap + p * 32;
        const __half* Bs = Bp + p * 32;
        uint32_t ab = sbase + p * STAGE_SZ;
        uint32_t bb = ab + STAGE_A;
#pragma unroll
        for (int i = 0; i < 4; i++) {
            int r = i * 32 + srow;
            cp16(ab + r * ROWB + sc * 16, As + (size_t)r * K + sc * 8);
            cp16(bb + r * ROWB + sc * 16, Bs + (size_t)r * K + sc * 8);
        }
        cp_commit();
    }

    int buf = 0;
#pragma unroll 1
    for (int it = 0; it < kiters; ++it) {
        cp_wait<1>();
        __syncthreads();

        const uint32_t ab = sbase + buf * STAGE_SZ;
        const uint32_t bb = ab + STAGE_A;

#pragma unroll
        for (int ks = 0; ks < 2; ks++) {
            uint32_t afr[4][4], bfr[8][2];
#pragma unroll
            for (int mt = 0; mt < 4; mt++)
                ldm_x4(afr[mt],
                       ab + (mb0 + mt) * (16 * ROWB) + ks * 32 + laneOffA);
#pragma unroll
            for (int t = 0; t < 4; t++) {
                uint32_t r[4];
                ldm_x4(r, bb + (nb0 + 2 * t) * (8 * ROWB) + ks * 32 + laneOffB);
                bfr[2 * t][0]     = r[0]; bfr[2 * t][1]     = r[1];
                bfr[2 * t + 1][0] = r[2]; bfr[2 * t + 1][1] = r[3];
            }
#pragma unroll
            for (int mt = 0; mt < 4; mt++)
#pragma unroll
                for (int nt = 0; nt < 8; nt++)
                    mma_f16(acc[mt * 8 + nt], afr[mt], bfr[nt]);
        }

        if (it + 2 < kiters) {
            const __half* As = Ap + (it + 2) * 32;
            const __half* Bs = Bp + (it + 2) * 32;
            uint32_t ab2 = sbase + ((it + 2) % 3) * STAGE_SZ;
            uint32_t bb2 = ab2 + STAGE_A;
#pragma unroll
            for (int i = 0; i < 4; i++) {
                int r = i * 32 + srow;
                cp16(ab2 + r * ROWB + sc * 16, As + (size_t)r * K + sc * 8);
                cp16(bb2 + r * ROWB + sc * 16, Bs + (size_t)r * K + sc * 8);
            }
        }
        cp_commit();

        buf = (buf + 1 == 3) ? 0 : buf + 1;
    }
}

// ---------------------------------------------------------------------------
// fused fp32 -> fp16 conversion (all 5 tensors, one launch)
// ---------------------------------------------------------------------------
#define CVT_N0 1048576
#define CVT_N1 1310720
#define CVT_N2 1441792
#define CVT_N3 1572864
#define CVT_N4 1835008

__global__ __launch_bounds__(256)
void cvt_all(const float* __restrict__ x, const float* __restrict__ wq,
             const float* __restrict__ wk, const float* __restrict__ wv,
             const float* __restrict__ wp) {
    int i = blockIdx.x * blockDim.x + threadIdx.x;
    const float* src; __half* dst; int base;
    if (i < CVT_N0)      { src = x;  dst = g_xh;  base = 0; }
    else if (i < CVT_N1) { src = wq; dst = g_wqh; base = CVT_N0; }
    else if (i < CVT_N2) { src = wk; dst = g_wkh; base = CVT_N1; }
    else if (i < CVT_N3) { src = wv; dst = g_wvh; base = CVT_N2; }
    else if (i < CVT_N4) { src = wp; dst = g_wph; base = CVT_N3; }
    else return;
    int j = i - base;
    float4 v = ((const float4*)src)[j];
    __half2* d = (__half2*)dst + (size_t)j * 2;
    d[0] = __floats2half2_rn(v.x, v.y);
    d[1] = __floats2half2_rn(v.z, v.w);
}

// ---------------------------------------------------------------------------
// Fused QKV projection (fp16 in, fp16 out).
// ---------------------------------------------------------------------------
__global__ __launch_bounds__(128, 2)
void gemm_qkv_h(const __half* __restrict__ x,
                const __half* __restrict__ Wq, const __half* __restrict__ Wk,
                const __half* __restrict__ Wv,
                __half* __restrict__ q, __half* __restrict__ k,
                __half* __restrict__ v) {
    extern __shared__ char gsm[];

    const int nb = blockIdx.x;
    const int m0 = blockIdx.y * 128;

    const __half* W; __half* C; int ldc, n0;
    if (nb < 8)       { W = Wq; C = q; ldc = DMODEL;  n0 = nb * 128; }
    else if (nb < 12) { W = Wk; C = k; ldc = NKV_DIM; n0 = (nb - 8) * 128; }
    else              { W = Wv; C = v; ldc = NKV_DIM; n0 = (nb - 12) * 128; }

    float acc[32][4];
    hgemm_mainloop(x + (size_t)m0 * DMODEL, W + (size_t)n0 * DMODEL, DMODEL,
                   acc, gsm);

    const int tid  = threadIdx.x;
    const int lane = tid & 31;
    const int wid  = tid >> 5;
    const int mb0  = (wid & 1) * 4;
    const int nb0  = (wid >> 1) * 8;
    const int lq   = lane >> 2;
    const int lr   = lane & 3;

#pragma unroll
    for (int mt = 0; mt < 4; mt++) {
        const int row = m0 + (mb0 + mt) * 16 + lq;
#pragma unroll
        for (int nt = 0; nt < 8; nt++) {
            const int col = n0 + (nb0 + nt) * 8 + 2 * lr;
            float* d = acc[mt * 8 + nt];
            *(__half2*)(C + (size_t)row * ldc + col) =
                __floats2half2_rn(d[0], d[1]);
            *(__half2*)(C + (size_t)(row + 8) * ldc + col) =
                __floats2half2_rn(d[2], d[3]);
        }
    }
}

// Output projection (fp16 in, fp32 out).
__global__ __launch_bounds__(128, 2)
void gemm_proj_h(const __half* __restrict__ A, const __half* __restrict__ B,
                 float* __restrict__ C, int N, int K) {
    extern __shared__ char gsm[];

    const int m0 = blockIdx.y * 128;
    const int n0 = blockIdx.x * 128;

    float acc[32][4];
    hgemm_mainloop(A + (size_t)m0 * K, B + (size_t)n0 * K, K, acc, gsm);

    const int tid  = threadIdx.x;
    const int lane = tid & 31;
    const int wid  = tid >> 5;
    const int mb0  = (wid & 1) * 4;
    const int nb0  = (wid >> 1) * 8;
    const int lq   = lane >> 2;
    const int lr   = lane & 3;

#pragma unroll
    for (int mt = 0; mt < 4; mt++) {
        const int row = m0 + (mb0 + mt) * 16 + lq;
#pragma unroll
        for (int nt = 0; nt < 8; nt++) {
            const int col = n0 + (nb0 + nt) * 8 + 2 * lr;
            float* d = acc[mt * 8 + nt];
            *(float2*)(C + (size_t)row * N + col)       = make_float2(d[0], d[1]);
            *(float2*)(C + (size_t)(row + 8) * N + col) = make_float2(d[2], d[3]);
        }
    }
}

// ---------------------------------------------------------------------------
// fp16 flash attention, cp.async + ldmatrix edition.
// 128 threads / 4 warps; warp owns 32 q rows (2 m-tiles); 64-key sub-tiles;
// 3-stage cp.async pipeline for K/V; Q fragments register-persistent;
// V fragments via ldmatrix.trans; QSCALE folded into softmax FMA.
// Smem rows stride 144B (36 banks -> conflict-free ldmatrix phases).
// ---------------------------------------------------------------------------
#define AROWB   144
#define QTILE   (128 * AROWB)            // 18432
#define KSTG    (64 * AROWB)             // 9216
#define KVSTG   (2 * KSTG)               // 18432 (K + V)
#define ATTN_SMEM (QTILE + 3 * KVSTG)    // 73728
#define NST (T_SEQ / 64)

__global__ __launch_bounds__(128, 2)
void attn_mma(const __half* __restrict__ Q, const __half* __restrict__ Kg,
              const __half* __restrict__ Vg, __half* __restrict__ Y) {
    extern __shared__ char atsm[];
    const uint32_t sb = (uint32_t)__cvta_generic_to_shared(atsm);
    const uint32_t qs = sb;

    const int qt = blockIdx.x;
    const int h  = blockIdx.y;
    const int b  = blockIdx.z;
    const int kv = h >> 1;

    const int tid  = threadIdx.x;
    const int lane = tid & 31;
    const int wid  = tid >> 5;
    const int lq   = lane >> 2;
    const int lr   = lane & 3;

    const __half* qp = Q + ((size_t)(b * T_SEQ + qt * 128)) * DMODEL + h * DHEAD;
    const __half* kbase = Kg + ((size_t)(b * T_SEQ)) * NKV_DIM + kv * DHEAD;
    const __half* vbase = Vg + ((size_t)(b * T_SEQ)) * NKV_DIM + kv * DHEAD;

    // A-form lane offset (also correct for V-trans tiles); B-form for K.
    const uint32_t laneOffA =
        (uint32_t)((((lane >> 3) & 1) * 8 + (lane & 7)) * AROWB + (lane >> 4) * 16);
    const uint32_t laneOffB =
        (uint32_t)(((lane & 7) + (lane >> 4) * 8) * AROWB + ((lane >> 3) & 1) * 16);

    // staging coords: row = ff>>3 , 16B chunk = ff&7
    const int sr = tid >> 3;             // rows stride 16 over i
    const int sc = tid & 7;

    // ---- prologue: cp.async Q + KV stage 0, then KV stage 1 ----
#pragma unroll
    for (int i = 0; i < 8; i++) {
        int r = i * 16 + sr;
        cp16(qs + r * AROWB + sc * 16, qp + (size_t)r * DMODEL + sc * 8);
    }
    {
        uint32_t kd = sb + QTILE;
        uint32_t vd = kd + KSTG;
#pragma unroll
        for (int i = 0; i < 4; i++) {
            int r = i * 16 + sr;
            cp16(kd + r * AROWB + sc * 16, kbase + (size_t)r * NKV_DIM + sc * 8);
            cp16(vd + r * AROWB + sc * 16, vbase + (size_t)r * NKV_DIM + sc * 8);
        }
    }
    cp_commit();
    {
        uint32_t kd = sb + QTILE + KVSTG;
        uint32_t vd = kd + KSTG;
        const __half* kp = kbase + (size_t)64 * NKV_DIM;
        const __half* vp = vbase + (size_t)64 * NKV_DIM;
#pragma unroll
        for (int i = 0; i < 4; i++) {
            int r = i * 16 + sr;
            cp16(kd + r * AROWB + sc * 16, kp + (size_t)r * NKV_DIM + sc * 8);
            cp16(vd + r * AROWB + sc * 16, vp + (size_t)r * NKV_DIM + sc * 8);
        }
    }
    cp_commit();

    cp_wait<1>();
    __syncthreads();

    // ---- Q fragments: register-persistent (raw, unscaled) ----
    const int mtA = wid * 2;
    const int mtB = wid * 2 + 1;
    uint32_t qfA[4][4], qfB[4][4];
#pragma unroll
    for (int kb = 0; kb < 4; kb++) {
        ldm_x4(qfA[kb], qs + mtA * (16 * AROWB) + kb * 32 + laneOffA);
        ldm_x4(qfB[kb], qs + mtB * (16 * AROWB) + kb * 32 + laneOffA);
    }

    float oA[8][4], oB[8][4];
#pragma unroll
    for (int i = 0; i < 8; i++)
#pragma unroll
        for (int j = 0; j < 4; j++) { oA[i][j] = 0.0f; oB[i][j] = 0.0f; }
    float mA0 = -1e30f, mA1 = -1e30f, lA0 = 0.0f, lA1 = 0.0f;
    float mB0 = -1e30f, mB1 = -1e30f, lB0 = 0.0f, lB1 = 0.0f;

#pragma unroll 1
    for (int st = 0; st < NST; st++) {
        if (st) { cp_wait<1>(); __syncthreads(); }

        // issue KV stage st+2 (overlaps with compute below)
        if (st + 2 < NST) {
            uint32_t kd = sb + QTILE + ((st + 2) % 3) * KVSTG;
            uint32_t vd = kd + KSTG;
            const __half* kp = kbase + (size_t)(st + 2) * 64 * NKV_DIM;
            const __half* vp = vbase + (size_t)(st + 2) * 64 * NKV_DIM;
#pragma unroll
            for (int i = 0; i < 4; i++) {
                int r = i * 16 + sr;
                cp16(kd + r * AROWB + sc * 16, kp + (size_t)r * NKV_DIM + sc * 8);
                cp16(vd + r * AROWB + sc * 16, vp + (size_t)r * NKV_DIM + sc * 8);
            }
        }
        cp_commit();

        const uint32_t kb_ = sb + QTILE + (st % 3) * KVSTG;
        const uint32_t vb_ = kb_ + KSTG;

        // ---- S = Q @ K^T (raw scores); K frag shared by both m-tiles ----
        float sfA[8][4], sfB[8][4];
#pragma unroll
        for (int nt = 0; nt < 8; nt++) {
            sfA[nt][0] = sfA[nt][1] = sfA[nt][2] = sfA[nt][3] = 0.0f;
            sfB[nt][0] = sfB[nt][1] = sfB[nt][2] = sfB[nt][3] = 0.0f;
        }
#pragma unroll
        for (int kb = 0; kb < 4; kb++) {
#pragma unroll
            for (int p = 0; p < 4; p++) {
                uint32_t r[4];
                ldm_x4(r, kb_ + p * (16 * AROWB) + kb * 32 + laneOffB);
                mma_f16(sfA[2 * p],     qfA[kb], &r[0]);
                mma_f16(sfA[2 * p + 1], qfA[kb], &r[2]);
                mma_f16(sfB[2 * p],     qfB[kb], &r[0]);
                mma_f16(sfB[2 * p + 1], qfB[kb], &r[2]);
            }
        }

        // ---- online softmax (log2 domain; QSCALE folded via FMA) ----
        {
            float mx0 = -1e30f, mx1 = -1e30f;
#pragma unroll
            for (int nt = 0; nt < 8; nt++) {
                mx0 = fmaxf(mx0, fmaxf(sfA[nt][0], sfA[nt][1]));
                mx1 = fmaxf(mx1, fmaxf(sfA[nt][2], sfA[nt][3]));
            }
            mx0 = fmaxf(mx0, __shfl_xor_sync(0xffffffffu, mx0, 1));
            mx0 = fmaxf(mx0, __shfl_xor_sync(0xffffffffu, mx0, 2));
            mx1 = fmaxf(mx1, __shfl_xor_sync(0xffffffffu, mx1, 1));
            mx1 = fmaxf(mx1, __shfl_xor_sync(0xffffffffu, mx1, 2));
            const float mn0 = fmaxf(mA0, mx0 * QSCALE);
            const float mn1 = fmaxf(mA1, mx1 * QSCALE);
            const float al0 = ex2f(mA0 - mn0);
            const float al1 = ex2f(mA1 - mn1);
            mA0 = mn0; mA1 = mn1;
            float s0 = 0.0f, s1 = 0.0f;
#pragma unroll
            for (int nt = 0; nt < 8; nt++) {
                sfA[nt][0] = ex2f(fmaf(sfA[nt][0], QSCALE, -mn0)); s0 += sfA[nt][0];
                sfA[nt][1] = ex2f(fmaf(sfA[nt][1], QSCALE, -mn0)); s0 += sfA[nt][1];
                sfA[nt][2] = ex2f(fmaf(sfA[nt][2], QSCALE, -mn1)); s1 += sfA[nt][2];
                sfA[nt][3] = ex2f(fmaf(sfA[nt][3], QSCALE, -mn1)); s1 += sfA[nt][3];
            }
            s0 += __shfl_xor_sync(0xffffffffu, s0, 1);
            s0 += __shfl_xor_sync(0xffffffffu, s0, 2);
            s1 += __shfl_xor_sync(0xffffffffu, s1, 1);
            s1 += __shfl_xor_sync(0xffffffffu, s1, 2);
            lA0 = lA0 * al0 + s0;
            lA1 = lA1 * al1 + s1;
#pragma unroll
            for (int nb = 0; nb < 8; nb++) {
                oA[nb][0] *= al0; oA[nb][1] *= al0;
                oA[nb][2] *= al1; oA[nb][3] *= al1;
            }
        }
        {
            float mx0 = -1e30f, mx1 = -1e30f;
#pragma unroll
            for (int nt = 0; nt < 8; nt++) {
                mx0 = fmaxf(mx0, fmaxf(sfB[nt][0], sfB[nt][1]));
                mx1 = fmaxf(mx1, fmaxf(sfB[nt][2], sfB[nt][3]));
            }
            mx0 = fmaxf(mx0, __shfl_xor_sync(0xffffffffu, mx0, 1));
            mx0 = fmaxf(mx0, __shfl_xor_sync(0xffffffffu, mx0, 2));
            mx1 = fmaxf(mx1, __shfl_xor_sync(0xffffffffu, mx1, 1));
            mx1 = fmaxf(mx1, __shfl_xor_sync(0xffffffffu, mx1, 2));
            const float mn0 = fmaxf(mB0, mx0 * QSCALE);
            const float mn1 = fmaxf(mB1, mx1 * QSCALE);
            const float al0 = ex2f(mB0 - mn0);
            const float al1 = ex2f(mB1 - mn1);
            mB0 = mn0; mB1 = mn1;
            float s0 = 0.0f, s1 = 0.0f;
#pragma unroll
            for (int nt = 0; nt < 8; nt++) {
                sfB[nt][0] = ex2f(fmaf(sfB[nt][0], QSCALE, -mn0)); s0 += sfB[nt][0];
                sfB[nt][1] = ex2f(fmaf(sfB[nt][1], QSCALE, -mn0)); s0 += sfB[nt][1];
                sfB[nt][2] = ex2f(fmaf(sfB[nt][2], QSCALE, -mn1)); s1 += sfB[nt][2];
                sfB[nt][3] = ex2f(fmaf(sfB[nt][3], QSCALE, -mn1)); s1 += sfB[nt][3];
            }
            s0 += __shfl_xor_sync(0xffffffffu, s0, 1);
            s0 += __shfl_xor_sync(0xffffffffu, s0, 2);
            s1 += __shfl_xor_sync(0xffffffffu, s1, 1);
            s1 += __shfl_xor_sync(0xffffffffu, s1, 2);
            lB0 = lB0 * al0 + s0;
            lB1 = lB1 * al1 + s1;
#pragma unroll
            for (int nb = 0; nb < 8; nb++) {
                oB[nb][0] *= al0; oB[nb][1] *= al0;
                oB[nb][2] *= al1; oB[nb][3] *= al1;
            }
        }

        // ---- PV: P packed to A-frag in registers; V frags via ldm.trans ----
#pragma unroll
        for (int kt = 0; kt < 4; kt++) {
            uint32_t paA[4], paB[4];
            {
                __half2 t0 = __floats2half2_rn(sfA[2 * kt][0],     sfA[2 * kt][1]);
                __half2 t1 = __floats2half2_rn(sfA[2 * kt][2],     sfA[2 * kt][3]);
                __half2 t2 = __floats2half2_rn(sfA[2 * kt + 1][0], sfA[2 * kt + 1][1]);
                __half2 t3 = __floats2half2_rn(sfA[2 * kt + 1][2], sfA[2 * kt + 1][3]);
                paA[0] = *(uint32_t*)&t0; paA[1] = *(uint32_t*)&t1;
                paA[2] = *(uint32_t*)&t2; paA[3] = *(uint32_t*)&t3;
            }
            {
                __half2 t0 = __floats2half2_rn(sfB[2 * kt][0],     sfB[2 * kt][1]);
                __half2 t1 = __floats2half2_rn(sfB[2 * kt][2],     sfB[2 * kt][3]);
                __half2 t2 = __floats2half2_rn(sfB[2 * kt + 1][0], sfB[2 * kt + 1][1]);
                __half2 t3 = __floats2half2_rn(sfB[2 * kt + 1][2], sfB[2 * kt + 1][3]);
                paB[0] = *(uint32_t*)&t0; paB[1] = *(uint32_t*)&t1;
                paB[2] = *(uint32_t*)&t2; paB[3] = *(uint32_t*)&t3;
            }

#pragma unroll
            for (int p = 0; p < 4; p++) {
                uint32_t r[4];
                ldm_t4(r, vb_ + kt * (16 * AROWB) + p * 32 + laneOffA);
                mma_f16(oA[2 * p],     paA, &r[0]);
                mma_f16(oA[2 * p + 1], paA, &r[2]);
                mma_f16(oB[2 * p],     paB, &r[0]);
                mma_f16(oB[2 * p + 1], paB, &r[2]);
            }
        }
    }

    // ---- epilogue: fp16 Y ----
    {
        const float i0 = 1.0f / lA0, i1 = 1.0f / lA1;
        __half* yp = Y + ((size_t)(b * T_SEQ + qt * 128 + mtA * 16)) * DMODEL + h * DHEAD;
#pragma unroll
        for (int nb = 0; nb < 8; nb++) {
            const int col = nb * 8 + 2 * lr;
            *(__half2*)(yp + (size_t)lq * DMODEL + col) =
                __floats2half2_rn(oA[nb][0] * i0, oA[nb][1] * i0);
            *(__half2*)(yp + (size_t)(lq + 8) * DMODEL + col) =
                __floats2half2_rn(oA[nb][2] * i1, oA[nb][3] * i1);
        }
    }
    {
        const float i0 = 1.0f / lB0, i1 = 1.0f / lB1;
        __half* yp = Y + ((size_t)(b * T_SEQ + qt * 128 + mtB * 16)) * DMODEL + h * DHEAD;
#pragma unroll
        for (int nb = 0; nb < 8; nb++) {
            const int col = nb * 8 + 2 * lr;
            *(__half2*)(yp + (size_t)lq * DMODEL + col) =
                __floats2half2_rn(oB[nb][0] * i0, oB[nb][1] * i0);
            *(__half2*)(yp + (size_t)(lq + 8) * DMODEL + col) =
                __floats2half2_rn(oB[nb][2] * i1, oB[nb][3] * i1);
        }
    }
}

// ---------------------------------------------------------------------------
// Launch
// ---------------------------------------------------------------------------
extern "C" void kernel_launch(void* const* d_in, const int* in_sizes, int n_in,
                              void* d_out, int out_size) {
    const float* x     = (const float*)d_in[0];
    const float* Wq    = (const float*)d_in[1];
    const float* Wk    = (const float*)d_in[2];
    const float* Wv    = (const float*)d_in[3];
    const float* Wproj = (const float*)d_in[4];
    float* out = (float*)d_out;

    void *pxh, *pwq, *pwk, *pwv, *pwp, *pq, *pk, *pv, *py;
    cudaGetSymbolAddress(&pxh, g_xh);
    cudaGetSymbolAddress(&pwq, g_wqh);
    cudaGetSymbolAddress(&pwk, g_wkh);
    cudaGetSymbolAddress(&pwv, g_wvh);
    cudaGetSymbolAddress(&pwp, g_wph);
    cudaGetSymbolAddress(&pq, g_q);
    cudaGetSymbolAddress(&pk, g_k);
    cudaGetSymbolAddress(&pv, g_v);
    cudaGetSymbolAddress(&py, g_y);

    cudaFuncSetAttribute(attn_mma, cudaFuncAttributeMaxDynamicSharedMemorySize,
                         ATTN_SMEM);
    cudaFuncSetAttribute(gemm_qkv_h, cudaFuncAttributeMaxDynamicSharedMemorySize,
                         GEMM_SMEM);
    cudaFuncSetAttribute(gemm_proj_h, cudaFuncAttributeMaxDynamicSharedMemorySize,
                         GEMM_SMEM);

    cvt_all<<<(CVT_N4 + 255) / 256, 256>>>(x, Wq, Wk, Wv, Wproj);

    gemm_qkv_h<<<dim3(16, MTOT / 128), dim3(128), GEMM_SMEM>>>(
        (const __half*)pxh, (const __half*)pwq, (const __half*)pwk,
        (const __half*)pwv, (__half*)pq, (__half*)pk, (__half*)pv);
    attn_mma<<<dim3(T_SEQ / 128, NHEADS, BATCH), dim3(128), ATTN_SMEM>>>(
        (const __half*)pq, (const __half*)pk, (const __half*)pv, (__half*)py);
    gemm_proj_h<<<dim3(DMODEL / 128, MTOT / 128), dim3(128), GEMM_SMEM>>>(
        (const __half*)py, (const __half*)pwp, out, DMODEL, DMODEL);
}